// round 3
// baseline (speedup 1.0000x reference)
#include <cuda_runtime.h>
#include <math.h>

// Problem constants
#define BB 2
#define SS 2048
#define DD 256
#define HH 8
#define FF 1024
#define DK 32
#define LL 3
#define BS (BB*SS)            // 4096 rows
#define NEG_MAX (-3.402823466e38f)
#define SCALE 0.17677669529663687f   // 1/sqrt(32)

// ---------------- device scratch (static: no allocations allowed) ----------------
__device__ float g_x  [BS*DD];   // activations (residual stream)
__device__ float g_q  [BS*DD];   // [b][h][s][dk]
__device__ float g_k  [BS*DD];
__device__ float g_v  [BS*DD];
__device__ float g_o  [BS*DD];   // attention output, [b][s][h*dk]
__device__ float g_t  [BS*DD];   // pre-LN temp
__device__ float g_hid[BS*FF];   // FFN hidden
__device__ unsigned int g_mpk[BB*SS*SS/32];  // packed mask bits (1 MB)

// ---------------- kernels ----------------

// Pack int32 mask (0/1) into bits: word w covers mask elements [32w, 32w+32)
__global__ void maskpack_kernel(const int* __restrict__ mask) {
    int w = blockIdx.x * 256 + threadIdx.x;        // 262144 words
    const int4* p = (const int4*)(mask) + w * 8;
    unsigned int bits = 0;
#pragma unroll
    for (int j = 0; j < 8; j++) {
        int4 v = p[j];
        bits |= (v.x != 0 ? 1u : 0u) << (j * 4 + 0);
        bits |= (v.y != 0 ? 1u : 0u) << (j * 4 + 1);
        bits |= (v.z != 0 ? 1u : 0u) << (j * 4 + 2);
        bits |= (v.w != 0 ? 1u : 0u) << (j * 4 + 3);
    }
    g_mpk[w] = bits;
}

__global__ void addpe_kernel(const float* __restrict__ x, const float* __restrict__ pe) {
    int i = blockIdx.x * 256 + threadIdx.x;       // 1,048,576 total
    g_x[i] = x[i] + pe[i & (SS*DD - 1)];          // pe broadcast over batch (SS*DD = 2^19)
}

// QKV projection: 16 rows/block, 256 threads (thread = output col c = h*32+kk)
__global__ void __launch_bounds__(256) qkv_kernel(const float* __restrict__ Wq,
                                                  const float* __restrict__ Wk,
                                                  const float* __restrict__ Wv) {
    __shared__ float Xs[16][DD];
    int c = threadIdx.x;
    int row0 = blockIdx.x * 16;
#pragma unroll
    for (int i = 0; i < 16; i++) Xs[i][c] = g_x[(row0 + i) * DD + c];
    __syncthreads();

    float aq[16], ak[16], av[16];
#pragma unroll
    for (int r = 0; r < 16; r++) { aq[r] = 0.f; ak[r] = 0.f; av[r] = 0.f; }

    // W layout (H, D, DK): element [h][d][kk] at h*8192 + d*32 + kk
    int wbase = (c >> 5) * 8192 + (c & 31);
#pragma unroll 2
    for (int d = 0; d < DD; d++) {
        float wq = Wq[wbase + d * 32];
        float wk = Wk[wbase + d * 32];
        float wv = Wv[wbase + d * 32];
#pragma unroll
        for (int r = 0; r < 16; r++) {
            float xv = Xs[r][d];
            aq[r] = fmaf(xv, wq, aq[r]);
            ak[r] = fmaf(xv, wk, ak[r]);
            av[r] = fmaf(xv, wv, av[r]);
        }
    }
    int h = c >> 5, kk = c & 31;
#pragma unroll
    for (int r = 0; r < 16; r++) {
        int row = row0 + r;
        int b = row >> 11, s = row & 2047;
        int oi = ((b * HH + h) * SS + s) * DK + kk;
        g_q[oi] = aq[r]; g_k[oi] = ak[r]; g_v[oi] = av[r];
    }
}

// Flash attention: 128 queries/block (one per thread), 64-key tiles in shared
#define QT 128
#define KT 64
__global__ void __launch_bounds__(QT) attn_kernel() {
    __shared__ float Ks[KT * DK];
    __shared__ float Vs[KT * DK];

    int t = threadIdx.x;
    int bh = blockIdx.x >> 4;              // S/QT = 16 query tiles
    int qt = blockIdx.x & 15;
    int b = bh >> 3;
    int sq = qt * QT + t;

    const float* qptr = g_q + ((size_t)bh * SS + sq) * DK;
    float4 qv[8];
#pragma unroll
    for (int i = 0; i < 8; i++) qv[i] = reinterpret_cast<const float4*>(qptr)[i];

    float4 av[8];
#pragma unroll
    for (int i = 0; i < 8; i++) av[i] = make_float4(0.f, 0.f, 0.f, 0.f);
    float m = -INFINITY, lsum = 0.f;

    const float4* kbase = (const float4*)(g_k + (size_t)bh * SS * DK);
    const float4* vbase = (const float4*)(g_v + (size_t)bh * SS * DK);
    // packed mask row for this query: SS/32 = 64 words per row
    const unsigned int* mrow = g_mpk + ((size_t)b * SS + sq) * (SS / 32);

    for (int k0 = 0; k0 < SS; k0 += KT) {
        __syncthreads();
        // load K/V tiles: 512 float4 each, 128 threads x 4
#pragma unroll
        for (int j = 0; j < 4; j++) {
            ((float4*)Ks)[t + j * 128] = kbase[k0 * 8 + t + j * 128];
            ((float4*)Vs)[t + j * 128] = vbase[k0 * 8 + t + j * 128];
        }
        unsigned int mw0 = mrow[(k0 >> 5)];
        unsigned int mw1 = mrow[(k0 >> 5) + 1];
        __syncthreads();

        for (int half = 0; half < 2; half++) {
            unsigned int mw = half ? mw1 : mw0;
            int base = half * 32;
            for (int u = 0; u < 32; u++) {
                int sk = base + u;
                const float4* kr = (const float4*)(Ks + sk * DK);
                float d0 = 0.f, d1 = 0.f, d2 = 0.f, d3 = 0.f;
#pragma unroll
                for (int i = 0; i < 8; i++) {
                    float4 kk4 = kr[i];
                    d0 = fmaf(qv[i].x, kk4.x, d0);
                    d1 = fmaf(qv[i].y, kk4.y, d1);
                    d2 = fmaf(qv[i].z, kk4.z, d2);
                    d3 = fmaf(qv[i].w, kk4.w, d3);
                }
                float sc = ((d0 + d1) + (d2 + d3)) * SCALE;
                if ((mw >> u) & 1u) sc = NEG_MAX;
                if (sc > m) {                       // lazy rescale
                    float corr = __expf(m - sc);
                    m = sc;
                    lsum *= corr;
#pragma unroll
                    for (int i = 0; i < 8; i++) {
                        av[i].x *= corr; av[i].y *= corr;
                        av[i].z *= corr; av[i].w *= corr;
                    }
                }
                float p = __expf(sc - m);
                lsum += p;
                const float4* vr = (const float4*)(Vs + sk * DK);
#pragma unroll
                for (int i = 0; i < 8; i++) {
                    float4 vv = vr[i];
                    av[i].x = fmaf(p, vv.x, av[i].x);
                    av[i].y = fmaf(p, vv.y, av[i].y);
                    av[i].z = fmaf(p, vv.z, av[i].z);
                    av[i].w = fmaf(p, vv.w, av[i].w);
                }
            }
        }
    }
    float inv = 1.f / lsum;
    int h = bh & 7;
    float4* optr = (float4*)(g_o + ((size_t)b * SS + sq) * DD + h * DK);
#pragma unroll
    for (int i = 0; i < 8; i++) {
        float4 r = av[i];
        r.x *= inv; r.y *= inv; r.z *= inv; r.w *= inv;
        optr[i] = r;
    }
}

// Wo projection: g_t = g_o @ Wo + bo
__global__ void __launch_bounds__(256) wo_kernel(const float* __restrict__ W,
                                                 const float* __restrict__ bias) {
    __shared__ float Xs[16][DD];
    int c = threadIdx.x;
    int row0 = blockIdx.x * 16;
#pragma unroll
    for (int i = 0; i < 16; i++) Xs[i][c] = g_o[(row0 + i) * DD + c];
    __syncthreads();
    float acc[16];
#pragma unroll
    for (int r = 0; r < 16; r++) acc[r] = 0.f;
#pragma unroll 2
    for (int d = 0; d < DD; d++) {
        float w = W[d * DD + c];
#pragma unroll
        for (int r = 0; r < 16; r++) acc[r] = fmaf(Xs[r][d], w, acc[r]);
    }
    float bv = bias[c];
#pragma unroll
    for (int r = 0; r < 16; r++) g_t[(row0 + r) * DD + c] = acc[r] + bv;
}

// residual + layernorm: g_x = LN(g_t + g_x) * gamma + beta
__global__ void __launch_bounds__(256) ln_kernel(const float* __restrict__ gam,
                                                 const float* __restrict__ bet) {
    int row = blockIdx.x, t = threadIdx.x;
    int idx = row * DD + t;
    float v = g_t[idx] + g_x[idx];
    __shared__ float sh[8];
    float s = v;
#pragma unroll
    for (int o = 16; o; o >>= 1) s += __shfl_xor_sync(0xffffffffu, s, o);
    if ((t & 31) == 0) sh[t >> 5] = s;
    __syncthreads();
    if (t < 32) {
        float w = (t < 8) ? sh[t] : 0.f;
#pragma unroll
        for (int o = 4; o; o >>= 1) w += __shfl_xor_sync(0xffffffffu, w, o);
        if (t == 0) sh[0] = w;
    }
    __syncthreads();
    float mu = sh[0] * (1.f / DD);
    __syncthreads();
    float d = v - mu;
    float s2 = d * d;
#pragma unroll
    for (int o = 16; o; o >>= 1) s2 += __shfl_xor_sync(0xffffffffu, s2, o);
    if ((t & 31) == 0) sh[t >> 5] = s2;
    __syncthreads();
    if (t < 32) {
        float w = (t < 8) ? sh[t] : 0.f;
#pragma unroll
        for (int o = 4; o; o >>= 1) w += __shfl_xor_sync(0xffffffffu, w, o);
        if (t == 0) sh[0] = w;
    }
    __syncthreads();
    float var = sh[0] * (1.f / DD);
    float rstd = rsqrtf(var + 1e-7f);
    g_x[idx] = d * rstd * gam[t] + bet[t];
}

// FFN layer 1: g_hid = relu(g_x @ W1 + b1), N=1024, 4 cols/thread
__global__ void __launch_bounds__(256) ffn1_kernel(const float* __restrict__ W,
                                                   const float* __restrict__ bias) {
    __shared__ float Xs[16][DD];
    int t = threadIdx.x;
    int row0 = blockIdx.x * 16;
#pragma unroll
    for (int i = 0; i < 16; i++) Xs[i][t] = g_x[(row0 + i) * DD + t];
    __syncthreads();
    float acc[16][4];
#pragma unroll
    for (int r = 0; r < 16; r++)
#pragma unroll
        for (int j = 0; j < 4; j++) acc[r][j] = 0.f;
    for (int d = 0; d < DD; d++) {
        float w0 = W[d * FF + t];
        float w1 = W[d * FF + t + 256];
        float w2 = W[d * FF + t + 512];
        float w3 = W[d * FF + t + 768];
#pragma unroll
        for (int r = 0; r < 16; r++) {
            float xv = Xs[r][d];
            acc[r][0] = fmaf(xv, w0, acc[r][0]);
            acc[r][1] = fmaf(xv, w1, acc[r][1]);
            acc[r][2] = fmaf(xv, w2, acc[r][2]);
            acc[r][3] = fmaf(xv, w3, acc[r][3]);
        }
    }
#pragma unroll
    for (int j = 0; j < 4; j++) {
        float bv = bias[t + j * 256];
#pragma unroll
        for (int r = 0; r < 16; r++)
            g_hid[(row0 + r) * FF + t + j * 256] = fmaxf(acc[r][j] + bv, 0.f);
    }
}

// FFN layer 2: g_t = g_hid @ W2 + b2   (K=1024, 64KB dynamic smem)
__global__ void __launch_bounds__(256) ffn2_kernel(const float* __restrict__ W,
                                                   const float* __restrict__ bias) {
    extern __shared__ float Xs2[];   // [16][1024]
    int t = threadIdx.x;
    int row0 = blockIdx.x * 16;
#pragma unroll
    for (int i = 0; i < 16; i++)
#pragma unroll
        for (int j = 0; j < 4; j++)
            Xs2[i * FF + t + j * 256] = g_hid[(row0 + i) * FF + t + j * 256];
    __syncthreads();
    float acc[16];
#pragma unroll
    for (int r = 0; r < 16; r++) acc[r] = 0.f;
#pragma unroll 2
    for (int d = 0; d < FF; d++) {
        float w = W[d * DD + t];
#pragma unroll
        for (int r = 0; r < 16; r++) acc[r] = fmaf(Xs2[r * FF + d], w, acc[r]);
    }
    float bv = bias[t];
#pragma unroll
    for (int r = 0; r < 16; r++) g_t[(row0 + r) * DD + t] = acc[r] + bv;
}

__global__ void copy_kernel(float* __restrict__ out) {
    int i = blockIdx.x * 256 + threadIdx.x;
    out[i] = g_x[i];
}

// ---------------- launch ----------------
extern "C" void kernel_launch(void* const* d_in, const int* in_sizes, int n_in,
                              void* d_out, int out_size) {
    const float* x  = (const float*)d_in[0];
    const int*   mask = (const int*)d_in[1];     // jnp bool promoted to int32 by harness
    const float* pe = (const float*)d_in[2];
    const float* Wq = (const float*)d_in[3];
    const float* Wk = (const float*)d_in[4];
    const float* Wv = (const float*)d_in[5];
    const float* Wo = (const float*)d_in[6];
    const float* bo = (const float*)d_in[7];
    const float* ln1_g = (const float*)d_in[8];
    const float* ln1_b = (const float*)d_in[9];
    const float* W1 = (const float*)d_in[10];
    const float* b1 = (const float*)d_in[11];
    const float* W2 = (const float*)d_in[12];
    const float* b2 = (const float*)d_in[13];
    const float* ln2_g = (const float*)d_in[14];
    const float* ln2_b = (const float*)d_in[15];

    cudaFuncSetAttribute(ffn2_kernel, cudaFuncAttributeMaxDynamicSharedMemorySize, 65536);

    maskpack_kernel<<<(BB*SS*SS/32) / 256, 256>>>(mask);
    addpe_kernel<<<BS * DD / 256, 256>>>(x, pe);

    for (int l = 0; l < LL; l++) {
        qkv_kernel<<<BS / 16, 256>>>(Wq + l * HH * DD * DK,
                                     Wk + l * HH * DD * DK,
                                     Wv + l * HH * DD * DK);
        attn_kernel<<<BB * HH * (SS / QT), QT>>>();
        wo_kernel<<<BS / 16, 256>>>(Wo + l * DD * DD, bo + l * DD);
        ln_kernel<<<BS, 256>>>(ln1_g + l * DD, ln1_b + l * DD);
        ffn1_kernel<<<BS / 16, 256>>>(W1 + l * DD * FF, b1 + l * FF);
        ffn2_kernel<<<BS / 16, 256, 65536>>>(W2 + l * FF * DD, b2 + l * DD);
        ln_kernel<<<BS, 256>>>(ln2_g + l * DD, ln2_b + l * DD);
    }
    copy_kernel<<<BS * DD / 256, 256>>>((float*)d_out);
}

// round 7
// speedup vs baseline: 1.4440x; 1.4440x over previous
#include <cuda_runtime.h>
#include <math.h>

// Problem constants
#define BB 2
#define SS 2048
#define DD 256
#define HH 8
#define FF 1024
#define DK 32
#define LL 3
#define BS (BB*SS)            // 4096 rows
#define BHS (BB*HH*SS)        // 32768 query slots
#define NEG_MAX (-3.402823466e38f)
#define SCALE 0.17677669529663687f   // 1/sqrt(32)
#define NCHUNK 4
#define CHUNK (SS/NCHUNK)     // 512 keys per chunk

// ---------------- device scratch (static: no allocations allowed) ----------------
__device__ float g_x  [BS*DD];   // activations (residual stream)
__device__ float g_q  [BS*DD];   // [b][h][s][dk]
__device__ float g_k  [BS*DD];
__device__ float g_v  [BS*DD];
__device__ float g_o  [BS*DD];   // attention output, [b][s][h*dk]
__device__ float g_t  [BS*DD];   // pre-LN temp
__device__ float g_hid[BS*FF];   // FFN hidden
__device__ unsigned int g_mpk[BB*SS*SS/32];  // packed mask bits (1 MB)
// split-KV partials
__device__ float g_pm  [NCHUNK*BHS];
__device__ float g_pl  [NCHUNK*BHS];
__device__ float g_pacc[(size_t)NCHUNK*BHS*DK];

// ---------------- kernels ----------------

// Pack int32 mask (0/1) into bits: word w covers mask elements [32w, 32w+32)
__global__ void maskpack_kernel(const int* __restrict__ mask) {
    int w = blockIdx.x * 256 + threadIdx.x;        // 262144 words
    const int4* p = (const int4*)(mask) + w * 8;
    unsigned int bits = 0;
#pragma unroll
    for (int j = 0; j < 8; j++) {
        int4 v = p[j];
        bits |= (v.x != 0 ? 1u : 0u) << (j * 4 + 0);
        bits |= (v.y != 0 ? 1u : 0u) << (j * 4 + 1);
        bits |= (v.z != 0 ? 1u : 0u) << (j * 4 + 2);
        bits |= (v.w != 0 ? 1u : 0u) << (j * 4 + 3);
    }
    g_mpk[w] = bits;
}

__global__ void addpe_kernel(const float* __restrict__ x, const float* __restrict__ pe) {
    int i = blockIdx.x * 256 + threadIdx.x;       // 1,048,576 total
    g_x[i] = x[i] + pe[i & (SS*DD - 1)];          // pe broadcast over batch
}

// QKV projection: 16 rows/block, 256 threads (thread = output col c = h*32+kk)
__global__ void __launch_bounds__(256) qkv_kernel(const float* __restrict__ Wq,
                                                  const float* __restrict__ Wk,
                                                  const float* __restrict__ Wv) {
    __shared__ float4 Xs4[16][64];
    int t = threadIdx.x;
    int row0 = blockIdx.x * 16;
    const float4* gx4 = (const float4*)g_x;
#pragma unroll
    for (int j = 0; j < 4; j++) {
        int idx = t + j * 256;
        Xs4[idx >> 6][idx & 63] = gx4[(size_t)(row0 + (idx >> 6)) * 64 + (idx & 63)];
    }
    __syncthreads();

    float aq[16], ak[16], av[16];
#pragma unroll
    for (int r = 0; r < 16; r++) { aq[r] = 0.f; ak[r] = 0.f; av[r] = 0.f; }

    // W layout (H, D, DK): element [h][d][kk] at h*8192 + d*32 + kk
    int wbase = (t >> 5) * 8192 + (t & 31);
#pragma unroll 2
    for (int d4 = 0; d4 < 64; d4++) {
        int base = wbase + d4 * 128;
        float q0 = Wq[base], q1 = Wq[base + 32], q2 = Wq[base + 64], q3 = Wq[base + 96];
        float k0 = Wk[base], k1 = Wk[base + 32], k2 = Wk[base + 64], k3 = Wk[base + 96];
        float v0 = Wv[base], v1 = Wv[base + 32], v2 = Wv[base + 64], v3 = Wv[base + 96];
#pragma unroll
        for (int r = 0; r < 16; r++) {
            float4 xv = Xs4[r][d4];
            aq[r] = fmaf(xv.x, q0, aq[r]); aq[r] = fmaf(xv.y, q1, aq[r]);
            aq[r] = fmaf(xv.z, q2, aq[r]); aq[r] = fmaf(xv.w, q3, aq[r]);
            ak[r] = fmaf(xv.x, k0, ak[r]); ak[r] = fmaf(xv.y, k1, ak[r]);
            ak[r] = fmaf(xv.z, k2, ak[r]); ak[r] = fmaf(xv.w, k3, ak[r]);
            av[r] = fmaf(xv.x, v0, av[r]); av[r] = fmaf(xv.y, v1, av[r]);
            av[r] = fmaf(xv.z, v2, av[r]); av[r] = fmaf(xv.w, v3, av[r]);
        }
    }
    int h = t >> 5, kk = t & 31;
#pragma unroll
    for (int r = 0; r < 16; r++) {
        int row = row0 + r;
        int b = row >> 11, s = row & 2047;
        int oi = ((b * HH + h) * SS + s) * DK + kk;
        g_q[oi] = aq[r]; g_k[oi] = ak[r]; g_v[oi] = av[r];
    }
}

// Flash attention, split-KV: each block does CHUNK keys for 128 queries
#define QT 128
#define KT 64
__global__ void __launch_bounds__(QT) attn_kernel() {
    __shared__ float Ks[KT * DK];
    __shared__ float Vs[KT * DK];

    int t = threadIdx.x;
    int cid = blockIdx.x & (NCHUNK - 1);
    int qb = blockIdx.x >> 2;              // NCHUNK==4
    int bh = qb >> 4;                      // S/QT = 16 query tiles
    int qt = qb & 15;
    int b = bh >> 3;
    int sq = qt * QT + t;

    const float* qptr = g_q + ((size_t)bh * SS + sq) * DK;
    float4 qv[8];
#pragma unroll
    for (int i = 0; i < 8; i++) qv[i] = reinterpret_cast<const float4*>(qptr)[i];

    float4 av[8];
#pragma unroll
    for (int i = 0; i < 8; i++) av[i] = make_float4(0.f, 0.f, 0.f, 0.f);
    float m = -INFINITY, lsum = 0.f;

    const float4* kbase = (const float4*)(g_k + (size_t)bh * SS * DK);
    const float4* vbase = (const float4*)(g_v + (size_t)bh * SS * DK);
    const unsigned int* mrow = g_mpk + ((size_t)b * SS + sq) * (SS / 32);

    int kend = cid * CHUNK + CHUNK;
    for (int k0 = cid * CHUNK; k0 < kend; k0 += KT) {
        __syncthreads();
#pragma unroll
        for (int j = 0; j < 4; j++) {
            ((float4*)Ks)[t + j * 128] = kbase[k0 * 8 + t + j * 128];
            ((float4*)Vs)[t + j * 128] = vbase[k0 * 8 + t + j * 128];
        }
        unsigned int mw0 = mrow[(k0 >> 5)];
        unsigned int mw1 = mrow[(k0 >> 5) + 1];
        __syncthreads();

        for (int half = 0; half < 2; half++) {
            unsigned int mw = half ? mw1 : mw0;
            int base = half * 32;
            for (int u = 0; u < 32; u++) {
                int sk = base + u;
                const float4* kr = (const float4*)(Ks + sk * DK);
                float d0 = 0.f, d1 = 0.f, d2 = 0.f, d3 = 0.f;
#pragma unroll
                for (int i = 0; i < 8; i++) {
                    float4 kk4 = kr[i];
                    d0 = fmaf(qv[i].x, kk4.x, d0);
                    d1 = fmaf(qv[i].y, kk4.y, d1);
                    d2 = fmaf(qv[i].z, kk4.z, d2);
                    d3 = fmaf(qv[i].w, kk4.w, d3);
                }
                float sc = ((d0 + d1) + (d2 + d3)) * SCALE;
                if ((mw >> u) & 1u) sc = NEG_MAX;
                if (sc > m) {                       // lazy rescale
                    float corr = __expf(m - sc);
                    m = sc;
                    lsum *= corr;
#pragma unroll
                    for (int i = 0; i < 8; i++) {
                        av[i].x *= corr; av[i].y *= corr;
                        av[i].z *= corr; av[i].w *= corr;
                    }
                }
                float p = __expf(sc - m);
                lsum += p;
                const float4* vr = (const float4*)(Vs + sk * DK);
#pragma unroll
                for (int i = 0; i < 8; i++) {
                    float4 vv = vr[i];
                    av[i].x = fmaf(p, vv.x, av[i].x);
                    av[i].y = fmaf(p, vv.y, av[i].y);
                    av[i].z = fmaf(p, vv.z, av[i].z);
                    av[i].w = fmaf(p, vv.w, av[i].w);
                }
            }
        }
    }
    // store unnormalized partials
    int qidx = bh * SS + sq;
    g_pm[cid * BHS + qidx] = m;
    g_pl[cid * BHS + qidx] = lsum;
    float4* pp = (float4*)(g_pacc + ((size_t)cid * BHS + qidx) * DK);
#pragma unroll
    for (int i = 0; i < 8; i++) pp[i] = av[i];
}

// merge NCHUNK partials with log-sum-exp weights, write head-concat output
__global__ void __launch_bounds__(256) attn_combine_kernel() {
    int qidx = blockIdx.x * 256 + threadIdx.x;    // 0..BHS-1
    float gm = -INFINITY;
#pragma unroll
    for (int c = 0; c < NCHUNK; c++) gm = fmaxf(gm, g_pm[c * BHS + qidx]);
    float L = 0.f;
    float4 acc[8];
#pragma unroll
    for (int i = 0; i < 8; i++) acc[i] = make_float4(0.f, 0.f, 0.f, 0.f);
#pragma unroll
    for (int c = 0; c < NCHUNK; c++) {
        float w = __expf(g_pm[c * BHS + qidx] - gm);
        L += g_pl[c * BHS + qidx] * w;
        const float4* pp = (const float4*)(g_pacc + ((size_t)c * BHS + qidx) * DK);
#pragma unroll
        for (int i = 0; i < 8; i++) {
            float4 v = pp[i];
            acc[i].x = fmaf(v.x, w, acc[i].x);
            acc[i].y = fmaf(v.y, w, acc[i].y);
            acc[i].z = fmaf(v.z, w, acc[i].z);
            acc[i].w = fmaf(v.w, w, acc[i].w);
        }
    }
    float inv = 1.f / L;
    int bh = qidx >> 11, sq = qidx & 2047;
    int b = bh >> 3, h = bh & 7;
    float4* optr = (float4*)(g_o + ((size_t)b * SS + sq) * DD + h * DK);
#pragma unroll
    for (int i = 0; i < 8; i++) {
        float4 r = acc[i];
        r.x *= inv; r.y *= inv; r.z *= inv; r.w *= inv;
        optr[i] = r;
    }
}

// Wo projection: g_t = g_o @ Wo + bo
__global__ void __launch_bounds__(256) wo_kernel(const float* __restrict__ W,
                                                 const float* __restrict__ bias) {
    __shared__ float4 Xs4[16][64];
    int t = threadIdx.x;
    int row0 = blockIdx.x * 16;
    const float4* go4 = (const float4*)g_o;
#pragma unroll
    for (int j = 0; j < 4; j++) {
        int idx = t + j * 256;
        Xs4[idx >> 6][idx & 63] = go4[(size_t)(row0 + (idx >> 6)) * 64 + (idx & 63)];
    }
    __syncthreads();
    float acc[16];
#pragma unroll
    for (int r = 0; r < 16; r++) acc[r] = 0.f;
#pragma unroll 2
    for (int d4 = 0; d4 < 64; d4++) {
        int base = d4 * 4 * DD + t;
        float w0 = W[base], w1 = W[base + DD], w2 = W[base + 2 * DD], w3 = W[base + 3 * DD];
#pragma unroll
        for (int r = 0; r < 16; r++) {
            float4 xv = Xs4[r][d4];
            acc[r] = fmaf(xv.x, w0, acc[r]); acc[r] = fmaf(xv.y, w1, acc[r]);
            acc[r] = fmaf(xv.z, w2, acc[r]); acc[r] = fmaf(xv.w, w3, acc[r]);
        }
    }
    float bv = bias[t];
#pragma unroll
    for (int r = 0; r < 16; r++) g_t[(row0 + r) * DD + t] = acc[r] + bv;
}

// residual + layernorm: g_x = LN(g_t + g_x) * gamma + beta
__global__ void __launch_bounds__(256) ln_kernel(const float* __restrict__ gam,
                                                 const float* __restrict__ bet) {
    int row = blockIdx.x, t = threadIdx.x;
    int idx = row * DD + t;
    float v = g_t[idx] + g_x[idx];
    __shared__ float sh[8];
    float s = v;
#pragma unroll
    for (int o = 16; o; o >>= 1) s += __shfl_xor_sync(0xffffffffu, s, o);
    if ((t & 31) == 0) sh[t >> 5] = s;
    __syncthreads();
    if (t < 32) {
        float w = (t < 8) ? sh[t] : 0.f;
#pragma unroll
        for (int o = 4; o; o >>= 1) w += __shfl_xor_sync(0xffffffffu, w, o);
        if (t == 0) sh[0] = w;
    }
    __syncthreads();
    float mu = sh[0] * (1.f / DD);
    __syncthreads();
    float d = v - mu;
    float s2 = d * d;
#pragma unroll
    for (int o = 16; o; o >>= 1) s2 += __shfl_xor_sync(0xffffffffu, s2, o);
    if ((t & 31) == 0) sh[t >> 5] = s2;
    __syncthreads();
    if (t < 32) {
        float w = (t < 8) ? sh[t] : 0.f;
#pragma unroll
        for (int o = 4; o; o >>= 1) w += __shfl_xor_sync(0xffffffffu, w, o);
        if (t == 0) sh[0] = w;
    }
    __syncthreads();
    float var = sh[0] * (1.f / DD);
    float rstd = rsqrtf(var + 1e-7f);
    g_x[idx] = d * rstd * gam[t] + bet[t];
}

// FFN layer 1: g_hid = relu(g_x @ W1 + b1); grid (BS/16, 2), 2 cols/thread
__global__ void __launch_bounds__(256) ffn1_kernel(const float* __restrict__ W,
                                                   const float* __restrict__ bias) {
    __shared__ float4 Xs4[16][64];
    int t = threadIdx.x;
    int row0 = blockIdx.x * 16;
    int c0 = blockIdx.y * 512 + t;        // cols c0 and c0+256
    const float4* gx4 = (const float4*)g_x;
#pragma unroll
    for (int j = 0; j < 4; j++) {
        int idx = t + j * 256;
        Xs4[idx >> 6][idx & 63] = gx4[(size_t)(row0 + (idx >> 6)) * 64 + (idx & 63)];
    }
    __syncthreads();
    float a0[16], a1[16];
#pragma unroll
    for (int r = 0; r < 16; r++) { a0[r] = 0.f; a1[r] = 0.f; }
#pragma unroll 2
    for (int d4 = 0; d4 < 64; d4++) {
        int base = d4 * 4 * FF + c0;
        float w00 = W[base], w01 = W[base + FF], w02 = W[base + 2 * FF], w03 = W[base + 3 * FF];
        float w10 = W[base + 256], w11 = W[base + FF + 256],
              w12 = W[base + 2 * FF + 256], w13 = W[base + 3 * FF + 256];
#pragma unroll
        for (int r = 0; r < 16; r++) {
            float4 xv = Xs4[r][d4];
            a0[r] = fmaf(xv.x, w00, a0[r]); a0[r] = fmaf(xv.y, w01, a0[r]);
            a0[r] = fmaf(xv.z, w02, a0[r]); a0[r] = fmaf(xv.w, w03, a0[r]);
            a1[r] = fmaf(xv.x, w10, a1[r]); a1[r] = fmaf(xv.y, w11, a1[r]);
            a1[r] = fmaf(xv.z, w12, a1[r]); a1[r] = fmaf(xv.w, w13, a1[r]);
        }
    }
    float b0 = bias[c0], b1v = bias[c0 + 256];
#pragma unroll
    for (int r = 0; r < 16; r++) {
        g_hid[(size_t)(row0 + r) * FF + c0]       = fmaxf(a0[r] + b0, 0.f);
        g_hid[(size_t)(row0 + r) * FF + c0 + 256] = fmaxf(a1[r] + b1v, 0.f);
    }
}

// FFN layer 2: g_t = g_hid @ W2 + b2, K=1024 processed in 4 chunks of 256
__global__ void __launch_bounds__(256) ffn2_kernel(const float* __restrict__ W,
                                                   const float* __restrict__ bias) {
    __shared__ float4 Xs4[16][64];
    int t = threadIdx.x;
    int row0 = blockIdx.x * 16;
    const float4* gh4 = (const float4*)g_hid;
    float acc[16];
#pragma unroll
    for (int r = 0; r < 16; r++) acc[r] = 0.f;

    for (int kc = 0; kc < 4; kc++) {
        __syncthreads();
#pragma unroll
        for (int j = 0; j < 4; j++) {
            int idx = t + j * 256;
            Xs4[idx >> 6][idx & 63] =
                gh4[(size_t)(row0 + (idx >> 6)) * 256 + kc * 64 + (idx & 63)];
        }
        __syncthreads();
#pragma unroll 2
        for (int d4 = 0; d4 < 64; d4++) {
            int base = (kc * 256 + d4 * 4) * DD + t;
            float w0 = W[base], w1 = W[base + DD], w2 = W[base + 2 * DD], w3 = W[base + 3 * DD];
#pragma unroll
            for (int r = 0; r < 16; r++) {
                float4 xv = Xs4[r][d4];
                acc[r] = fmaf(xv.x, w0, acc[r]); acc[r] = fmaf(xv.y, w1, acc[r]);
                acc[r] = fmaf(xv.z, w2, acc[r]); acc[r] = fmaf(xv.w, w3, acc[r]);
            }
        }
    }
    float bv = bias[t];
#pragma unroll
    for (int r = 0; r < 16; r++) g_t[(row0 + r) * DD + t] = acc[r] + bv;
}

__global__ void copy_kernel(float* __restrict__ out) {
    int i = blockIdx.x * 256 + threadIdx.x;
    out[i] = g_x[i];
}

// ---------------- launch ----------------
extern "C" void kernel_launch(void* const* d_in, const int* in_sizes, int n_in,
                              void* d_out, int out_size) {
    const float* x  = (const float*)d_in[0];
    const int*   mask = (const int*)d_in[1];     // jnp bool promoted to int32
    const float* pe = (const float*)d_in[2];
    const float* Wq = (const float*)d_in[3];
    const float* Wk = (const float*)d_in[4];
    const float* Wv = (const float*)d_in[5];
    const float* Wo = (const float*)d_in[6];
    const float* bo = (const float*)d_in[7];
    const float* ln1_g = (const float*)d_in[8];
    const float* ln1_b = (const float*)d_in[9];
    const float* W1 = (const float*)d_in[10];
    const float* b1 = (const float*)d_in[11];
    const float* W2 = (const float*)d_in[12];
    const float* b2 = (const float*)d_in[13];
    const float* ln2_g = (const float*)d_in[14];
    const float* ln2_b = (const float*)d_in[15];

    maskpack_kernel<<<(BB*SS*SS/32) / 256, 256>>>(mask);
    addpe_kernel<<<BS * DD / 256, 256>>>(x, pe);

    for (int l = 0; l < LL; l++) {
        qkv_kernel<<<BS / 16, 256>>>(Wq + l * HH * DD * DK,
                                     Wk + l * HH * DD * DK,
                                     Wv + l * HH * DD * DK);
        attn_kernel<<<BB * HH * (SS / QT) * NCHUNK, QT>>>();
        attn_combine_kernel<<<BHS / 256, 256>>>();
        wo_kernel<<<BS / 16, 256>>>(Wo + l * DD * DD, bo + l * DD);
        ln_kernel<<<BS, 256>>>(ln1_g + l * DD, ln1_b + l * DD);
        ffn1_kernel<<<dim3(BS / 16, 2), 256>>>(W1 + l * DD * FF, b1 + l * FF);
        ffn2_kernel<<<BS / 16, 256>>>(W2 + l * FF * DD, b2 + l * DD);
        ln_kernel<<<BS, 256>>>(ln2_g + l * DD, ln2_b + l * DD);
    }
    copy_kernel<<<BS * DD / 256, 256>>>((float*)d_out);
}

// round 9
// speedup vs baseline: 2.5178x; 1.7436x over previous
#include <cuda_runtime.h>
#include <cuda_bf16.h>
#include <math.h>

// Problem constants
#define BB 2
#define SS 2048
#define DD 256
#define HH 8
#define FF 1024
#define DK 32
#define LL 3
#define BS (BB*SS)            // 4096 rows
#define NEG_MAX (-3.402823466e38f)
#define SCALE 0.17677669529663687f   // 1/sqrt(32)

typedef unsigned int uint32;

// ---------------- device scratch (static: no allocations allowed) ----------------
__device__ float g_x  [BS*DD];   // activations (residual stream)
__device__ float g_o  [BS*DD];   // attention output, [b][s][h*dk]
__device__ float g_t  [BS*DD];   // pre-LN temp
__device__ float g_hid[BS*FF];   // FFN hidden
__device__ unsigned int g_mpk[BB*SS*SS/32];        // packed mask bits (1 MB)
__device__ __nv_bfloat16 g_qh[BS*DD];  // Q bf16 [bh][s][dk]
__device__ __nv_bfloat16 g_kh[BS*DD];  // K bf16 [bh][s][dk]
__device__ __nv_bfloat16 g_vh[BS*DD];  // V bf16 transposed [bh][dk][s]

// ---------------- mma helpers ----------------
__device__ __forceinline__ void mma_bf16(float* c, const uint32* a, const uint32* b) {
    asm volatile(
        "mma.sync.aligned.m16n8k16.row.col.f32.bf16.bf16.f32 "
        "{%0,%1,%2,%3}, {%4,%5,%6,%7}, {%8,%9}, {%0,%1,%2,%3};\n"
        : "+f"(c[0]), "+f"(c[1]), "+f"(c[2]), "+f"(c[3])
        : "r"(a[0]), "r"(a[1]), "r"(a[2]), "r"(a[3]), "r"(b[0]), "r"(b[1]));
}
__device__ __forceinline__ uint32 pack_bf16(float lo, float hi) {
    uint32 d;
    asm("cvt.rn.bf16x2.f32 %0, %1, %2;" : "=r"(d) : "f"(hi), "f"(lo));
    return d;
}

// ---------------- kernels ----------------

// Pack int32 mask (0/1) into bits: word w covers mask elements [32w, 32w+32)
__global__ void maskpack_kernel(const int* __restrict__ mask) {
    int w = blockIdx.x * 256 + threadIdx.x;        // 262144 words
    const int4* p = (const int4*)(mask) + w * 8;
    unsigned int bits = 0;
#pragma unroll
    for (int j = 0; j < 8; j++) {
        int4 v = p[j];
        bits |= (v.x != 0 ? 1u : 0u) << (j * 4 + 0);
        bits |= (v.y != 0 ? 1u : 0u) << (j * 4 + 1);
        bits |= (v.z != 0 ? 1u : 0u) << (j * 4 + 2);
        bits |= (v.w != 0 ? 1u : 0u) << (j * 4 + 3);
    }
    g_mpk[w] = bits;
}

__global__ void addpe_kernel(const float* __restrict__ x, const float* __restrict__ pe) {
    int i = blockIdx.x * 256 + threadIdx.x;
    g_x[i] = x[i] + pe[i & (SS*DD - 1)];
}

// QKV projection: 16 rows/block, 256 threads; emits bf16 Q,K ([bh][s][dk]) and V^T ([bh][dk][s])
__global__ void __launch_bounds__(256) qkv_kernel(const float* __restrict__ Wq,
                                                  const float* __restrict__ Wk,
                                                  const float* __restrict__ Wv) {
    __shared__ float4 Xs4[16][64];
    int t = threadIdx.x;
    int row0 = blockIdx.x * 16;
    const float4* gx4 = (const float4*)g_x;
#pragma unroll
    for (int j = 0; j < 4; j++) {
        int idx = t + j * 256;
        Xs4[idx >> 6][idx & 63] = gx4[(size_t)(row0 + (idx >> 6)) * 64 + (idx & 63)];
    }
    __syncthreads();

    float aq[16], ak[16], av[16];
#pragma unroll
    for (int r = 0; r < 16; r++) { aq[r] = 0.f; ak[r] = 0.f; av[r] = 0.f; }

    // W layout (H, D, DK): element [h][d][kk] at h*8192 + d*32 + kk
    int wbase = (t >> 5) * 8192 + (t & 31);
#pragma unroll 2
    for (int d4 = 0; d4 < 64; d4++) {
        int base = wbase + d4 * 128;
        float q0 = Wq[base], q1 = Wq[base + 32], q2 = Wq[base + 64], q3 = Wq[base + 96];
        float k0 = Wk[base], k1 = Wk[base + 32], k2 = Wk[base + 64], k3 = Wk[base + 96];
        float v0 = Wv[base], v1 = Wv[base + 32], v2 = Wv[base + 64], v3 = Wv[base + 96];
#pragma unroll
        for (int r = 0; r < 16; r++) {
            float4 xv = Xs4[r][d4];
            aq[r] = fmaf(xv.x, q0, aq[r]); aq[r] = fmaf(xv.y, q1, aq[r]);
            aq[r] = fmaf(xv.z, q2, aq[r]); aq[r] = fmaf(xv.w, q3, aq[r]);
            ak[r] = fmaf(xv.x, k0, ak[r]); ak[r] = fmaf(xv.y, k1, ak[r]);
            ak[r] = fmaf(xv.z, k2, ak[r]); ak[r] = fmaf(xv.w, k3, ak[r]);
            av[r] = fmaf(xv.x, v0, av[r]); av[r] = fmaf(xv.y, v1, av[r]);
            av[r] = fmaf(xv.z, v2, av[r]); av[r] = fmaf(xv.w, v3, av[r]);
        }
    }
    int h = t >> 5, kk = t & 31;
    int b0r = row0 >> 11, s0 = row0 & 2047;
#pragma unroll
    for (int r = 0; r < 16; r++) {
        int oi = ((b0r * HH + h) * SS + s0 + r) * DK + kk;
        g_qh[oi] = __float2bfloat16(aq[r]);
        g_kh[oi] = __float2bfloat16(ak[r]);
    }
    // V transposed: thread owns dk=kk for 16 consecutive s -> one 32B store
    __align__(16) __nv_bfloat16 vb[16];
#pragma unroll
    for (int r = 0; r < 16; r++) vb[r] = __float2bfloat16(av[r]);
    size_t vi = ((size_t)(b0r * HH + h) * DK + kk) * SS + s0;
    ((float4*)(g_vh + vi))[0] = ((float4*)vb)[0];
    ((float4*)(g_vh + vi))[1] = ((float4*)vb)[1];
}

// ------------- tensor-core flash attention -------------
// block: 128 thr (4 warps), 64 queries of one (b,h); warp w owns rows w*16..w*16+15
#define KSTRIDE 20   // uints per Ks row (32 bf16 + pad = 80B)
#define VSTRIDE 36   // uints per Vt row (64 bf16 + pad = 144B)
__global__ void __launch_bounds__(128) attn_mma_kernel() {
    __shared__ uint32 Ks[64 * KSTRIDE];   // [key][dk pairs]
    __shared__ uint32 Vt[32 * VSTRIDE];   // [dk][key pairs]
    __shared__ uint32 Msk[128];           // 64 rows x 2 words

    int t = threadIdx.x;
    int lane = t & 31, w = t >> 5;
    int bh = blockIdx.x >> 5;             // 32 q-tiles of 64
    int qt = blockIdx.x & 31;
    int b = bh >> 3, h = bh & 7;
    int m0 = w * 16;
    int g = lane >> 2, q4 = lane & 3;

    int sq_lo = qt * 64 + m0 + g;         // global query rows for this lane
    // Q A-fragments (k = dk, two k16 frags), loaded straight from global
    const uint32* qrow_lo = (const uint32*)(g_qh + ((size_t)bh * SS + sq_lo) * DK);
    const uint32* qrow_hi = qrow_lo + 8 * (DK / 2);
    uint32 aq[2][4];
#pragma unroll
    for (int kk = 0; kk < 2; kk++) {
        int base = kk * 8 + q4;
        aq[kk][0] = qrow_lo[base];     aq[kk][1] = qrow_hi[base];
        aq[kk][2] = qrow_lo[base + 4]; aq[kk][3] = qrow_hi[base + 4];
    }

    float mr_lo = -INFINITY, mr_hi = -INFINITY, l_lo = 0.f, l_hi = 0.f;
    float o[4][4];
#pragma unroll
    for (int jn = 0; jn < 4; jn++)
#pragma unroll
        for (int e = 0; e < 4; e++) o[jn][e] = 0.f;

    const float4* ksrc = (const float4*)(g_kh + (size_t)bh * SS * DK);
    const unsigned int* mbase = g_mpk + (size_t)(b * SS + qt * 64) * (SS / 32);

    for (int k0 = 0; k0 < SS; k0 += 64) {
        __syncthreads();
        // stage K tile: 64 keys x 32 bf16 = 256 float4 (4 float4 per key row)
#pragma unroll
        for (int j = 0; j < 2; j++) {
            int idx = t + j * 128;                 // 256 float4
            int row = idx >> 2, c4 = idx & 3;
            *(float4*)&Ks[row * KSTRIDE + c4 * 4] = ksrc[k0 * 4 + idx];
        }
        // stage V^T tile: 32 rows x 128B
#pragma unroll
        for (int j = 0; j < 2; j++) {
            int idx = t + j * 128;
            int row = idx >> 3, c4 = idx & 7;
            *(float4*)&Vt[row * VSTRIDE + c4 * 4] =
                ((const float4*)(g_vh + ((size_t)bh * DK + row) * SS + k0))[c4];
        }
        // stage mask words: 64 rows x 2
        Msk[t] = mbase[(size_t)(t >> 1) * (SS / 32) + (k0 >> 5) + (t & 1)];
        __syncthreads();

        // ---- S = Q K^T ----
        float c[8][4];
#pragma unroll
        for (int j = 0; j < 8; j++) { c[j][0] = c[j][1] = c[j][2] = c[j][3] = 0.f; }
#pragma unroll
        for (int j = 0; j < 8; j++) {
            int krow = (8 * j + g) * KSTRIDE;
            uint32 bfr[2];
            bfr[0] = Ks[krow + q4];     bfr[1] = Ks[krow + q4 + 4];
            mma_bf16(c[j], aq[0], bfr);
            bfr[0] = Ks[krow + 8 + q4]; bfr[1] = Ks[krow + 8 + q4 + 4];
            mma_bf16(c[j], aq[1], bfr);
        }
        // ---- mask + scale ----
        uint32 ml0 = Msk[(m0 + g) * 2],     ml1 = Msk[(m0 + g) * 2 + 1];
        uint32 mh0 = Msk[(m0 + g + 8) * 2], mh1 = Msk[(m0 + g + 8) * 2 + 1];
#pragma unroll
        for (int j = 0; j < 8; j++) {
#pragma unroll
            for (int e = 0; e < 2; e++) {
                int bit = 8 * j + 2 * q4 + e;          // 0..63
                uint32 wl = (bit < 32) ? ml0 : ml1;
                uint32 wh = (bit < 32) ? mh0 : mh1;
                int bp = bit & 31;
                c[j][e]     = ((wl >> bp) & 1u) ? NEG_MAX : c[j][e] * SCALE;
                c[j][2 + e] = ((wh >> bp) & 1u) ? NEG_MAX : c[j][2 + e] * SCALE;
            }
        }
        // ---- online softmax ----
        float mx_lo = c[0][0], mx_hi = c[0][2];
#pragma unroll
        for (int j = 0; j < 8; j++) {
            mx_lo = fmaxf(mx_lo, fmaxf(c[j][0], c[j][1]));
            mx_hi = fmaxf(mx_hi, fmaxf(c[j][2], c[j][3]));
        }
        mx_lo = fmaxf(mx_lo, __shfl_xor_sync(0xffffffffu, mx_lo, 1));
        mx_lo = fmaxf(mx_lo, __shfl_xor_sync(0xffffffffu, mx_lo, 2));
        mx_hi = fmaxf(mx_hi, __shfl_xor_sync(0xffffffffu, mx_hi, 1));
        mx_hi = fmaxf(mx_hi, __shfl_xor_sync(0xffffffffu, mx_hi, 2));
        float mn_lo = fmaxf(mr_lo, mx_lo), mn_hi = fmaxf(mr_hi, mx_hi);
        float corr_lo = __expf(mr_lo - mn_lo), corr_hi = __expf(mr_hi - mn_hi);
        mr_lo = mn_lo; mr_hi = mn_hi;

        float sum_lo = 0.f, sum_hi = 0.f;
#pragma unroll
        for (int j = 0; j < 8; j++) {
            c[j][0] = __expf(c[j][0] - mn_lo); sum_lo += c[j][0];
            c[j][1] = __expf(c[j][1] - mn_lo); sum_lo += c[j][1];
            c[j][2] = __expf(c[j][2] - mn_hi); sum_hi += c[j][2];
            c[j][3] = __expf(c[j][3] - mn_hi); sum_hi += c[j][3];
        }
        sum_lo += __shfl_xor_sync(0xffffffffu, sum_lo, 1);
        sum_lo += __shfl_xor_sync(0xffffffffu, sum_lo, 2);
        sum_hi += __shfl_xor_sync(0xffffffffu, sum_hi, 1);
        sum_hi += __shfl_xor_sync(0xffffffffu, sum_hi, 2);
        l_lo = l_lo * corr_lo + sum_lo;
        l_hi = l_hi * corr_hi + sum_hi;
        // rescale O
#pragma unroll
        for (int jn = 0; jn < 4; jn++) {
            o[jn][0] *= corr_lo; o[jn][1] *= corr_lo;
            o[jn][2] *= corr_hi; o[jn][3] *= corr_hi;
        }
        // ---- pack P into A-fragments (C-frag pairs == A-frag pairs) ----
        uint32 pf[4][4];
#pragma unroll
        for (int jj = 0; jj < 4; jj++) {
            pf[jj][0] = pack_bf16(c[2 * jj][0],     c[2 * jj][1]);
            pf[jj][1] = pack_bf16(c[2 * jj][2],     c[2 * jj][3]);
            pf[jj][2] = pack_bf16(c[2 * jj + 1][0], c[2 * jj + 1][1]);
            pf[jj][3] = pack_bf16(c[2 * jj + 1][2], c[2 * jj + 1][3]);
        }
        // ---- O += P V ----
#pragma unroll
        for (int jn = 0; jn < 4; jn++) {
            int vrow = (8 * jn + g) * VSTRIDE;
#pragma unroll
            for (int jj = 0; jj < 4; jj++) {
                uint32 bfr[2];
                bfr[0] = Vt[vrow + 8 * jj + q4];
                bfr[1] = Vt[vrow + 8 * jj + q4 + 4];
                mma_bf16(o[jn], pf[jj], bfr);
            }
        }
    }
    // epilogue: normalize + write (head-concat layout)
    float inv_lo = 1.f / l_lo, inv_hi = 1.f / l_hi;
    float* orow_lo = g_o + ((size_t)b * SS + sq_lo) * DD + h * DK;
    float* orow_hi = orow_lo + 8 * DD;
#pragma unroll
    for (int jn = 0; jn < 4; jn++) {
        int col = 8 * jn + 2 * q4;
        float2 v0 = make_float2(o[jn][0] * inv_lo, o[jn][1] * inv_lo);
        float2 v1 = make_float2(o[jn][2] * inv_hi, o[jn][3] * inv_hi);
        *(float2*)(orow_lo + col) = v0;
        *(float2*)(orow_hi + col) = v1;
    }
}

// Wo projection: g_t = g_o @ Wo + bo
__global__ void __launch_bounds__(256) wo_kernel(const float* __restrict__ W,
                                                 const float* __restrict__ bias) {
    __shared__ float4 Xs4[16][64];
    int t = threadIdx.x;
    int row0 = blockIdx.x * 16;
    const float4* go4 = (const float4*)g_o;
#pragma unroll
    for (int j = 0; j < 4; j++) {
        int idx = t + j * 256;
        Xs4[idx >> 6][idx & 63] = go4[(size_t)(row0 + (idx >> 6)) * 64 + (idx & 63)];
    }
    __syncthreads();
    float acc[16];
#pragma unroll
    for (int r = 0; r < 16; r++) acc[r] = 0.f;
#pragma unroll 2
    for (int d4 = 0; d4 < 64; d4++) {
        int base = d4 * 4 * DD + t;
        float w0 = W[base], w1 = W[base + DD], w2 = W[base + 2 * DD], w3 = W[base + 3 * DD];
#pragma unroll
        for (int r = 0; r < 16; r++) {
            float4 xv = Xs4[r][d4];
            acc[r] = fmaf(xv.x, w0, acc[r]); acc[r] = fmaf(xv.y, w1, acc[r]);
            acc[r] = fmaf(xv.z, w2, acc[r]); acc[r] = fmaf(xv.w, w3, acc[r]);
        }
    }
    float bv = bias[t];
#pragma unroll
    for (int r = 0; r < 16; r++) g_t[(row0 + r) * DD + t] = acc[r] + bv;
}

// residual + layernorm: g_x = LN(g_t + g_x) * gamma + beta
__global__ void __launch_bounds__(256) ln_kernel(const float* __restrict__ gam,
                                                 const float* __restrict__ bet) {
    int row = blockIdx.x, t = threadIdx.x;
    int idx = row * DD + t;
    float v = g_t[idx] + g_x[idx];
    __shared__ float sh[8];
    float s = v;
#pragma unroll
    for (int o = 16; o; o >>= 1) s += __shfl_xor_sync(0xffffffffu, s, o);
    if ((t & 31) == 0) sh[t >> 5] = s;
    __syncthreads();
    if (t < 32) {
        float w = (t < 8) ? sh[t] : 0.f;
#pragma unroll
        for (int o = 4; o; o >>= 1) w += __shfl_xor_sync(0xffffffffu, w, o);
        if (t == 0) sh[0] = w;
    }
    __syncthreads();
    float mu = sh[0] * (1.f / DD);
    __syncthreads();
    float d = v - mu;
    float s2 = d * d;
#pragma unroll
    for (int o = 16; o; o >>= 1) s2 += __shfl_xor_sync(0xffffffffu, s2, o);
    if ((t & 31) == 0) sh[t >> 5] = s2;
    __syncthreads();
    if (t < 32) {
        float w = (t < 8) ? sh[t] : 0.f;
#pragma unroll
        for (int o = 4; o; o >>= 1) w += __shfl_xor_sync(0xffffffffu, w, o);
        if (t == 0) sh[0] = w;
    }
    __syncthreads();
    float var = sh[0] * (1.f / DD);
    float rstd = rsqrtf(var + 1e-7f);
    g_x[idx] = d * rstd * gam[t] + bet[t];
}

// FFN layer 1: g_hid = relu(g_x @ W1 + b1); grid (BS/16, 2), 2 cols/thread
__global__ void __launch_bounds__(256) ffn1_kernel(const float* __restrict__ W,
                                                   const float* __restrict__ bias) {
    __shared__ float4 Xs4[16][64];
    int t = threadIdx.x;
    int row0 = blockIdx.x * 16;
    int c0 = blockIdx.y * 512 + t;
    const float4* gx4 = (const float4*)g_x;
#pragma unroll
    for (int j = 0; j < 4; j++) {
        int idx = t + j * 256;
        Xs4[idx >> 6][idx & 63] = gx4[(size_t)(row0 + (idx >> 6)) * 64 + (idx & 63)];
    }
    __syncthreads();
    float a0[16], a1[16];
#pragma unroll
    for (int r = 0; r < 16; r++) { a0[r] = 0.f; a1[r] = 0.f; }
#pragma unroll 2
    for (int d4 = 0; d4 < 64; d4++) {
        int base = d4 * 4 * FF + c0;
        float w00 = W[base], w01 = W[base + FF], w02 = W[base + 2 * FF], w03 = W[base + 3 * FF];
        float w10 = W[base + 256], w11 = W[base + FF + 256],
              w12 = W[base + 2 * FF + 256], w13 = W[base + 3 * FF + 256];
#pragma unroll
        for (int r = 0; r < 16; r++) {
            float4 xv = Xs4[r][d4];
            a0[r] = fmaf(xv.x, w00, a0[r]); a0[r] = fmaf(xv.y, w01, a0[r]);
            a0[r] = fmaf(xv.z, w02, a0[r]); a0[r] = fmaf(xv.w, w03, a0[r]);
            a1[r] = fmaf(xv.x, w10, a1[r]); a1[r] = fmaf(xv.y, w11, a1[r]);
            a1[r] = fmaf(xv.z, w12, a1[r]); a1[r] = fmaf(xv.w, w13, a1[r]);
        }
    }
    float b0 = bias[c0], b1v = bias[c0 + 256];
#pragma unroll
    for (int r = 0; r < 16; r++) {
        g_hid[(size_t)(row0 + r) * FF + c0]       = fmaxf(a0[r] + b0, 0.f);
        g_hid[(size_t)(row0 + r) * FF + c0 + 256] = fmaxf(a1[r] + b1v, 0.f);
    }
}

// FFN layer 2: g_t = g_hid @ W2 + b2, K=1024 in 4 chunks of 256
__global__ void __launch_bounds__(256) ffn2_kernel(const float* __restrict__ W,
                                                   const float* __restrict__ bias) {
    __shared__ float4 Xs4[16][64];
    int t = threadIdx.x;
    int row0 = blockIdx.x * 16;
    const float4* gh4 = (const float4*)g_hid;
    float acc[16];
#pragma unroll
    for (int r = 0; r < 16; r++) acc[r] = 0.f;

    for (int kc = 0; kc < 4; kc++) {
        __syncthreads();
#pragma unroll
        for (int j = 0; j < 4; j++) {
            int idx = t + j * 256;
            Xs4[idx >> 6][idx & 63] =
                gh4[(size_t)(row0 + (idx >> 6)) * 256 + kc * 64 + (idx & 63)];
        }
        __syncthreads();
#pragma unroll 2
        for (int d4 = 0; d4 < 64; d4++) {
            int base = (kc * 256 + d4 * 4) * DD + t;
            float w0 = W[base], w1 = W[base + DD], w2 = W[base + 2 * DD], w3 = W[base + 3 * DD];
#pragma unroll
            for (int r = 0; r < 16; r++) {
                float4 xv = Xs4[r][d4];
                acc[r] = fmaf(xv.x, w0, acc[r]); acc[r] = fmaf(xv.y, w1, acc[r]);
                acc[r] = fmaf(xv.z, w2, acc[r]); acc[r] = fmaf(xv.w, w3, acc[r]);
            }
        }
    }
    float bv = bias[t];
#pragma unroll
    for (int r = 0; r < 16; r++) g_t[(row0 + r) * DD + t] = acc[r] + bv;
}

__global__ void copy_kernel(float* __restrict__ out) {
    int i = blockIdx.x * 256 + threadIdx.x;
    out[i] = g_x[i];
}

// ---------------- launch ----------------
extern "C" void kernel_launch(void* const* d_in, const int* in_sizes, int n_in,
                              void* d_out, int out_size) {
    const float* x  = (const float*)d_in[0];
    const int*   mask = (const int*)d_in[1];     // jnp bool promoted to int32
    const float* pe = (const float*)d_in[2];
    const float* Wq = (const float*)d_in[3];
    const float* Wk = (const float*)d_in[4];
    const float* Wv = (const float*)d_in[5];
    const float* Wo = (const float*)d_in[6];
    const float* bo = (const float*)d_in[7];
    const float* ln1_g = (const float*)d_in[8];
    const float* ln1_b = (const float*)d_in[9];
    const float* W1 = (const float*)d_in[10];
    const float* b1 = (const float*)d_in[11];
    const float* W2 = (const float*)d_in[12];
    const float* b2 = (const float*)d_in[13];
    const float* ln2_g = (const float*)d_in[14];
    const float* ln2_b = (const float*)d_in[15];

    maskpack_kernel<<<(BB*SS*SS/32) / 256, 256>>>(mask);
    addpe_kernel<<<BS * DD / 256, 256>>>(x, pe);

    for (int l = 0; l < LL; l++) {
        qkv_kernel<<<BS / 16, 256>>>(Wq + l * HH * DD * DK,
                                     Wk + l * HH * DD * DK,
                                     Wv + l * HH * DD * DK);
        attn_mma_kernel<<<BB * HH * (SS / 64), 128>>>();
        wo_kernel<<<BS / 16, 256>>>(Wo + l * DD * DD, bo + l * DD);
        ln_kernel<<<BS, 256>>>(ln1_g + l * DD, ln1_b + l * DD);
        ffn1_kernel<<<dim3(BS / 16, 2), 256>>>(W1 + l * DD * FF, b1 + l * FF);
        ffn2_kernel<<<BS / 16, 256>>>(W2 + l * FF * DD, b2 + l * DD);
        ln_kernel<<<BS, 256>>>(ln2_g + l * DD, ln2_b + l * DD);
    }
    copy_kernel<<<BS * DD / 256, 256>>>((float*)d_out);
}

// round 10
// speedup vs baseline: 4.1300x; 1.6403x over previous
#include <cuda_runtime.h>
#include <cuda_bf16.h>
#include <math.h>

// Problem constants
#define BB 2
#define SS 2048
#define DD 256
#define HH 8
#define FF 1024
#define DK 32
#define LL 3
#define BS (BB*SS)            // 4096 rows
#define NEG_MAX (-3.402823466e38f)
#define SCALE 0.17677669529663687f   // 1/sqrt(32)

typedef unsigned int uint32;

// ---------------- device scratch (static: no allocations allowed) ----------------
__device__ float g_x  [BS*DD];           // residual stream fp32
__device__ float g_t  [BS*DD];           // pre-LN temp fp32
__device__ __nv_bfloat16 g_xh[BS*DD], g_xl[BS*DD];      // x hi/lo
__device__ __nv_bfloat16 g_oh[BS*DD], g_ol[BS*DD];      // attn out hi/lo
__device__ __nv_bfloat16 g_hidh[BS*FF], g_hidl[BS*FF];  // FFN hidden hi/lo
__device__ unsigned int g_mpk[BB*SS*SS/32];             // packed mask bits
__device__ __nv_bfloat16 g_qh[BS*DD];    // Q bf16 [bh][s][dk]
__device__ __nv_bfloat16 g_kh[BS*DD];    // K bf16 [bh][s][dk]
__device__ __nv_bfloat16 g_vh[BS*DD];    // V bf16 transposed [bh][dk][s]
// split/transposed weights: layout [n][k], hi/lo
__device__ __nv_bfloat16 Wqkv_h[LL*768*DD], Wqkv_l[LL*768*DD];
__device__ __nv_bfloat16 Wo_h [LL*DD*DD],  Wo_l [LL*DD*DD];
__device__ __nv_bfloat16 W1_h [LL*FF*DD],  W1_l [LL*FF*DD];
__device__ __nv_bfloat16 W2_h [LL*DD*FF],  W2_l [LL*DD*FF];

// ---------------- helpers ----------------
__device__ __forceinline__ void mma_bf16(float* c, const uint32* a, const uint32* b) {
    asm volatile(
        "mma.sync.aligned.m16n8k16.row.col.f32.bf16.bf16.f32 "
        "{%0,%1,%2,%3}, {%4,%5,%6,%7}, {%8,%9}, {%0,%1,%2,%3};\n"
        : "+f"(c[0]), "+f"(c[1]), "+f"(c[2]), "+f"(c[3])
        : "r"(a[0]), "r"(a[1]), "r"(a[2]), "r"(a[3]), "r"(b[0]), "r"(b[1]));
}
__device__ __forceinline__ uint32 pack_bf16(float lo, float hi) {
    uint32 d;
    asm("cvt.rn.bf16x2.f32 %0, %1, %2;" : "=r"(d) : "f"(hi), "f"(lo));
    return d;
}
// split two floats into packed hi-word and lo-word
__device__ __forceinline__ void split2(float v0, float v1, uint32& hw, uint32& lw) {
    float h0 = __bfloat162float(__float2bfloat16(v0));
    float h1 = __bfloat162float(__float2bfloat16(v1));
    hw = pack_bf16(v0, v1);
    lw = pack_bf16(v0 - h0, v1 - h1);
}

// ---------------- mask / pe / weight prep ----------------
__global__ void maskpack_kernel(const int* __restrict__ mask) {
    int w = blockIdx.x * 256 + threadIdx.x;
    const int4* p = (const int4*)(mask) + w * 8;
    unsigned int bits = 0;
#pragma unroll
    for (int j = 0; j < 8; j++) {
        int4 v = p[j];
        bits |= (v.x != 0 ? 1u : 0u) << (j * 4 + 0);
        bits |= (v.y != 0 ? 1u : 0u) << (j * 4 + 1);
        bits |= (v.z != 0 ? 1u : 0u) << (j * 4 + 2);
        bits |= (v.w != 0 ? 1u : 0u) << (j * 4 + 3);
    }
    g_mpk[w] = bits;
}

__global__ void addpe_kernel(const float* __restrict__ x, const float* __restrict__ pe) {
    int i = blockIdx.x * 256 + threadIdx.x;
    float v = x[i] + pe[i & (SS*DD - 1)];
    g_x[i] = v;
    __nv_bfloat16 h = __float2bfloat16(v);
    g_xh[i] = h;
    g_xl[i] = __float2bfloat16(v - __bfloat162float(h));
}

// generic weight transpose+split: Wt[l][n][k] from W[l][k][n]
__global__ void wtsplit_kernel(const float* __restrict__ W,
                               __nv_bfloat16* __restrict__ Th,
                               __nv_bfloat16* __restrict__ Tl, int K, int N) {
    int idx = blockIdx.x * 256 + threadIdx.x;      // over LL*K*N
    int per = K * N;
    int l = idx / per, r = idx - l * per;
    int n = r / K, k = r - n * K;
    float v = W[(size_t)l * per + (size_t)k * N + n];
    __nv_bfloat16 h = __float2bfloat16(v);
    Th[idx] = h;
    Tl[idx] = __float2bfloat16(v - __bfloat162float(h));
}

// qkv weights: combined rows n = type*256 + h*32 + kk, k = d
__global__ void wqkvsplit_kernel(const float* __restrict__ Wq,
                                 const float* __restrict__ Wk,
                                 const float* __restrict__ Wv) {
    int idx = blockIdx.x * 256 + threadIdx.x;      // over LL*768*256
    int per = 768 * 256;
    int l = idx / per, r = idx - l * per;
    int n = r >> 8, k = r & 255;
    int type = n >> 8, nl = n & 255;
    int h = nl >> 5, kk = nl & 31;
    const float* W = (type == 0) ? Wq : ((type == 1) ? Wk : Wv);
    float v = W[(size_t)l * HH * DD * DK + h * DD * DK + k * DK + kk];
    __nv_bfloat16 hh = __float2bfloat16(v);
    Wqkv_h[idx] = hh;
    Wqkv_l[idx] = __float2bfloat16(v - __bfloat162float(hh));
}

// ---------------- tensor-core split-bf16 GEMM ----------------
// C[M=4096, N] = A[M,KD] * B^T (B stored [n][k] hi/lo). Tile 128x64, 256 thr.
// EPI 0: g_t = acc + bias (N=256 out stride)
// EPI 1: g_hid hi/lo = relu(acc + bias) (N=1024 out stride)
// EPI 2: qkv scatter (no bias)
#define KSTR 20   // u32 per smem row (32 bf16 + 16B pad)
template<int KD, int EPI>
__global__ void __launch_bounds__(256) gemm_kernel(
    const __nv_bfloat16* __restrict__ Ah, const __nv_bfloat16* __restrict__ Al,
    const __nv_bfloat16* __restrict__ Bh, const __nv_bfloat16* __restrict__ Bl,
    const float* __restrict__ bias)
{
    __shared__ uint32 Ash[128 * KSTR], Asl[128 * KSTR];
    __shared__ uint32 Bsh[64 * KSTR],  Bsl[64 * KSTR];
    int t = threadIdx.x, lane = t & 31, w = t >> 5;
    int m0 = blockIdx.x * 128;
    int g = lane >> 2, q4 = lane & 3;
    int mw = w * 16;

    float c[8][4];
#pragma unroll
    for (int nb = 0; nb < 8; nb++) { c[nb][0] = c[nb][1] = c[nb][2] = c[nb][3] = 0.f; }

    int arow = t >> 1, ac4 = (t & 1) * 2;          // A staging coords
    int brow = t >> 2, bc4 = t & 3;                // B staging coords

    for (int k0 = 0; k0 < KD; k0 += 32) {
        __syncthreads();
        {
            const uint4* sh = (const uint4*)(Ah + (size_t)(m0 + arow) * KD + k0);
            const uint4* sl = (const uint4*)(Al + (size_t)(m0 + arow) * KD + k0);
            *(uint4*)&Ash[arow * KSTR + ac4 * 4]       = sh[ac4];
            *(uint4*)&Ash[arow * KSTR + (ac4 + 1) * 4] = sh[ac4 + 1];
            *(uint4*)&Asl[arow * KSTR + ac4 * 4]       = sl[ac4];
            *(uint4*)&Asl[arow * KSTR + (ac4 + 1) * 4] = sl[ac4 + 1];
        }
        {
            size_t boff = (size_t)((size_t)blockIdx.y * 64 + brow) * KD + k0 + bc4 * 8;
            *(uint4*)&Bsh[brow * KSTR + bc4 * 4] = *(const uint4*)(Bh + boff);
            *(uint4*)&Bsl[brow * KSTR + bc4 * 4] = *(const uint4*)(Bl + boff);
        }
        __syncthreads();
#pragma unroll
        for (int kh = 0; kh < 2; kh++) {
            uint32 ah[4], al[4];
            int ab = (mw + g) * KSTR + kh * 8 + q4;
            ah[0] = Ash[ab];            ah[1] = Ash[ab + 8 * KSTR];
            ah[2] = Ash[ab + 4];        ah[3] = Ash[ab + 8 * KSTR + 4];
            al[0] = Asl[ab];            al[1] = Asl[ab + 8 * KSTR];
            al[2] = Asl[ab + 4];        al[3] = Asl[ab + 8 * KSTR + 4];
#pragma unroll
            for (int nb = 0; nb < 8; nb++) {
                int bb = (nb * 8 + g) * KSTR + kh * 8 + q4;
                uint32 bh2[2] = { Bsh[bb], Bsh[bb + 4] };
                uint32 bl2[2] = { Bsl[bb], Bsl[bb + 4] };
                mma_bf16(c[nb], ah, bh2);
                mma_bf16(c[nb], al, bh2);
                mma_bf16(c[nb], ah, bl2);
            }
        }
    }

    int r0 = m0 + mw + g;           // rows r0 and r0+8
    if (EPI == 0) {
#pragma unroll
        for (int nb = 0; nb < 8; nb++) {
            int col = blockIdx.y * 64 + nb * 8 + 2 * q4;
            float b0 = bias[col], b1 = bias[col + 1];
            *(float2*)&g_t[(size_t)r0 * DD + col] =
                make_float2(c[nb][0] + b0, c[nb][1] + b1);
            *(float2*)&g_t[(size_t)(r0 + 8) * DD + col] =
                make_float2(c[nb][2] + b0, c[nb][3] + b1);
        }
    } else if (EPI == 1) {
#pragma unroll
        for (int nb = 0; nb < 8; nb++) {
            int col = blockIdx.y * 64 + nb * 8 + 2 * q4;
            float b0 = bias[col], b1 = bias[col + 1];
            float v0 = fmaxf(c[nb][0] + b0, 0.f), v1 = fmaxf(c[nb][1] + b1, 0.f);
            float v2 = fmaxf(c[nb][2] + b0, 0.f), v3 = fmaxf(c[nb][3] + b1, 0.f);
            uint32 hw, lw;
            split2(v0, v1, hw, lw);
            ((uint32*)g_hidh)[((size_t)r0 * FF + col) >> 1] = hw;
            ((uint32*)g_hidl)[((size_t)r0 * FF + col) >> 1] = lw;
            split2(v2, v3, hw, lw);
            ((uint32*)g_hidh)[((size_t)(r0 + 8) * FF + col) >> 1] = hw;
            ((uint32*)g_hidl)[((size_t)(r0 + 8) * FF + col) >> 1] = lw;
        }
    } else {
        // qkv scatter: type 0=Q,1=K,2=V
        int type = blockIdx.y >> 2;
        int nbase = (blockIdx.y & 3) * 64;
        int b = r0 >> 11, s0 = r0 & 2047;          // s1 = s0+8 (same b)
#pragma unroll
        for (int nb = 0; nb < 8; nb++) {
            int nl = nbase + nb * 8 + 2 * q4;
            int h = nl >> 5, kk = nl & 31;
            if (type == 2) {
                size_t vb = ((size_t)(b * HH + h) * DK + kk) * SS;
                g_vh[vb + s0]             = __float2bfloat16(c[nb][0]);
                g_vh[vb + SS + s0]        = __float2bfloat16(c[nb][1]);
                g_vh[vb + s0 + 8]         = __float2bfloat16(c[nb][2]);
                g_vh[vb + SS + s0 + 8]    = __float2bfloat16(c[nb][3]);
            } else {
                __nv_bfloat16* dst = (type == 0) ? g_qh : g_kh;
                size_t i0 = (((size_t)(b * HH + h) * SS + s0) * DK + kk) >> 1;
                ((uint32*)dst)[i0]       = pack_bf16(c[nb][0], c[nb][1]);
                ((uint32*)dst)[i0 + 128] = pack_bf16(c[nb][2], c[nb][3]);  // s0+8: +8*DK/2
            }
        }
    }
}

// ------------- tensor-core flash attention (unchanged core, hi/lo epilogue) -------------
#define KSTRIDE 20
#define VSTRIDE 36
__global__ void __launch_bounds__(128) attn_mma_kernel() {
    __shared__ uint32 Ks[64 * KSTRIDE];
    __shared__ uint32 Vt[32 * VSTRIDE];
    __shared__ uint32 Msk[128];

    int t = threadIdx.x;
    int lane = t & 31, w = t >> 5;
    int bh = blockIdx.x >> 5;
    int qt = blockIdx.x & 31;
    int b = bh >> 3, h = bh & 7;
    int m0 = w * 16;
    int g = lane >> 2, q4 = lane & 3;

    int sq_lo = qt * 64 + m0 + g;
    const uint32* qrow_lo = (const uint32*)(g_qh + ((size_t)bh * SS + sq_lo) * DK);
    const uint32* qrow_hi = qrow_lo + 8 * (DK / 2);
    uint32 aq[2][4];
#pragma unroll
    for (int kk = 0; kk < 2; kk++) {
        int base = kk * 8 + q4;
        aq[kk][0] = qrow_lo[base];     aq[kk][1] = qrow_hi[base];
        aq[kk][2] = qrow_lo[base + 4]; aq[kk][3] = qrow_hi[base + 4];
    }

    float mr_lo = -INFINITY, mr_hi = -INFINITY, l_lo = 0.f, l_hi = 0.f;
    float o[4][4];
#pragma unroll
    for (int jn = 0; jn < 4; jn++)
#pragma unroll
        for (int e = 0; e < 4; e++) o[jn][e] = 0.f;

    const float4* ksrc = (const float4*)(g_kh + (size_t)bh * SS * DK);
    const unsigned int* mbase = g_mpk + (size_t)(b * SS + qt * 64) * (SS / 32);

    for (int k0 = 0; k0 < SS; k0 += 64) {
        __syncthreads();
#pragma unroll
        for (int j = 0; j < 2; j++) {
            int idx = t + j * 128;
            int row = idx >> 2, c4 = idx & 3;
            *(float4*)&Ks[row * KSTRIDE + c4 * 4] = ksrc[k0 * 4 + idx];
        }
#pragma unroll
        for (int j = 0; j < 2; j++) {
            int idx = t + j * 128;
            int row = idx >> 3, c4 = idx & 7;
            *(float4*)&Vt[row * VSTRIDE + c4 * 4] =
                ((const float4*)(g_vh + ((size_t)bh * DK + row) * SS + k0))[c4];
        }
        Msk[t] = mbase[(size_t)(t >> 1) * (SS / 32) + (k0 >> 5) + (t & 1)];
        __syncthreads();

        float c[8][4];
#pragma unroll
        for (int j = 0; j < 8; j++) { c[j][0] = c[j][1] = c[j][2] = c[j][3] = 0.f; }
#pragma unroll
        for (int j = 0; j < 8; j++) {
            int krow = (8 * j + g) * KSTRIDE;
            uint32 bfr[2];
            bfr[0] = Ks[krow + q4];     bfr[1] = Ks[krow + q4 + 4];
            mma_bf16(c[j], aq[0], bfr);
            bfr[0] = Ks[krow + 8 + q4]; bfr[1] = Ks[krow + 8 + q4 + 4];
            mma_bf16(c[j], aq[1], bfr);
        }
        uint32 ml0 = Msk[(m0 + g) * 2],     ml1 = Msk[(m0 + g) * 2 + 1];
        uint32 mh0 = Msk[(m0 + g + 8) * 2], mh1 = Msk[(m0 + g + 8) * 2 + 1];
#pragma unroll
        for (int j = 0; j < 8; j++) {
#pragma unroll
            for (int e = 0; e < 2; e++) {
                int bit = 8 * j + 2 * q4 + e;
                uint32 wl = (bit < 32) ? ml0 : ml1;
                uint32 wh = (bit < 32) ? mh0 : mh1;
                int bp = bit & 31;
                c[j][e]     = ((wl >> bp) & 1u) ? NEG_MAX : c[j][e] * SCALE;
                c[j][2 + e] = ((wh >> bp) & 1u) ? NEG_MAX : c[j][2 + e] * SCALE;
            }
        }
        float mx_lo = c[0][0], mx_hi = c[0][2];
#pragma unroll
        for (int j = 0; j < 8; j++) {
            mx_lo = fmaxf(mx_lo, fmaxf(c[j][0], c[j][1]));
            mx_hi = fmaxf(mx_hi, fmaxf(c[j][2], c[j][3]));
        }
        mx_lo = fmaxf(mx_lo, __shfl_xor_sync(0xffffffffu, mx_lo, 1));
        mx_lo = fmaxf(mx_lo, __shfl_xor_sync(0xffffffffu, mx_lo, 2));
        mx_hi = fmaxf(mx_hi, __shfl_xor_sync(0xffffffffu, mx_hi, 1));
        mx_hi = fmaxf(mx_hi, __shfl_xor_sync(0xffffffffu, mx_hi, 2));
        float mn_lo = fmaxf(mr_lo, mx_lo), mn_hi = fmaxf(mr_hi, mx_hi);
        float corr_lo = __expf(mr_lo - mn_lo), corr_hi = __expf(mr_hi - mn_hi);
        mr_lo = mn_lo; mr_hi = mn_hi;

        float sum_lo = 0.f, sum_hi = 0.f;
#pragma unroll
        for (int j = 0; j < 8; j++) {
            c[j][0] = __expf(c[j][0] - mn_lo); sum_lo += c[j][0];
            c[j][1] = __expf(c[j][1] - mn_lo); sum_lo += c[j][1];
            c[j][2] = __expf(c[j][2] - mn_hi); sum_hi += c[j][2];
            c[j][3] = __expf(c[j][3] - mn_hi); sum_hi += c[j][3];
        }
        sum_lo += __shfl_xor_sync(0xffffffffu, sum_lo, 1);
        sum_lo += __shfl_xor_sync(0xffffffffu, sum_lo, 2);
        sum_hi += __shfl_xor_sync(0xffffffffu, sum_hi, 1);
        sum_hi += __shfl_xor_sync(0xffffffffu, sum_hi, 2);
        l_lo = l_lo * corr_lo + sum_lo;
        l_hi = l_hi * corr_hi + sum_hi;
#pragma unroll
        for (int jn = 0; jn < 4; jn++) {
            o[jn][0] *= corr_lo; o[jn][1] *= corr_lo;
            o[jn][2] *= corr_hi; o[jn][3] *= corr_hi;
        }
        uint32 pf[4][4];
#pragma unroll
        for (int jj = 0; jj < 4; jj++) {
            pf[jj][0] = pack_bf16(c[2 * jj][0],     c[2 * jj][1]);
            pf[jj][1] = pack_bf16(c[2 * jj][2],     c[2 * jj][3]);
            pf[jj][2] = pack_bf16(c[2 * jj + 1][0], c[2 * jj + 1][1]);
            pf[jj][3] = pack_bf16(c[2 * jj + 1][2], c[2 * jj + 1][3]);
        }
#pragma unroll
        for (int jn = 0; jn < 4; jn++) {
            int vrow = (8 * jn + g) * VSTRIDE;
#pragma unroll
            for (int jj = 0; jj < 4; jj++) {
                uint32 bfr[2];
                bfr[0] = Vt[vrow + 8 * jj + q4];
                bfr[1] = Vt[vrow + 8 * jj + q4 + 4];
                mma_bf16(o[jn], pf[jj], bfr);
            }
        }
    }
    // epilogue: normalize, split hi/lo, write packed
    float inv_lo = 1.f / l_lo, inv_hi = 1.f / l_hi;
    size_t obase = ((size_t)b * SS + sq_lo) * DD + h * DK;     // rows sq_lo, +8
#pragma unroll
    for (int jn = 0; jn < 4; jn++) {
        int col = 8 * jn + 2 * q4;
        uint32 hw, lw;
        split2(o[jn][0] * inv_lo, o[jn][1] * inv_lo, hw, lw);
        ((uint32*)g_oh)[(obase + col) >> 1] = hw;
        ((uint32*)g_ol)[(obase + col) >> 1] = lw;
        split2(o[jn][2] * inv_hi, o[jn][3] * inv_hi, hw, lw);
        ((uint32*)g_oh)[(obase + 8 * DD + col) >> 1] = hw;
        ((uint32*)g_ol)[(obase + 8 * DD + col) >> 1] = lw;
    }
}

// residual + layernorm: g_x = LN(g_t + g_x) * gamma + beta (+ hi/lo outputs)
__global__ void __launch_bounds__(256) ln_kernel(const float* __restrict__ gam,
                                                 const float* __restrict__ bet) {
    int row = blockIdx.x, t = threadIdx.x;
    int idx = row * DD + t;
    float v = g_t[idx] + g_x[idx];
    __shared__ float sh[8];
    float s = v;
#pragma unroll
    for (int o = 16; o; o >>= 1) s += __shfl_xor_sync(0xffffffffu, s, o);
    if ((t & 31) == 0) sh[t >> 5] = s;
    __syncthreads();
    if (t < 32) {
        float w = (t < 8) ? sh[t] : 0.f;
#pragma unroll
        for (int o = 4; o; o >>= 1) w += __shfl_xor_sync(0xffffffffu, w, o);
        if (t == 0) sh[0] = w;
    }
    __syncthreads();
    float mu = sh[0] * (1.f / DD);
    __syncthreads();
    float d = v - mu;
    float s2 = d * d;
#pragma unroll
    for (int o = 16; o; o >>= 1) s2 += __shfl_xor_sync(0xffffffffu, s2, o);
    if ((t & 31) == 0) sh[t >> 5] = s2;
    __syncthreads();
    if (t < 32) {
        float w = (t < 8) ? sh[t] : 0.f;
#pragma unroll
        for (int o = 4; o; o >>= 1) w += __shfl_xor_sync(0xffffffffu, w, o);
        if (t == 0) sh[0] = w;
    }
    __syncthreads();
    float var = sh[0] * (1.f / DD);
    float rstd = rsqrtf(var + 1e-7f);
    float out = d * rstd * gam[t] + bet[t];
    g_x[idx] = out;
    __nv_bfloat16 hh = __float2bfloat16(out);
    g_xh[idx] = hh;
    g_xl[idx] = __float2bfloat16(out - __bfloat162float(hh));
}

__global__ void copy_kernel(float* __restrict__ out) {
    int i = blockIdx.x * 256 + threadIdx.x;
    out[i] = g_x[i];
}

// ---------------- launch ----------------
extern "C" void kernel_launch(void* const* d_in, const int* in_sizes, int n_in,
                              void* d_out, int out_size) {
    const float* x  = (const float*)d_in[0];
    const int*   mask = (const int*)d_in[1];     // jnp bool promoted to int32
    const float* pe = (const float*)d_in[2];
    const float* Wq = (const float*)d_in[3];
    const float* Wk = (const float*)d_in[4];
    const float* Wv = (const float*)d_in[5];
    const float* Wo = (const float*)d_in[6];
    const float* bo = (const float*)d_in[7];
    const float* ln1_g = (const float*)d_in[8];
    const float* ln1_b = (const float*)d_in[9];
    const float* W1 = (const float*)d_in[10];
    const float* b1 = (const float*)d_in[11];
    const float* W2 = (const float*)d_in[12];
    const float* b2 = (const float*)d_in[13];
    const float* ln2_g = (const float*)d_in[14];
    const float* ln2_b = (const float*)d_in[15];

    // device symbol addresses (host query; not a stream op, capture-safe)
    void *p_xh, *p_xl, *p_oh, *p_ol, *p_hh, *p_hl;
    void *p_wqkvh, *p_wqkvl, *p_woh, *p_wol, *p_w1h, *p_w1l, *p_w2h, *p_w2l;
    cudaGetSymbolAddress(&p_xh, g_xh);   cudaGetSymbolAddress(&p_xl, g_xl);
    cudaGetSymbolAddress(&p_oh, g_oh);   cudaGetSymbolAddress(&p_ol, g_ol);
    cudaGetSymbolAddress(&p_hh, g_hidh); cudaGetSymbolAddress(&p_hl, g_hidl);
    cudaGetSymbolAddress(&p_wqkvh, Wqkv_h); cudaGetSymbolAddress(&p_wqkvl, Wqkv_l);
    cudaGetSymbolAddress(&p_woh, Wo_h);  cudaGetSymbolAddress(&p_wol, Wo_l);
    cudaGetSymbolAddress(&p_w1h, W1_h);  cudaGetSymbolAddress(&p_w1l, W1_l);
    cudaGetSymbolAddress(&p_w2h, W2_h);  cudaGetSymbolAddress(&p_w2l, W2_l);
    const __nv_bfloat16 *xh = (const __nv_bfloat16*)p_xh, *xl = (const __nv_bfloat16*)p_xl;
    const __nv_bfloat16 *oh = (const __nv_bfloat16*)p_oh, *ol = (const __nv_bfloat16*)p_ol;
    const __nv_bfloat16 *hh = (const __nv_bfloat16*)p_hh, *hl = (const __nv_bfloat16*)p_hl;

    // one-time weight prep (idempotent, runs every call)
    wqkvsplit_kernel<<<LL * 768 * 256 / 256, 256>>>(Wq, Wk, Wv);
    wtsplit_kernel<<<LL * DD * DD / 256, 256>>>(Wo, (__nv_bfloat16*)p_woh, (__nv_bfloat16*)p_wol, DD, DD);
    wtsplit_kernel<<<LL * DD * FF / 256, 256>>>(W1, (__nv_bfloat16*)p_w1h, (__nv_bfloat16*)p_w1l, DD, FF);
    wtsplit_kernel<<<LL * FF * DD / 256, 256>>>(W2, (__nv_bfloat16*)p_w2h, (__nv_bfloat16*)p_w2l, FF, DD);
    maskpack_kernel<<<(BB*SS*SS/32) / 256, 256>>>(mask);
    addpe_kernel<<<BS * DD / 256, 256>>>(x, pe);

    for (int l = 0; l < LL; l++) {
        const __nv_bfloat16* wqh = (const __nv_bfloat16*)p_wqkvh + (size_t)l * 768 * DD;
        const __nv_bfloat16* wql = (const __nv_bfloat16*)p_wqkvl + (size_t)l * 768 * DD;
        const __nv_bfloat16* woh2 = (const __nv_bfloat16*)p_woh + (size_t)l * DD * DD;
        const __nv_bfloat16* wol2 = (const __nv_bfloat16*)p_wol + (size_t)l * DD * DD;
        const __nv_bfloat16* w1h2 = (const __nv_bfloat16*)p_w1h + (size_t)l * FF * DD;
        const __nv_bfloat16* w1l2 = (const __nv_bfloat16*)p_w1l + (size_t)l * FF * DD;
        const __nv_bfloat16* w2h2 = (const __nv_bfloat16*)p_w2h + (size_t)l * DD * FF;
        const __nv_bfloat16* w2l2 = (const __nv_bfloat16*)p_w2l + (size_t)l * DD * FF;

        gemm_kernel<256, 2><<<dim3(32, 12), 256>>>(xh, xl, wqh, wql, nullptr);       // QKV
        attn_mma_kernel<<<BB * HH * (SS / 64), 128>>>();
        gemm_kernel<256, 0><<<dim3(32, 4), 256>>>(oh, ol, woh2, wol2, bo + l * DD);  // Wo
        ln_kernel<<<BS, 256>>>(ln1_g + l * DD, ln1_b + l * DD);
        gemm_kernel<256, 1><<<dim3(32, 16), 256>>>(xh, xl, w1h2, w1l2, b1 + l * FF); // FFN1
        gemm_kernel<1024, 0><<<dim3(32, 4), 256>>>(hh, hl, w2h2, w2l2, b2 + l * DD); // FFN2
        ln_kernel<<<BS, 256>>>(ln2_g + l * DD, ln2_b + l * DD);
    }
    copy_kernel<<<BS * DD / 256, 256>>>((float*)d_out);
}

// round 12
// speedup vs baseline: 4.1823x; 1.0127x over previous
#include <cuda_runtime.h>
#include <cuda_bf16.h>
#include <math.h>

// Problem constants
#define BB 2
#define SS 2048
#define DD 256
#define HH 8
#define FF 1024
#define DK 32
#define LL 3
#define BS (BB*SS)            // 4096 rows
#define BHS (BB*HH*SS)        // 32768 query slots
#define NEG_MAX (-3.402823466e38f)
#define SCALE 0.17677669529663687f   // 1/sqrt(32)
#define NCHUNK 2
#define CHUNK (SS/NCHUNK)     // 1024 keys per split-KV chunk

typedef unsigned int uint32;

// ---------------- device scratch (static: no allocations allowed) ----------------
__device__ float g_x  [BS*DD];           // residual stream fp32
__device__ float g_t  [BS*DD];           // pre-LN temp fp32
__device__ __nv_bfloat16 g_xh[BS*DD], g_xl[BS*DD];      // x hi/lo
__device__ __nv_bfloat16 g_oh[BS*DD], g_ol[BS*DD];      // attn out hi/lo
__device__ __nv_bfloat16 g_hidh[BS*FF], g_hidl[BS*FF];  // FFN hidden hi/lo
__device__ unsigned int g_mpk[BB*SS*SS/32];             // packed mask bits
__device__ __nv_bfloat16 g_qh[BS*DD];    // Q bf16 [bh][s][dk]
__device__ __nv_bfloat16 g_kh[BS*DD];    // K bf16 [bh][s][dk]
__device__ __nv_bfloat16 g_vh[BS*DD];    // V bf16 transposed [bh][dk][s]
// split-KV partials
__device__ float g_pm[NCHUNK*BHS], g_pl[NCHUNK*BHS];
__device__ float g_pacc[(size_t)NCHUNK*BHS*DK];
// split/transposed weights: layout [n][k], hi/lo
__device__ __nv_bfloat16 Wqkv_h[LL*768*DD], Wqkv_l[LL*768*DD];
__device__ __nv_bfloat16 Wo_h [LL*DD*DD],  Wo_l [LL*DD*DD];
__device__ __nv_bfloat16 W1_h [LL*FF*DD],  W1_l [LL*FF*DD];
__device__ __nv_bfloat16 W2_h [LL*DD*FF],  W2_l [LL*DD*FF];

// ---------------- helpers ----------------
__device__ __forceinline__ void mma_bf16(float* c, const uint32* a, const uint32* b) {
    asm volatile(
        "mma.sync.aligned.m16n8k16.row.col.f32.bf16.bf16.f32 "
        "{%0,%1,%2,%3}, {%4,%5,%6,%7}, {%8,%9}, {%0,%1,%2,%3};\n"
        : "+f"(c[0]), "+f"(c[1]), "+f"(c[2]), "+f"(c[3])
        : "r"(a[0]), "r"(a[1]), "r"(a[2]), "r"(a[3]), "r"(b[0]), "r"(b[1]));
}
__device__ __forceinline__ uint32 pack_bf16(float lo, float hi) {
    uint32 d;
    asm("cvt.rn.bf16x2.f32 %0, %1, %2;" : "=r"(d) : "f"(hi), "f"(lo));
    return d;
}
__device__ __forceinline__ void split2(float v0, float v1, uint32& hw, uint32& lw) {
    float h0 = __bfloat162float(__float2bfloat16(v0));
    float h1 = __bfloat162float(__float2bfloat16(v1));
    hw = pack_bf16(v0, v1);
    lw = pack_bf16(v0 - h0, v1 - h1);
}

// ---------------- mask / pe / weight prep ----------------
__global__ void maskpack_kernel(const int* __restrict__ mask) {
    int w = blockIdx.x * 256 + threadIdx.x;
    const int4* p = (const int4*)(mask) + w * 8;
    unsigned int bits = 0;
#pragma unroll
    for (int j = 0; j < 8; j++) {
        int4 v = p[j];
        bits |= (v.x != 0 ? 1u : 0u) << (j * 4 + 0);
        bits |= (v.y != 0 ? 1u : 0u) << (j * 4 + 1);
        bits |= (v.z != 0 ? 1u : 0u) << (j * 4 + 2);
        bits |= (v.w != 0 ? 1u : 0u) << (j * 4 + 3);
    }
    g_mpk[w] = bits;
}

__global__ void addpe_kernel(const float* __restrict__ x, const float* __restrict__ pe) {
    int i = blockIdx.x * 256 + threadIdx.x;
    float v = x[i] + pe[i & (SS*DD - 1)];
    g_x[i] = v;
    __nv_bfloat16 h = __float2bfloat16(v);
    g_xh[i] = h;
    g_xl[i] = __float2bfloat16(v - __bfloat162float(h));
}

// generic weight transpose+split: Wt[l][n][k] from W[l][k][n]
__global__ void wtsplit_kernel(const float* __restrict__ W,
                               __nv_bfloat16* __restrict__ Th,
                               __nv_bfloat16* __restrict__ Tl, int K, int N) {
    int idx = blockIdx.x * 256 + threadIdx.x;
    int per = K * N;
    int l = idx / per, r = idx - l * per;
    int n = r / K, k = r - n * K;
    float v = W[(size_t)l * per + (size_t)k * N + n];
    __nv_bfloat16 h = __float2bfloat16(v);
    Th[idx] = h;
    Tl[idx] = __float2bfloat16(v - __bfloat162float(h));
}

// qkv weights: combined rows n = type*256 + h*32 + kk, k = d (hi + lo)
__global__ void wqkvsplit_kernel(const float* __restrict__ Wq,
                                 const float* __restrict__ Wk,
                                 const float* __restrict__ Wv) {
    int idx = blockIdx.x * 256 + threadIdx.x;
    int per = 768 * 256;
    int l = idx / per, r = idx - l * per;
    int n = r >> 8, k = r & 255;
    int type = n >> 8, nl = n & 255;
    int h = nl >> 5, kk = nl & 31;
    const float* W = (type == 0) ? Wq : ((type == 1) ? Wk : Wv);
    float v = W[(size_t)l * HH * DD * DK + h * DD * DK + k * DK + kk];
    __nv_bfloat16 hh = __float2bfloat16(v);
    Wqkv_h[idx] = hh;
    Wqkv_l[idx] = __float2bfloat16(v - __bfloat162float(hh));
}

// ---------------- tensor-core split-bf16 GEMM ----------------
// C[M=4096, N] = A[M,KD] * B^T (B stored [n][k]). Tile 128x64, 256 thr.
// NMMA=3: hi/lo split (fp32-grade). NMMA=1: plain bf16.
// EPI 0: g_t = acc + bias; EPI 1: g_hid hi/lo = relu(acc+bias);
// EPI 2: Q/K scatter (type = blockIdx.y>>2, 0..1); EPI 3: V scatter
#define KSTR 20   // u32 per smem row (32 bf16 + 16B pad)
template<int KD, int EPI, int NMMA>
__global__ void __launch_bounds__(256) gemm_kernel(
    const __nv_bfloat16* __restrict__ Ah, const __nv_bfloat16* __restrict__ Al,
    const __nv_bfloat16* __restrict__ Bh, const __nv_bfloat16* __restrict__ Bl,
    const float* __restrict__ bias)
{
    __shared__ uint32 Ash[128 * KSTR];
    __shared__ uint32 Asl[(NMMA == 3) ? 128 * KSTR : 4];
    __shared__ uint32 Bsh[64 * KSTR];
    __shared__ uint32 Bsl[(NMMA == 3) ? 64 * KSTR : 4];
    int t = threadIdx.x, lane = t & 31, w = t >> 5;
    int m0 = blockIdx.x * 128;
    int g = lane >> 2, q4 = lane & 3;
    int mw = w * 16;

    float c[8][4];
#pragma unroll
    for (int nb = 0; nb < 8; nb++) { c[nb][0] = c[nb][1] = c[nb][2] = c[nb][3] = 0.f; }

    int arow = t >> 1, ac4 = (t & 1) * 2;
    int brow = t >> 2, bc4 = t & 3;

    for (int k0 = 0; k0 < KD; k0 += 32) {
        __syncthreads();
        {
            const uint4* sh = (const uint4*)(Ah + (size_t)(m0 + arow) * KD + k0);
            *(uint4*)&Ash[arow * KSTR + ac4 * 4]       = sh[ac4];
            *(uint4*)&Ash[arow * KSTR + (ac4 + 1) * 4] = sh[ac4 + 1];
            if (NMMA == 3) {
                const uint4* sl = (const uint4*)(Al + (size_t)(m0 + arow) * KD + k0);
                *(uint4*)&Asl[arow * KSTR + ac4 * 4]       = sl[ac4];
                *(uint4*)&Asl[arow * KSTR + (ac4 + 1) * 4] = sl[ac4 + 1];
            }
        }
        {
            size_t boff = (size_t)((size_t)blockIdx.y * 64 + brow) * KD + k0 + bc4 * 8;
            *(uint4*)&Bsh[brow * KSTR + bc4 * 4] = *(const uint4*)(Bh + boff);
            if (NMMA == 3)
                *(uint4*)&Bsl[brow * KSTR + bc4 * 4] = *(const uint4*)(Bl + boff);
        }
        __syncthreads();
#pragma unroll
        for (int kh = 0; kh < 2; kh++) {
            uint32 ah[4], al[4];
            int ab = (mw + g) * KSTR + kh * 8 + q4;
            ah[0] = Ash[ab];            ah[1] = Ash[ab + 8 * KSTR];
            ah[2] = Ash[ab + 4];        ah[3] = Ash[ab + 8 * KSTR + 4];
            if (NMMA == 3) {
                al[0] = Asl[ab];        al[1] = Asl[ab + 8 * KSTR];
                al[2] = Asl[ab + 4];    al[3] = Asl[ab + 8 * KSTR + 4];
            }
#pragma unroll
            for (int nb = 0; nb < 8; nb++) {
                int bb = (nb * 8 + g) * KSTR + kh * 8 + q4;
                uint32 bh2[2] = { Bsh[bb], Bsh[bb + 4] };
                mma_bf16(c[nb], ah, bh2);
                if (NMMA == 3) {
                    uint32 bl2[2] = { Bsl[bb], Bsl[bb + 4] };
                    mma_bf16(c[nb], al, bh2);
                    mma_bf16(c[nb], ah, bl2);
                }
            }
        }
    }

    int r0 = m0 + mw + g;
    if (EPI == 0) {
#pragma unroll
        for (int nb = 0; nb < 8; nb++) {
            int col = blockIdx.y * 64 + nb * 8 + 2 * q4;
            float b0 = bias[col], b1 = bias[col + 1];
            *(float2*)&g_t[(size_t)r0 * DD + col] =
                make_float2(c[nb][0] + b0, c[nb][1] + b1);
            *(float2*)&g_t[(size_t)(r0 + 8) * DD + col] =
                make_float2(c[nb][2] + b0, c[nb][3] + b1);
        }
    } else if (EPI == 1) {
#pragma unroll
        for (int nb = 0; nb < 8; nb++) {
            int col = blockIdx.y * 64 + nb * 8 + 2 * q4;
            float b0 = bias[col], b1 = bias[col + 1];
            float v0 = fmaxf(c[nb][0] + b0, 0.f), v1 = fmaxf(c[nb][1] + b1, 0.f);
            float v2 = fmaxf(c[nb][2] + b0, 0.f), v3 = fmaxf(c[nb][3] + b1, 0.f);
            uint32 hw, lw;
            split2(v0, v1, hw, lw);
            ((uint32*)g_hidh)[((size_t)r0 * FF + col) >> 1] = hw;
            ((uint32*)g_hidl)[((size_t)r0 * FF + col) >> 1] = lw;
            split2(v2, v3, hw, lw);
            ((uint32*)g_hidh)[((size_t)(r0 + 8) * FF + col) >> 1] = hw;
            ((uint32*)g_hidl)[((size_t)(r0 + 8) * FF + col) >> 1] = lw;
        }
    } else if (EPI == 2) {
        // Q/K scatter: blockIdx.y 0..7, type 0=Q,1=K
        int type = blockIdx.y >> 2;
        int nbase = (blockIdx.y & 3) * 64;
        int b = r0 >> 11, s0 = r0 & 2047;
#pragma unroll
        for (int nb = 0; nb < 8; nb++) {
            int nl = nbase + nb * 8 + 2 * q4;
            int h = nl >> 5, kk = nl & 31;
            __nv_bfloat16* dst = (type == 0) ? g_qh : g_kh;
            size_t i0 = (((size_t)(b * HH + h) * SS + s0) * DK + kk) >> 1;
            ((uint32*)dst)[i0]       = pack_bf16(c[nb][0], c[nb][1]);
            ((uint32*)dst)[i0 + 128] = pack_bf16(c[nb][2], c[nb][3]);
        }
    } else {
        // V scatter (transposed): blockIdx.y 0..3
        int nbase = blockIdx.y * 64;
        int b = r0 >> 11, s0 = r0 & 2047;
#pragma unroll
        for (int nb = 0; nb < 8; nb++) {
            int nl = nbase + nb * 8 + 2 * q4;
            int h = nl >> 5, kk = nl & 31;
            size_t vb = ((size_t)(b * HH + h) * DK + kk) * SS;
            g_vh[vb + s0]             = __float2bfloat16(c[nb][0]);
            g_vh[vb + SS + s0]        = __float2bfloat16(c[nb][1]);
            g_vh[vb + s0 + 8]         = __float2bfloat16(c[nb][2]);
            g_vh[vb + SS + s0 + 8]    = __float2bfloat16(c[nb][3]);
        }
    }
}

// ------------- tensor-core flash attention, split-KV x2 -------------
#define KSTRIDE 20
#define VSTRIDE 36
__global__ void __launch_bounds__(128) attn_mma_kernel() {
    __shared__ uint32 Ks[64 * KSTRIDE];
    __shared__ uint32 Vt[32 * VSTRIDE];
    __shared__ uint32 Msk[128];

    int t = threadIdx.x;
    int lane = t & 31, w = t >> 5;
    int cid = blockIdx.x & (NCHUNK - 1);
    int qb = blockIdx.x >> 1;             // NCHUNK==2
    int bh = qb >> 5;
    int qt = qb & 31;
    int b = bh >> 3;
    int m0 = w * 16;
    int g = lane >> 2, q4 = lane & 3;

    int sq_lo = qt * 64 + m0 + g;
    const uint32* qrow_lo = (const uint32*)(g_qh + ((size_t)bh * SS + sq_lo) * DK);
    const uint32* qrow_hi = qrow_lo + 8 * (DK / 2);
    uint32 aq[2][4];
#pragma unroll
    for (int kk = 0; kk < 2; kk++) {
        int base = kk * 8 + q4;
        aq[kk][0] = qrow_lo[base];     aq[kk][1] = qrow_hi[base];
        aq[kk][2] = qrow_lo[base + 4]; aq[kk][3] = qrow_hi[base + 4];
    }

    float mr_lo = -INFINITY, mr_hi = -INFINITY, l_lo = 0.f, l_hi = 0.f;
    float o[4][4];
#pragma unroll
    for (int jn = 0; jn < 4; jn++)
#pragma unroll
        for (int e = 0; e < 4; e++) o[jn][e] = 0.f;

    const float4* ksrc = (const float4*)(g_kh + (size_t)bh * SS * DK);
    const unsigned int* mbase = g_mpk + (size_t)(b * SS + qt * 64) * (SS / 32);

    int kend = cid * CHUNK + CHUNK;
    for (int k0 = cid * CHUNK; k0 < kend; k0 += 64) {
        __syncthreads();
#pragma unroll
        for (int j = 0; j < 2; j++) {
            int idx = t + j * 128;
            int row = idx >> 2, c4 = idx & 3;
            *(float4*)&Ks[row * KSTRIDE + c4 * 4] = ksrc[k0 * 4 + idx];
        }
#pragma unroll
        for (int j = 0; j < 2; j++) {
            int idx = t + j * 128;
            int row = idx >> 3, c4 = idx & 7;
            *(float4*)&Vt[row * VSTRIDE + c4 * 4] =
                ((const float4*)(g_vh + ((size_t)bh * DK + row) * SS + k0))[c4];
        }
        Msk[t] = mbase[(size_t)(t >> 1) * (SS / 32) + (k0 >> 5) + (t & 1)];
        __syncthreads();

        float c[8][4];
#pragma unroll
        for (int j = 0; j < 8; j++) { c[j][0] = c[j][1] = c[j][2] = c[j][3] = 0.f; }
#pragma unroll
        for (int j = 0; j < 8; j++) {
            int krow = (8 * j + g) * KSTRIDE;
            uint32 bfr[2];
            bfr[0] = Ks[krow + q4];     bfr[1] = Ks[krow + q4 + 4];
            mma_bf16(c[j], aq[0], bfr);
            bfr[0] = Ks[krow + 8 + q4]; bfr[1] = Ks[krow + 8 + q4 + 4];
            mma_bf16(c[j], aq[1], bfr);
        }
        uint32 ml0 = Msk[(m0 + g) * 2],     ml1 = Msk[(m0 + g) * 2 + 1];
        uint32 mh0 = Msk[(m0 + g + 8) * 2], mh1 = Msk[(m0 + g + 8) * 2 + 1];
#pragma unroll
        for (int j = 0; j < 8; j++) {
#pragma unroll
            for (int e = 0; e < 2; e++) {
                int bit = 8 * j + 2 * q4 + e;
                uint32 wl = (bit < 32) ? ml0 : ml1;
                uint32 wh = (bit < 32) ? mh0 : mh1;
                int bp = bit & 31;
                c[j][e]     = ((wl >> bp) & 1u) ? NEG_MAX : c[j][e] * SCALE;
                c[j][2 + e] = ((wh >> bp) & 1u) ? NEG_MAX : c[j][2 + e] * SCALE;
            }
        }
        float mx_lo = c[0][0], mx_hi = c[0][2];
#pragma unroll
        for (int j = 0; j < 8; j++) {
            mx_lo = fmaxf(mx_lo, fmaxf(c[j][0], c[j][1]));
            mx_hi = fmaxf(mx_hi, fmaxf(c[j][2], c[j][3]));
        }
        mx_lo = fmaxf(mx_lo, __shfl_xor_sync(0xffffffffu, mx_lo, 1));
        mx_lo = fmaxf(mx_lo, __shfl_xor_sync(0xffffffffu, mx_lo, 2));
        mx_hi = fmaxf(mx_hi, __shfl_xor_sync(0xffffffffu, mx_hi, 1));
        mx_hi = fmaxf(mx_hi, __shfl_xor_sync(0xffffffffu, mx_hi, 2));
        float mn_lo = fmaxf(mr_lo, mx_lo), mn_hi = fmaxf(mr_hi, mx_hi);
        float corr_lo = __expf(mr_lo - mn_lo), corr_hi = __expf(mr_hi - mn_hi);
        mr_lo = mn_lo; mr_hi = mn_hi;

        float sum_lo = 0.f, sum_hi = 0.f;
#pragma unroll
        for (int j = 0; j < 8; j++) {
            c[j][0] = __expf(c[j][0] - mn_lo); sum_lo += c[j][0];
            c[j][1] = __expf(c[j][1] - mn_lo); sum_lo += c[j][1];
            c[j][2] = __expf(c[j][2] - mn_hi); sum_hi += c[j][2];
            c[j][3] = __expf(c[j][3] - mn_hi); sum_hi += c[j][3];
        }
        sum_lo += __shfl_xor_sync(0xffffffffu, sum_lo, 1);
        sum_lo += __shfl_xor_sync(0xffffffffu, sum_lo, 2);
        sum_hi += __shfl_xor_sync(0xffffffffu, sum_hi, 1);
        sum_hi += __shfl_xor_sync(0xffffffffu, sum_hi, 2);
        l_lo = l_lo * corr_lo + sum_lo;
        l_hi = l_hi * corr_hi + sum_hi;
#pragma unroll
        for (int jn = 0; jn < 4; jn++) {
            o[jn][0] *= corr_lo; o[jn][1] *= corr_lo;
            o[jn][2] *= corr_hi; o[jn][3] *= corr_hi;
        }
        uint32 pf[4][4];
#pragma unroll
        for (int jj = 0; jj < 4; jj++) {
            pf[jj][0] = pack_bf16(c[2 * jj][0],     c[2 * jj][1]);
            pf[jj][1] = pack_bf16(c[2 * jj][2],     c[2 * jj][3]);
            pf[jj][2] = pack_bf16(c[2 * jj + 1][0], c[2 * jj + 1][1]);
            pf[jj][3] = pack_bf16(c[2 * jj + 1][2], c[2 * jj + 1][3]);
        }
#pragma unroll
        for (int jn = 0; jn < 4; jn++) {
            int vrow = (8 * jn + g) * VSTRIDE;
#pragma unroll
            for (int jj = 0; jj < 4; jj++) {
                uint32 bfr[2];
                bfr[0] = Vt[vrow + 8 * jj + q4];
                bfr[1] = Vt[vrow + 8 * jj + q4 + 4];
                mma_bf16(o[jn], pf[jj], bfr);
            }
        }
    }
    // store unnormalized partials
    int qidx = bh * SS + sq_lo;       // rows qidx, qidx+8
    float* pp = g_pacc + ((size_t)cid * BHS + qidx) * DK;
#pragma unroll
    for (int jn = 0; jn < 4; jn++) {
        int col = 8 * jn + 2 * q4;
        *(float2*)&pp[col]          = make_float2(o[jn][0], o[jn][1]);
        *(float2*)&pp[8 * DK + col] = make_float2(o[jn][2], o[jn][3]);
    }
    if (q4 == 0) {
        g_pm[cid * BHS + qidx] = mr_lo;     g_pl[cid * BHS + qidx] = l_lo;
        g_pm[cid * BHS + qidx + 8] = mr_hi; g_pl[cid * BHS + qidx + 8] = l_hi;
    }
}

// merge 2 partials, normalize, write hi/lo attn output (head-concat layout)
__global__ void __launch_bounds__(256) attn_combine_kernel() {
    int q = blockIdx.x * 256 + threadIdx.x;   // 0..BHS-1
    float m0 = g_pm[q], m1 = g_pm[BHS + q];
    float gm = fmaxf(m0, m1);
    float w0 = __expf(m0 - gm), w1 = __expf(m1 - gm);
    float L = g_pl[q] * w0 + g_pl[BHS + q] * w1;
    float inv = 1.f / L;
    w0 *= inv; w1 *= inv;
    const float4* p0 = (const float4*)(g_pacc + (size_t)q * DK);
    const float4* p1 = (const float4*)(g_pacc + ((size_t)BHS + q) * DK);
    int bh = q >> 11, sq = q & 2047;
    int b = bh >> 3, h = bh & 7;
    size_t obase = ((size_t)b * SS + sq) * DD + h * DK;
    uint32* doh = (uint32*)g_oh + (obase >> 1);
    uint32* dol = (uint32*)g_ol + (obase >> 1);
#pragma unroll
    for (int i = 0; i < 8; i++) {
        float4 a = p0[i], bb = p1[i];
        float r0 = a.x * w0 + bb.x * w1, r1 = a.y * w0 + bb.y * w1;
        float r2 = a.z * w0 + bb.z * w1, r3 = a.w * w0 + bb.w * w1;
        uint32 hw, lw;
        split2(r0, r1, hw, lw);
        doh[i * 2] = hw; dol[i * 2] = lw;
        split2(r2, r3, hw, lw);
        doh[i * 2 + 1] = hw; dol[i * 2 + 1] = lw;
    }
}

// residual + layernorm: warp per row, 8 rows/block, shfl-only reductions
__global__ void __launch_bounds__(256) ln_kernel(const float* __restrict__ gam,
                                                 const float* __restrict__ bet) {
    int lane = threadIdx.x & 31, wrp = threadIdx.x >> 5;
    int row = blockIdx.x * 8 + wrp;
    const float4* t4 = (const float4*)(g_t + (size_t)row * DD) + lane * 2;
    const float4* x4 = (const float4*)(g_x + (size_t)row * DD) + lane * 2;
    float4 a0 = t4[0], a1 = t4[1], b0 = x4[0], b1 = x4[1];
    float v[8] = { a0.x + b0.x, a0.y + b0.y, a0.z + b0.z, a0.w + b0.w,
                   a1.x + b1.x, a1.y + b1.y, a1.z + b1.z, a1.w + b1.w };
    float s = 0.f;
#pragma unroll
    for (int i = 0; i < 8; i++) s += v[i];
#pragma unroll
    for (int o = 16; o; o >>= 1) s += __shfl_xor_sync(0xffffffffu, s, o);
    float mu = s * (1.f / DD);
    float s2 = 0.f;
#pragma unroll
    for (int i = 0; i < 8; i++) { float d = v[i] - mu; s2 += d * d; }
#pragma unroll
    for (int o = 16; o; o >>= 1) s2 += __shfl_xor_sync(0xffffffffu, s2, o);
    float rstd = rsqrtf(s2 * (1.f / DD) + 1e-7f);

    const float4* g4 = (const float4*)gam + lane * 2;
    const float4* be4 = (const float4*)bet + lane * 2;
    float4 gg0 = g4[0], gg1 = g4[1], bb0 = be4[0], bb1 = be4[1];
    float out[8];
    out[0] = (v[0] - mu) * rstd * gg0.x + bb0.x;
    out[1] = (v[1] - mu) * rstd * gg0.y + bb0.y;
    out[2] = (v[2] - mu) * rstd * gg0.z + bb0.z;
    out[3] = (v[3] - mu) * rstd * gg0.w + bb0.w;
    out[4] = (v[4] - mu) * rstd * gg1.x + bb1.x;
    out[5] = (v[5] - mu) * rstd * gg1.y + bb1.y;
    out[6] = (v[6] - mu) * rstd * gg1.z + bb1.z;
    out[7] = (v[7] - mu) * rstd * gg1.w + bb1.w;

    float4* xo = (float4*)(g_x + (size_t)row * DD) + lane * 2;
    xo[0] = make_float4(out[0], out[1], out[2], out[3]);
    xo[1] = make_float4(out[4], out[5], out[6], out[7]);
    uint32 hw[4], lw[4];
#pragma unroll
    for (int i = 0; i < 4; i++) split2(out[2 * i], out[2 * i + 1], hw[i], lw[i]);
    size_t wi = ((size_t)row * DD) / 2 + lane * 4;
    *(uint4*)((uint32*)g_xh + wi) = *(uint4*)hw;
    *(uint4*)((uint32*)g_xl + wi) = *(uint4*)lw;
}

__global__ void copy_kernel(float* __restrict__ out) {
    int i = blockIdx.x * 256 + threadIdx.x;
    out[i] = g_x[i];
}

// ---------------- launch ----------------
extern "C" void kernel_launch(void* const* d_in, const int* in_sizes, int n_in,
                              void* d_out, int out_size) {
    const float* x  = (const float*)d_in[0];
    const int*   mask = (const int*)d_in[1];     // jnp bool promoted to int32
    const float* pe = (const float*)d_in[2];
    const float* Wq = (const float*)d_in[3];
    const float* Wk = (const float*)d_in[4];
    const float* Wv = (const float*)d_in[5];
    const float* Wo = (const float*)d_in[6];
    const float* bo = (const float*)d_in[7];
    const float* ln1_g = (const float*)d_in[8];
    const float* ln1_b = (const float*)d_in[9];
    const float* W1 = (const float*)d_in[10];
    const float* b1 = (const float*)d_in[11];
    const float* W2 = (const float*)d_in[12];
    const float* b2 = (const float*)d_in[13];
    const float* ln2_g = (const float*)d_in[14];
    const float* ln2_b = (const float*)d_in[15];

    void *p_xh, *p_xl, *p_oh, *p_ol, *p_hh, *p_hl;
    void *p_wqkvh, *p_wqkvl, *p_woh, *p_wol, *p_w1h, *p_w1l, *p_w2h, *p_w2l;
    cudaGetSymbolAddress(&p_xh, g_xh);   cudaGetSymbolAddress(&p_xl, g_xl);
    cudaGetSymbolAddress(&p_oh, g_oh);   cudaGetSymbolAddress(&p_ol, g_ol);
    cudaGetSymbolAddress(&p_hh, g_hidh); cudaGetSymbolAddress(&p_hl, g_hidl);
    cudaGetSymbolAddress(&p_wqkvh, Wqkv_h); cudaGetSymbolAddress(&p_wqkvl, Wqkv_l);
    cudaGetSymbolAddress(&p_woh, Wo_h);  cudaGetSymbolAddress(&p_wol, Wo_l);
    cudaGetSymbolAddress(&p_w1h, W1_h);  cudaGetSymbolAddress(&p_w1l, W1_l);
    cudaGetSymbolAddress(&p_w2h, W2_h);  cudaGetSymbolAddress(&p_w2l, W2_l);
    const __nv_bfloat16 *xh = (const __nv_bfloat16*)p_xh, *xl = (const __nv_bfloat16*)p_xl;
    const __nv_bfloat16 *oh = (const __nv_bfloat16*)p_oh, *ol = (const __nv_bfloat16*)p_ol;
    const __nv_bfloat16 *hh = (const __nv_bfloat16*)p_hh, *hl = (const __nv_bfloat16*)p_hl;

    // weight prep (idempotent)
    wqkvsplit_kernel<<<LL * 768 * 256 / 256, 256>>>(Wq, Wk, Wv);
    wtsplit_kernel<<<LL * DD * DD / 256, 256>>>(Wo, (__nv_bfloat16*)p_woh, (__nv_bfloat16*)p_wol, DD, DD);
    wtsplit_kernel<<<LL * DD * FF / 256, 256>>>(W1, (__nv_bfloat16*)p_w1h, (__nv_bfloat16*)p_w1l, DD, FF);
    wtsplit_kernel<<<LL * FF * DD / 256, 256>>>(W2, (__nv_bfloat16*)p_w2h, (__nv_bfloat16*)p_w2l, FF, DD);
    maskpack_kernel<<<(BB*SS*SS/32) / 256, 256>>>(mask);
    addpe_kernel<<<BS * DD / 256, 256>>>(x, pe);

    for (int l = 0; l < LL; l++) {
        const __nv_bfloat16* wqh = (const __nv_bfloat16*)p_wqkvh + (size_t)l * 768 * DD;
        const __nv_bfloat16* wql = (const __nv_bfloat16*)p_wqkvl + (size_t)l * 768 * DD;
        const __nv_bfloat16* woh2 = (const __nv_bfloat16*)p_woh + (size_t)l * DD * DD;
        const __nv_bfloat16* wol2 = (const __nv_bfloat16*)p_wol + (size_t)l * DD * DD;
        const __nv_bfloat16* w1h2 = (const __nv_bfloat16*)p_w1h + (size_t)l * FF * DD;
        const __nv_bfloat16* w1l2 = (const __nv_bfloat16*)p_w1l + (size_t)l * FF * DD;
        const __nv_bfloat16* w2h2 = (const __nv_bfloat16*)p_w2h + (size_t)l * DD * FF;
        const __nv_bfloat16* w2l2 = (const __nv_bfloat16*)p_w2l + (size_t)l * DD * FF;

        // Q,K: fp32-grade 3-mma (softmax path). V: plain bf16 (linear path).
        gemm_kernel<256, 2, 3><<<dim3(32, 8), 256>>>(xh, xl, wqh, wql, nullptr);
        gemm_kernel<256, 3, 1><<<dim3(32, 4), 256>>>(xh, xl, wqh + (size_t)512 * DD,
                                                     wql + (size_t)512 * DD, nullptr);
        attn_mma_kernel<<<BB * HH * (SS / 64) * NCHUNK, 128>>>();
        attn_combine_kernel<<<BHS / 256, 256>>>();
        gemm_kernel<256, 0, 3><<<dim3(32, 4), 256>>>(oh, ol, woh2, wol2, bo + l * DD);  // Wo
        ln_kernel<<<BS / 8, 256>>>(ln1_g + l * DD, ln1_b + l * DD);
        gemm_kernel<256, 1, 3><<<dim3(32, 16), 256>>>(xh, xl, w1h2, w1l2, b1 + l * FF); // FFN1
        gemm_kernel<1024, 0, 3><<<dim3(32, 4), 256>>>(hh, hl, w2h2, w2l2, b2 + l * DD); // FFN2
        ln_kernel<<<BS / 8, 256>>>(ln2_g + l * DD, ln2_b + l * DD);
    }
    copy_kernel<<<BS * DD / 256, 256>>>((float*)d_out);
}

// round 13
// speedup vs baseline: 4.2273x; 1.0108x over previous
#include <cuda_runtime.h>
#include <cuda_bf16.h>
#include <math.h>

// Problem constants
#define BB 2
#define SS 2048
#define DD 256
#define HH 8
#define FF 1024
#define DK 32
#define LL 3
#define BS (BB*SS)            // 4096 rows
#define BHS (BB*HH*SS)        // 32768 query slots
#define NEG_MAX (-3.402823466e38f)
#define SCALE 0.17677669529663687f   // 1/sqrt(32)
#define NCHUNK 2
#define CHUNK (SS/NCHUNK)     // 1024 keys per split-KV chunk

typedef unsigned int uint32;

// ---------------- device scratch (static: no allocations allowed) ----------------
__device__ float g_x  [BS*DD];           // residual stream fp32
__device__ float g_t  [BS*DD];           // pre-LN temp fp32
__device__ __nv_bfloat16 g_xh[BS*DD], g_xl[BS*DD];      // x hi/lo
__device__ __nv_bfloat16 g_oh[BS*DD], g_ol[BS*DD];      // attn out hi/lo
__device__ __nv_bfloat16 g_hidh[BS*FF], g_hidl[BS*FF];  // FFN hidden hi/lo
__device__ unsigned int g_mpk[BB*SS*SS/32];             // packed mask bits
__device__ __nv_bfloat16 g_qh[BS*DD];    // Q bf16 [bh][s][dk]
__device__ __nv_bfloat16 g_kh[BS*DD];    // K bf16 [bh][s][dk]
__device__ __nv_bfloat16 g_vh[BS*DD];    // V bf16 transposed [bh][dk][s]
// split-KV partials
__device__ float g_pm[NCHUNK*BHS], g_pl[NCHUNK*BHS];
__device__ float g_pacc[(size_t)NCHUNK*BHS*DK];
// split/transposed weights: layout [n][k], hi/lo
__device__ __nv_bfloat16 Wqkv_h[LL*768*DD], Wqkv_l[LL*768*DD];
__device__ __nv_bfloat16 Wo_h [LL*DD*DD],  Wo_l [LL*DD*DD];
__device__ __nv_bfloat16 W1_h [LL*FF*DD],  W1_l [LL*FF*DD];
__device__ __nv_bfloat16 W2_h [LL*DD*FF],  W2_l [LL*DD*FF];

// ---------------- helpers ----------------
__device__ __forceinline__ void mma_bf16(float* c, const uint32* a, const uint32* b) {
    asm volatile(
        "mma.sync.aligned.m16n8k16.row.col.f32.bf16.bf16.f32 "
        "{%0,%1,%2,%3}, {%4,%5,%6,%7}, {%8,%9}, {%0,%1,%2,%3};\n"
        : "+f"(c[0]), "+f"(c[1]), "+f"(c[2]), "+f"(c[3])
        : "r"(a[0]), "r"(a[1]), "r"(a[2]), "r"(a[3]), "r"(b[0]), "r"(b[1]));
}
__device__ __forceinline__ uint32 pack_bf16(float lo, float hi) {
    uint32 d;
    asm("cvt.rn.bf16x2.f32 %0, %1, %2;" : "=r"(d) : "f"(hi), "f"(lo));
    return d;
}
__device__ __forceinline__ void split2(float v0, float v1, uint32& hw, uint32& lw) {
    float h0 = __bfloat162float(__float2bfloat16(v0));
    float h1 = __bfloat162float(__float2bfloat16(v1));
    hw = pack_bf16(v0, v1);
    lw = pack_bf16(v0 - h0, v1 - h1);
}
__device__ __forceinline__ void cp16(uint32 saddr, const void* gptr) {
    asm volatile("cp.async.cg.shared.global [%0], [%1], 16;\n" :: "r"(saddr), "l"(gptr));
}
__device__ __forceinline__ void cp4(uint32 saddr, const void* gptr) {
    asm volatile("cp.async.ca.shared.global [%0], [%1], 4;\n" :: "r"(saddr), "l"(gptr));
}
#define CP_COMMIT()  asm volatile("cp.async.commit_group;\n" ::: "memory")
#define CP_WAIT(n)   asm volatile("cp.async.wait_group %0;\n" :: "n"(n) : "memory")

// ---------------- mask / pe / weight prep ----------------
__global__ void maskpack_kernel(const int* __restrict__ mask) {
    int w = blockIdx.x * 256 + threadIdx.x;
    const int4* p = (const int4*)(mask) + w * 8;
    unsigned int bits = 0;
#pragma unroll
    for (int j = 0; j < 8; j++) {
        int4 v = p[j];
        bits |= (v.x != 0 ? 1u : 0u) << (j * 4 + 0);
        bits |= (v.y != 0 ? 1u : 0u) << (j * 4 + 1);
        bits |= (v.z != 0 ? 1u : 0u) << (j * 4 + 2);
        bits |= (v.w != 0 ? 1u : 0u) << (j * 4 + 3);
    }
    g_mpk[w] = bits;
}

__global__ void addpe_kernel(const float* __restrict__ x, const float* __restrict__ pe) {
    int i = blockIdx.x * 256 + threadIdx.x;
    float v = x[i] + pe[i & (SS*DD - 1)];
    g_x[i] = v;
    __nv_bfloat16 h = __float2bfloat16(v);
    g_xh[i] = h;
    g_xl[i] = __float2bfloat16(v - __bfloat162float(h));
}

// generic weight transpose+split: Wt[l][n][k] from W[l][k][n]
__global__ void wtsplit_kernel(const float* __restrict__ W,
                               __nv_bfloat16* __restrict__ Th,
                               __nv_bfloat16* __restrict__ Tl, int K, int N) {
    int idx = blockIdx.x * 256 + threadIdx.x;
    int per = K * N;
    int l = idx / per, r = idx - l * per;
    int n = r / K, k = r - n * K;
    float v = W[(size_t)l * per + (size_t)k * N + n];
    __nv_bfloat16 h = __float2bfloat16(v);
    Th[idx] = h;
    Tl[idx] = __float2bfloat16(v - __bfloat162float(h));
}

// qkv weights: combined rows n = type*256 + h*32 + kk, k = d (hi + lo)
__global__ void wqkvsplit_kernel(const float* __restrict__ Wq,
                                 const float* __restrict__ Wk,
                                 const float* __restrict__ Wv) {
    int idx = blockIdx.x * 256 + threadIdx.x;
    int per = 768 * 256;
    int l = idx / per, r = idx - l * per;
    int n = r >> 8, k = r & 255;
    int type = n >> 8, nl = n & 255;
    int h = nl >> 5, kk = nl & 31;
    const float* W = (type == 0) ? Wq : ((type == 1) ? Wk : Wv);
    float v = W[(size_t)l * HH * DD * DK + h * DD * DK + k * DK + kk];
    __nv_bfloat16 hh = __float2bfloat16(v);
    Wqkv_h[idx] = hh;
    Wqkv_l[idx] = __float2bfloat16(v - __bfloat162float(hh));
}

// ---------------- tensor-core split-bf16 GEMM ----------------
// C[M=4096, N] = A[M,KD] * B^T (B stored [n][k]). Tile 128x64, 256 thr.
// NMMA=3: hi/lo split (fp32-grade). NMMA=1: plain bf16.
// EPI 0: g_t = acc + bias; EPI 1: g_hid hi/lo = relu(acc+bias);
// EPI 2: QKV scatter (type = blockIdx.y>>2: 0=Q,1=K,2=V)
#define KSTR 20   // u32 per smem row (32 bf16 + 16B pad)
template<int KD, int EPI, int NMMA>
__global__ void __launch_bounds__(256) gemm_kernel(
    const __nv_bfloat16* __restrict__ Ah, const __nv_bfloat16* __restrict__ Al,
    const __nv_bfloat16* __restrict__ Bh, const __nv_bfloat16* __restrict__ Bl,
    const float* __restrict__ bias)
{
    __shared__ uint32 Ash[128 * KSTR];
    __shared__ uint32 Asl[(NMMA == 3) ? 128 * KSTR : 4];
    __shared__ uint32 Bsh[64 * KSTR];
    __shared__ uint32 Bsl[(NMMA == 3) ? 64 * KSTR : 4];
    int t = threadIdx.x, lane = t & 31, w = t >> 5;
    int m0 = blockIdx.x * 128;
    int g = lane >> 2, q4 = lane & 3;
    int mw = w * 16;

    float c[8][4];
#pragma unroll
    for (int nb = 0; nb < 8; nb++) { c[nb][0] = c[nb][1] = c[nb][2] = c[nb][3] = 0.f; }

    int arow = t >> 1, ac4 = (t & 1) * 2;
    int brow = t >> 2, bc4 = t & 3;

    for (int k0 = 0; k0 < KD; k0 += 32) {
        __syncthreads();
        {
            const uint4* sh = (const uint4*)(Ah + (size_t)(m0 + arow) * KD + k0);
            *(uint4*)&Ash[arow * KSTR + ac4 * 4]       = sh[ac4];
            *(uint4*)&Ash[arow * KSTR + (ac4 + 1) * 4] = sh[ac4 + 1];
            if (NMMA == 3) {
                const uint4* sl = (const uint4*)(Al + (size_t)(m0 + arow) * KD + k0);
                *(uint4*)&Asl[arow * KSTR + ac4 * 4]       = sl[ac4];
                *(uint4*)&Asl[arow * KSTR + (ac4 + 1) * 4] = sl[ac4 + 1];
            }
        }
        {
            size_t boff = (size_t)((size_t)blockIdx.y * 64 + brow) * KD + k0 + bc4 * 8;
            *(uint4*)&Bsh[brow * KSTR + bc4 * 4] = *(const uint4*)(Bh + boff);
            if (NMMA == 3)
                *(uint4*)&Bsl[brow * KSTR + bc4 * 4] = *(const uint4*)(Bl + boff);
        }
        __syncthreads();
#pragma unroll
        for (int kh = 0; kh < 2; kh++) {
            uint32 ah[4], al[4];
            int ab = (mw + g) * KSTR + kh * 8 + q4;
            ah[0] = Ash[ab];            ah[1] = Ash[ab + 8 * KSTR];
            ah[2] = Ash[ab + 4];        ah[3] = Ash[ab + 8 * KSTR + 4];
            if (NMMA == 3) {
                al[0] = Asl[ab];        al[1] = Asl[ab + 8 * KSTR];
                al[2] = Asl[ab + 4];    al[3] = Asl[ab + 8 * KSTR + 4];
            }
#pragma unroll
            for (int nb = 0; nb < 8; nb++) {
                int bb = (nb * 8 + g) * KSTR + kh * 8 + q4;
                uint32 bh2[2] = { Bsh[bb], Bsh[bb + 4] };
                mma_bf16(c[nb], ah, bh2);
                if (NMMA == 3) {
                    uint32 bl2[2] = { Bsl[bb], Bsl[bb + 4] };
                    mma_bf16(c[nb], al, bh2);
                    mma_bf16(c[nb], ah, bl2);
                }
            }
        }
    }

    int r0 = m0 + mw + g;
    if (EPI == 0) {
#pragma unroll
        for (int nb = 0; nb < 8; nb++) {
            int col = blockIdx.y * 64 + nb * 8 + 2 * q4;
            float b0 = bias[col], b1 = bias[col + 1];
            *(float2*)&g_t[(size_t)r0 * DD + col] =
                make_float2(c[nb][0] + b0, c[nb][1] + b1);
            *(float2*)&g_t[(size_t)(r0 + 8) * DD + col] =
                make_float2(c[nb][2] + b0, c[nb][3] + b1);
        }
    } else if (EPI == 1) {
#pragma unroll
        for (int nb = 0; nb < 8; nb++) {
            int col = blockIdx.y * 64 + nb * 8 + 2 * q4;
            float b0 = bias[col], b1 = bias[col + 1];
            float v0 = fmaxf(c[nb][0] + b0, 0.f), v1 = fmaxf(c[nb][1] + b1, 0.f);
            float v2 = fmaxf(c[nb][2] + b0, 0.f), v3 = fmaxf(c[nb][3] + b1, 0.f);
            uint32 hw, lw;
            split2(v0, v1, hw, lw);
            ((uint32*)g_hidh)[((size_t)r0 * FF + col) >> 1] = hw;
            ((uint32*)g_hidl)[((size_t)r0 * FF + col) >> 1] = lw;
            split2(v2, v3, hw, lw);
            ((uint32*)g_hidh)[((size_t)(r0 + 8) * FF + col) >> 1] = hw;
            ((uint32*)g_hidl)[((size_t)(r0 + 8) * FF + col) >> 1] = lw;
        }
    } else {
        // QKV scatter: blockIdx.y 0..11, type 0=Q,1=K,2=V
        int type = blockIdx.y >> 2;
        int nbase = (blockIdx.y & 3) * 64;
        int b = r0 >> 11, s0 = r0 & 2047;
#pragma unroll
        for (int nb = 0; nb < 8; nb++) {
            int nl = nbase + nb * 8 + 2 * q4;
            int h = nl >> 5, kk = nl & 31;
            if (type == 2) {
                size_t vb = ((size_t)(b * HH + h) * DK + kk) * SS;
                g_vh[vb + s0]             = __float2bfloat16(c[nb][0]);
                g_vh[vb + SS + s0]        = __float2bfloat16(c[nb][1]);
                g_vh[vb + s0 + 8]         = __float2bfloat16(c[nb][2]);
                g_vh[vb + SS + s0 + 8]    = __float2bfloat16(c[nb][3]);
            } else {
                __nv_bfloat16* dst = (type == 0) ? g_qh : g_kh;
                size_t i0 = (((size_t)(b * HH + h) * SS + s0) * DK + kk) >> 1;
                ((uint32*)dst)[i0]       = pack_bf16(c[nb][0], c[nb][1]);
                ((uint32*)dst)[i0 + 128] = pack_bf16(c[nb][2], c[nb][3]);
            }
        }
    }
}

// ------------- tensor-core flash attention, split-KV x2, cp.async 2-stage -------------
#define KSTRIDE 20
#define VSTRIDE 36
__global__ void __launch_bounds__(128) attn_mma_kernel() {
    __shared__ uint32 Ks[2][64 * KSTRIDE];
    __shared__ uint32 Vt[2][32 * VSTRIDE];
    __shared__ uint32 Msk[2][128];

    int t = threadIdx.x;
    int lane = t & 31, w = t >> 5;
    int cid = blockIdx.x & (NCHUNK - 1);
    int qb = blockIdx.x >> 1;             // NCHUNK==2
    int bh = qb >> 5;
    int qt = qb & 31;
    int b = bh >> 3;
    int m0 = w * 16;
    int g = lane >> 2, q4 = lane & 3;

    int sq_lo = qt * 64 + m0 + g;
    const uint32* qrow_lo = (const uint32*)(g_qh + ((size_t)bh * SS + sq_lo) * DK);
    const uint32* qrow_hi = qrow_lo + 8 * (DK / 2);
    uint32 aq[2][4];
#pragma unroll
    for (int kk = 0; kk < 2; kk++) {
        int base = kk * 8 + q4;
        aq[kk][0] = qrow_lo[base];     aq[kk][1] = qrow_hi[base];
        aq[kk][2] = qrow_lo[base + 4]; aq[kk][3] = qrow_hi[base + 4];
    }

    float mr_lo = -INFINITY, mr_hi = -INFINITY, l_lo = 0.f, l_hi = 0.f;
    float o[4][4];
#pragma unroll
    for (int jn = 0; jn < 4; jn++)
#pragma unroll
        for (int e = 0; e < 4; e++) o[jn][e] = 0.f;

    const float4* ksrc = (const float4*)(g_kh + (size_t)bh * SS * DK);
    const unsigned int* mbase = g_mpk + (size_t)(b * SS + qt * 64) * (SS / 32);

    // staging coordinates (fixed per thread)
    int krow = t >> 2, kc4 = t & 3;       // K: thread covers rows krow, krow+32
    int vrow_s = t >> 3, vc4 = t & 7;     // V: rows vrow_s, vrow_s+16
    uint32 ks0 = (uint32)__cvta_generic_to_shared(&Ks[0][krow * KSTRIDE + kc4 * 4]);
    uint32 ks1 = (uint32)__cvta_generic_to_shared(&Ks[0][(krow + 32) * KSTRIDE + kc4 * 4]);
    uint32 vs0 = (uint32)__cvta_generic_to_shared(&Vt[0][vrow_s * VSTRIDE + vc4 * 4]);
    uint32 vs1 = (uint32)__cvta_generic_to_shared(&Vt[0][(vrow_s + 16) * VSTRIDE + vc4 * 4]);
    uint32 ms0 = (uint32)__cvta_generic_to_shared(&Msk[0][t]);
    const uint32 kbufsz = (uint32)(64 * KSTRIDE * 4);
    const uint32 vbufsz = (uint32)(32 * VSTRIDE * 4);

    int kstart = cid * CHUNK;
    const int NT = CHUNK / 64;

    // prologue: issue tile 0 into buf 0
    {
        int k0 = kstart;
        cp16(ks0, ksrc + k0 * 4 + t);
        cp16(ks1, ksrc + k0 * 4 + t + 128);
        cp16(vs0, (const float4*)(g_vh + ((size_t)bh * DK + vrow_s) * SS + k0) + vc4);
        cp16(vs1, (const float4*)(g_vh + ((size_t)bh * DK + vrow_s + 16) * SS + k0) + vc4);
        cp4(ms0, mbase + (size_t)(t >> 1) * (SS / 32) + (k0 >> 5) + (t & 1));
        CP_COMMIT();
    }

    for (int i = 0; i < NT; i++) {
        int buf = i & 1;
        __syncthreads();                        // everyone done computing from buf^1
        if (i + 1 < NT) {
            int k0 = kstart + (i + 1) * 64;
            uint32 off = (buf ^ 1) ? 1u : 0u;
            cp16(ks0 + off * kbufsz, ksrc + k0 * 4 + t);
            cp16(ks1 + off * kbufsz, ksrc + k0 * 4 + t + 128);
            cp16(vs0 + off * vbufsz, (const float4*)(g_vh + ((size_t)bh * DK + vrow_s) * SS + k0) + vc4);
            cp16(vs1 + off * vbufsz, (const float4*)(g_vh + ((size_t)bh * DK + vrow_s + 16) * SS + k0) + vc4);
            cp4(ms0 + off * 512u, mbase + (size_t)(t >> 1) * (SS / 32) + (k0 >> 5) + (t & 1));
            CP_COMMIT();
            CP_WAIT(1);                          // tile i complete; tile i+1 in flight
        } else {
            CP_WAIT(0);
        }
        __syncthreads();                        // tile i visible to all threads

        // ---- compute tile i from buf ----
        float c[8][4];
#pragma unroll
        for (int j = 0; j < 8; j++) { c[j][0] = c[j][1] = c[j][2] = c[j][3] = 0.f; }
#pragma unroll
        for (int j = 0; j < 8; j++) {
            int kr = (8 * j + g) * KSTRIDE;
            uint32 bfr[2];
            bfr[0] = Ks[buf][kr + q4];     bfr[1] = Ks[buf][kr + q4 + 4];
            mma_bf16(c[j], aq[0], bfr);
            bfr[0] = Ks[buf][kr + 8 + q4]; bfr[1] = Ks[buf][kr + 8 + q4 + 4];
            mma_bf16(c[j], aq[1], bfr);
        }
        uint32 ml0 = Msk[buf][(m0 + g) * 2],     ml1 = Msk[buf][(m0 + g) * 2 + 1];
        uint32 mh0 = Msk[buf][(m0 + g + 8) * 2], mh1 = Msk[buf][(m0 + g + 8) * 2 + 1];
#pragma unroll
        for (int j = 0; j < 8; j++) {
#pragma unroll
            for (int e = 0; e < 2; e++) {
                int bit = 8 * j + 2 * q4 + e;
                uint32 wl = (bit < 32) ? ml0 : ml1;
                uint32 wh = (bit < 32) ? mh0 : mh1;
                int bp = bit & 31;
                c[j][e]     = ((wl >> bp) & 1u) ? NEG_MAX : c[j][e] * SCALE;
                c[j][2 + e] = ((wh >> bp) & 1u) ? NEG_MAX : c[j][2 + e] * SCALE;
            }
        }
        float mx_lo = c[0][0], mx_hi = c[0][2];
#pragma unroll
        for (int j = 0; j < 8; j++) {
            mx_lo = fmaxf(mx_lo, fmaxf(c[j][0], c[j][1]));
            mx_hi = fmaxf(mx_hi, fmaxf(c[j][2], c[j][3]));
        }
        mx_lo = fmaxf(mx_lo, __shfl_xor_sync(0xffffffffu, mx_lo, 1));
        mx_lo = fmaxf(mx_lo, __shfl_xor_sync(0xffffffffu, mx_lo, 2));
        mx_hi = fmaxf(mx_hi, __shfl_xor_sync(0xffffffffu, mx_hi, 1));
        mx_hi = fmaxf(mx_hi, __shfl_xor_sync(0xffffffffu, mx_hi, 2));
        float mn_lo = fmaxf(mr_lo, mx_lo), mn_hi = fmaxf(mr_hi, mx_hi);
        float corr_lo = __expf(mr_lo - mn_lo), corr_hi = __expf(mr_hi - mn_hi);
        mr_lo = mn_lo; mr_hi = mn_hi;

        float sum_lo = 0.f, sum_hi = 0.f;
#pragma unroll
        for (int j = 0; j < 8; j++) {
            c[j][0] = __expf(c[j][0] - mn_lo); sum_lo += c[j][0];
            c[j][1] = __expf(c[j][1] - mn_lo); sum_lo += c[j][1];
            c[j][2] = __expf(c[j][2] - mn_hi); sum_hi += c[j][2];
            c[j][3] = __expf(c[j][3] - mn_hi); sum_hi += c[j][3];
        }
        sum_lo += __shfl_xor_sync(0xffffffffu, sum_lo, 1);
        sum_lo += __shfl_xor_sync(0xffffffffu, sum_lo, 2);
        sum_hi += __shfl_xor_sync(0xffffffffu, sum_hi, 1);
        sum_hi += __shfl_xor_sync(0xffffffffu, sum_hi, 2);
        l_lo = l_lo * corr_lo + sum_lo;
        l_hi = l_hi * corr_hi + sum_hi;
#pragma unroll
        for (int jn = 0; jn < 4; jn++) {
            o[jn][0] *= corr_lo; o[jn][1] *= corr_lo;
            o[jn][2] *= corr_hi; o[jn][3] *= corr_hi;
        }
        uint32 pf[4][4];
#pragma unroll
        for (int jj = 0; jj < 4; jj++) {
            pf[jj][0] = pack_bf16(c[2 * jj][0],     c[2 * jj][1]);
            pf[jj][1] = pack_bf16(c[2 * jj][2],     c[2 * jj][3]);
            pf[jj][2] = pack_bf16(c[2 * jj + 1][0], c[2 * jj + 1][1]);
            pf[jj][3] = pack_bf16(c[2 * jj + 1][2], c[2 * jj + 1][3]);
        }
#pragma unroll
        for (int jn = 0; jn < 4; jn++) {
            int vr = (8 * jn + g) * VSTRIDE;
#pragma unroll
            for (int jj = 0; jj < 4; jj++) {
                uint32 bfr[2];
                bfr[0] = Vt[buf][vr + 8 * jj + q4];
                bfr[1] = Vt[buf][vr + 8 * jj + q4 + 4];
                mma_bf16(o[jn], pf[jj], bfr);
            }
        }
    }
    // store unnormalized partials
    int qidx = bh * SS + sq_lo;       // rows qidx, qidx+8
    float* pp = g_pacc + ((size_t)cid * BHS + qidx) * DK;
#pragma unroll
    for (int jn = 0; jn < 4; jn++) {
        int col = 8 * jn + 2 * q4;
        *(float2*)&pp[col]          = make_float2(o[jn][0], o[jn][1]);
        *(float2*)&pp[8 * DK + col] = make_float2(o[jn][2], o[jn][3]);
    }
    if (q4 == 0) {
        g_pm[cid * BHS + qidx] = mr_lo;     g_pl[cid * BHS + qidx] = l_lo;
        g_pm[cid * BHS + qidx + 8] = mr_hi; g_pl[cid * BHS + qidx + 8] = l_hi;
    }
}

// merge 2 partials, normalize, write hi/lo attn output (head-concat layout)
__global__ void __launch_bounds__(256) attn_combine_kernel() {
    int q = blockIdx.x * 256 + threadIdx.x;   // 0..BHS-1
    float m0 = g_pm[q], m1 = g_pm[BHS + q];
    float gm = fmaxf(m0, m1);
    float w0 = __expf(m0 - gm), w1 = __expf(m1 - gm);
    float L = g_pl[q] * w0 + g_pl[BHS + q] * w1;
    float inv = 1.f / L;
    w0 *= inv; w1 *= inv;
    const float4* p0 = (const float4*)(g_pacc + (size_t)q * DK);
    const float4* p1 = (const float4*)(g_pacc + ((size_t)BHS + q) * DK);
    int bh = q >> 11, sq = q & 2047;
    int b = bh >> 3, h = bh & 7;
    size_t obase = ((size_t)b * SS + sq) * DD + h * DK;
    uint32* doh = (uint32*)g_oh + (obase >> 1);
    uint32* dol = (uint32*)g_ol + (obase >> 1);
#pragma unroll
    for (int i = 0; i < 8; i++) {
        float4 a = p0[i], bb = p1[i];
        float r0 = a.x * w0 + bb.x * w1, r1 = a.y * w0 + bb.y * w1;
        float r2 = a.z * w0 + bb.z * w1, r3 = a.w * w0 + bb.w * w1;
        uint32 hw, lw;
        split2(r0, r1, hw, lw);
        doh[i * 2] = hw; dol[i * 2] = lw;
        split2(r2, r3, hw, lw);
        doh[i * 2 + 1] = hw; dol[i * 2 + 1] = lw;
    }
}

// residual + layernorm: warp per row, 8 rows/block, shfl-only reductions.
// outp == nullptr: write g_x + hi/lo. outp != nullptr (last layer): write outp only.
__global__ void __launch_bounds__(256) ln_kernel(const float* __restrict__ gam,
                                                 const float* __restrict__ bet,
                                                 float* __restrict__ outp) {
    int lane = threadIdx.x & 31, wrp = threadIdx.x >> 5;
    int row = blockIdx.x * 8 + wrp;
    const float4* t4 = (const float4*)(g_t + (size_t)row * DD) + lane * 2;
    const float4* x4 = (const float4*)(g_x + (size_t)row * DD) + lane * 2;
    float4 a0 = t4[0], a1 = t4[1], b0 = x4[0], b1 = x4[1];
    float v[8] = { a0.x + b0.x, a0.y + b0.y, a0.z + b0.z, a0.w + b0.w,
                   a1.x + b1.x, a1.y + b1.y, a1.z + b1.z, a1.w + b1.w };
    float s = 0.f;
#pragma unroll
    for (int i = 0; i < 8; i++) s += v[i];
#pragma unroll
    for (int o = 16; o; o >>= 1) s += __shfl_xor_sync(0xffffffffu, s, o);
    float mu = s * (1.f / DD);
    float s2 = 0.f;
#pragma unroll
    for (int i = 0; i < 8; i++) { float d = v[i] - mu; s2 += d * d; }
#pragma unroll
    for (int o = 16; o; o >>= 1) s2 += __shfl_xor_sync(0xffffffffu, s2, o);
    float rstd = rsqrtf(s2 * (1.f / DD) + 1e-7f);

    const float4* g4 = (const float4*)gam + lane * 2;
    const float4* be4 = (const float4*)bet + lane * 2;
    float4 gg0 = g4[0], gg1 = g4[1], bb0 = be4[0], bb1 = be4[1];
    float out[8];
    out[0] = (v[0] - mu) * rstd * gg0.x + bb0.x;
    out[1] = (v[1] - mu) * rstd * gg0.y + bb0.y;
    out[2] = (v[2] - mu) * rstd * gg0.z + bb0.z;
    out[3] = (v[3] - mu) * rstd * gg0.w + bb0.w;
    out[4] = (v[4] - mu) * rstd * gg1.x + bb1.x;
    out[5] = (v[5] - mu) * rstd * gg1.y + bb1.y;
    out[6] = (v[6] - mu) * rstd * gg1.z + bb1.z;
    out[7] = (v[7] - mu) * rstd * gg1.w + bb1.w;

    if (outp) {
        float4* oo = (float4*)(outp + (size_t)row * DD) + lane * 2;
        oo[0] = make_float4(out[0], out[1], out[2], out[3]);
        oo[1] = make_float4(out[4], out[5], out[6], out[7]);
    } else {
        float4* xo = (float4*)(g_x + (size_t)row * DD) + lane * 2;
        xo[0] = make_float4(out[0], out[1], out[2], out[3]);
        xo[1] = make_float4(out[4], out[5], out[6], out[7]);
        uint32 hw[4], lw[4];
#pragma unroll
        for (int i = 0; i < 4; i++) split2(out[2 * i], out[2 * i + 1], hw[i], lw[i]);
        size_t wi = ((size_t)row * DD) / 2 + lane * 4;
        *(uint4*)((uint32*)g_xh + wi) = *(uint4*)hw;
        *(uint4*)((uint32*)g_xl + wi) = *(uint4*)lw;
    }
}

// ---------------- launch ----------------
extern "C" void kernel_launch(void* const* d_in, const int* in_sizes, int n_in,
                              void* d_out, int out_size) {
    const float* x  = (const float*)d_in[0];
    const int*   mask = (const int*)d_in[1];     // jnp bool promoted to int32
    const float* pe = (const float*)d_in[2];
    const float* Wq = (const float*)d_in[3];
    const float* Wk = (const float*)d_in[4];
    const float* Wv = (const float*)d_in[5];
    const float* Wo = (const float*)d_in[6];
    const float* bo = (const float*)d_in[7];
    const float* ln1_g = (const float*)d_in[8];
    const float* ln1_b = (const float*)d_in[9];
    const float* W1 = (const float*)d_in[10];
    const float* b1 = (const float*)d_in[11];
    const float* W2 = (const float*)d_in[12];
    const float* b2 = (const float*)d_in[13];
    const float* ln2_g = (const float*)d_in[14];
    const float* ln2_b = (const float*)d_in[15];

    void *p_xh, *p_xl, *p_oh, *p_ol, *p_hh, *p_hl;
    void *p_wqkvh, *p_wqkvl, *p_woh, *p_wol, *p_w1h, *p_w1l, *p_w2h, *p_w2l;
    cudaGetSymbolAddress(&p_xh, g_xh);   cudaGetSymbolAddress(&p_xl, g_xl);
    cudaGetSymbolAddress(&p_oh, g_oh);   cudaGetSymbolAddress(&p_ol, g_ol);
    cudaGetSymbolAddress(&p_hh, g_hidh); cudaGetSymbolAddress(&p_hl, g_hidl);
    cudaGetSymbolAddress(&p_wqkvh, Wqkv_h); cudaGetSymbolAddress(&p_wqkvl, Wqkv_l);
    cudaGetSymbolAddress(&p_woh, Wo_h);  cudaGetSymbolAddress(&p_wol, Wo_l);
    cudaGetSymbolAddress(&p_w1h, W1_h);  cudaGetSymbolAddress(&p_w1l, W1_l);
    cudaGetSymbolAddress(&p_w2h, W2_h);  cudaGetSymbolAddress(&p_w2l, W2_l);
    const __nv_bfloat16 *xh = (const __nv_bfloat16*)p_xh, *xl = (const __nv_bfloat16*)p_xl;
    const __nv_bfloat16 *oh = (const __nv_bfloat16*)p_oh, *ol = (const __nv_bfloat16*)p_ol;
    const __nv_bfloat16 *hh = (const __nv_bfloat16*)p_hh, *hl = (const __nv_bfloat16*)p_hl;

    // weight prep (idempotent)
    wqkvsplit_kernel<<<LL * 768 * 256 / 256, 256>>>(Wq, Wk, Wv);
    wtsplit_kernel<<<LL * DD * DD / 256, 256>>>(Wo, (__nv_bfloat16*)p_woh, (__nv_bfloat16*)p_wol, DD, DD);
    wtsplit_kernel<<<LL * DD * FF / 256, 256>>>(W1, (__nv_bfloat16*)p_w1h, (__nv_bfloat16*)p_w1l, DD, FF);
    wtsplit_kernel<<<LL * FF * DD / 256, 256>>>(W2, (__nv_bfloat16*)p_w2h, (__nv_bfloat16*)p_w2l, FF, DD);
    maskpack_kernel<<<(BB*SS*SS/32) / 256, 256>>>(mask);
    addpe_kernel<<<BS * DD / 256, 256>>>(x, pe);

    for (int l = 0; l < LL; l++) {
        const __nv_bfloat16* wqh = (const __nv_bfloat16*)p_wqkvh + (size_t)l * 768 * DD;
        const __nv_bfloat16* wql = (const __nv_bfloat16*)p_wqkvl + (size_t)l * 768 * DD;
        const __nv_bfloat16* woh2 = (const __nv_bfloat16*)p_woh + (size_t)l * DD * DD;
        const __nv_bfloat16* wol2 = (const __nv_bfloat16*)p_wol + (size_t)l * DD * DD;
        const __nv_bfloat16* w1h2 = (const __nv_bfloat16*)p_w1h + (size_t)l * FF * DD;
        const __nv_bfloat16* w1l2 = (const __nv_bfloat16*)p_w1l + (size_t)l * FF * DD;
        const __nv_bfloat16* w2h2 = (const __nv_bfloat16*)p_w2h + (size_t)l * DD * FF;
        const __nv_bfloat16* w2l2 = (const __nv_bfloat16*)p_w2l + (size_t)l * DD * FF;

        // Q, K, V all fp32-grade 3-mma (V precision measurably matters: R12 post-mortem)
        gemm_kernel<256, 2, 3><<<dim3(32, 12), 256>>>(xh, xl, wqh, wql, nullptr);
        attn_mma_kernel<<<BB * HH * (SS / 64) * NCHUNK, 128>>>();
        attn_combine_kernel<<<BHS / 256, 256>>>();
        gemm_kernel<256, 0, 3><<<dim3(32, 4), 256>>>(oh, ol, woh2, wol2, bo + l * DD);  // Wo
        ln_kernel<<<BS / 8, 256>>>(ln1_g + l * DD, ln1_b + l * DD, nullptr);
        gemm_kernel<256, 1, 3><<<dim3(32, 16), 256>>>(xh, xl, w1h2, w1l2, b1 + l * FF); // FFN1
        gemm_kernel<1024, 0, 3><<<dim3(32, 4), 256>>>(hh, hl, w2h2, w2l2, b2 + l * DD); // FFN2
        ln_kernel<<<BS / 8, 256>>>(ln2_g + l * DD, ln2_b + l * DD,
                                   (l == LL - 1) ? (float*)d_out : nullptr);
    }
}

// round 14
// speedup vs baseline: 4.7352x; 1.1201x over previous
#include <cuda_runtime.h>
#include <cuda_bf16.h>
#include <math.h>

// Problem constants
#define BB 2
#define SS 2048
#define DD 256
#define HH 8
#define FF 1024
#define DK 32
#define LL 3
#define BS (BB*SS)            // 4096 rows
#define BHS (BB*HH*SS)        // 32768 query slots
#define NEG_MAX (-3.402823466e38f)
#define SCALE 0.17677669529663687f   // 1/sqrt(32)
#define NCHUNK 2
#define CHUNK (SS/NCHUNK)     // 1024 keys per split-KV chunk

typedef unsigned int uint32;

// ---------------- device scratch (static: no allocations allowed) ----------------
__device__ float g_x  [BS*DD];           // residual stream fp32
__device__ float g_t  [BS*DD];           // pre-LN temp fp32
__device__ __nv_bfloat16 g_xh[BS*DD], g_xl[BS*DD];      // x hi/lo
__device__ __nv_bfloat16 g_oh[BS*DD], g_ol[BS*DD];      // attn out hi/lo
__device__ __nv_bfloat16 g_hidh[BS*FF], g_hidl[BS*FF];  // FFN hidden hi/lo
__device__ unsigned int g_mpk[BB*SS*SS/32];             // packed mask bits
__device__ __nv_bfloat16 g_qh[BS*DD];    // Q bf16 [bh][s][dk]
__device__ __nv_bfloat16 g_kh[BS*DD];    // K bf16 [bh][s][dk]
__device__ __nv_bfloat16 g_vh[BS*DD];    // V bf16 transposed [bh][dk][s]
// split-KV partials
__device__ float g_pm[NCHUNK*BHS], g_pl[NCHUNK*BHS];
__device__ float g_pacc[(size_t)NCHUNK*BHS*DK];
// split/transposed weights: layout [n][k], hi/lo
__device__ __nv_bfloat16 Wqkv_h[LL*768*DD], Wqkv_l[LL*768*DD];
__device__ __nv_bfloat16 Wo_h [LL*DD*DD],  Wo_l [LL*DD*DD];
__device__ __nv_bfloat16 W1_h [LL*FF*DD],  W1_l [LL*FF*DD];
__device__ __nv_bfloat16 W2_h [LL*DD*FF],  W2_l [LL*DD*FF];

// ---------------- helpers ----------------
__device__ __forceinline__ void mma_bf16(float* c, const uint32* a, const uint32* b) {
    asm volatile(
        "mma.sync.aligned.m16n8k16.row.col.f32.bf16.bf16.f32 "
        "{%0,%1,%2,%3}, {%4,%5,%6,%7}, {%8,%9}, {%0,%1,%2,%3};\n"
        : "+f"(c[0]), "+f"(c[1]), "+f"(c[2]), "+f"(c[3])
        : "r"(a[0]), "r"(a[1]), "r"(a[2]), "r"(a[3]), "r"(b[0]), "r"(b[1]));
}
__device__ __forceinline__ uint32 pack_bf16(float lo, float hi) {
    uint32 d;
    asm("cvt.rn.bf16x2.f32 %0, %1, %2;" : "=r"(d) : "f"(hi), "f"(lo));
    return d;
}
__device__ __forceinline__ void split2(float v0, float v1, uint32& hw, uint32& lw) {
    float h0 = __bfloat162float(__float2bfloat16(v0));
    float h1 = __bfloat162float(__float2bfloat16(v1));
    hw = pack_bf16(v0, v1);
    lw = pack_bf16(v0 - h0, v1 - h1);
}
__device__ __forceinline__ void cp16(uint32 saddr, const void* gptr) {
    asm volatile("cp.async.cg.shared.global [%0], [%1], 16;\n" :: "r"(saddr), "l"(gptr));
}
__device__ __forceinline__ void cp4(uint32 saddr, const void* gptr) {
    asm volatile("cp.async.ca.shared.global [%0], [%1], 4;\n" :: "r"(saddr), "l"(gptr));
}
#define CP_COMMIT()  asm volatile("cp.async.commit_group;\n" ::: "memory")
#define CP_WAIT(n)   asm volatile("cp.async.wait_group %0;\n" :: "n"(n) : "memory")

// ---------------- mask / pe / weight prep ----------------
__global__ void maskpack_kernel(const int* __restrict__ mask) {
    int w = blockIdx.x * 256 + threadIdx.x;
    const int4* p = (const int4*)(mask) + w * 8;
    unsigned int bits = 0;
#pragma unroll
    for (int j = 0; j < 8; j++) {
        int4 v = p[j];
        bits |= (v.x != 0 ? 1u : 0u) << (j * 4 + 0);
        bits |= (v.y != 0 ? 1u : 0u) << (j * 4 + 1);
        bits |= (v.z != 0 ? 1u : 0u) << (j * 4 + 2);
        bits |= (v.w != 0 ? 1u : 0u) << (j * 4 + 3);
    }
    g_mpk[w] = bits;
}

__global__ void addpe_kernel(const float* __restrict__ x, const float* __restrict__ pe) {
    int i = blockIdx.x * 256 + threadIdx.x;
    float v = x[i] + pe[i & (SS*DD - 1)];
    g_x[i] = v;
    __nv_bfloat16 h = __float2bfloat16(v);
    g_xh[i] = h;
    g_xl[i] = __float2bfloat16(v - __bfloat162float(h));
}

// generic weight transpose+split: Wt[l][n][k] from W[l][k][n]
__global__ void wtsplit_kernel(const float* __restrict__ W,
                               __nv_bfloat16* __restrict__ Th,
                               __nv_bfloat16* __restrict__ Tl, int K, int N) {
    int idx = blockIdx.x * 256 + threadIdx.x;
    int per = K * N;
    int l = idx / per, r = idx - l * per;
    int n = r / K, k = r - n * K;
    float v = W[(size_t)l * per + (size_t)k * N + n];
    __nv_bfloat16 h = __float2bfloat16(v);
    Th[idx] = h;
    Tl[idx] = __float2bfloat16(v - __bfloat162float(h));
}

// qkv weights: combined rows n = type*256 + h*32 + kk, k = d (hi + lo)
__global__ void wqkvsplit_kernel(const float* __restrict__ Wq,
                                 const float* __restrict__ Wk,
                                 const float* __restrict__ Wv) {
    int idx = blockIdx.x * 256 + threadIdx.x;
    int per = 768 * 256;
    int l = idx / per, r = idx - l * per;
    int n = r >> 8, k = r & 255;
    int type = n >> 8, nl = n & 255;
    int h = nl >> 5, kk = nl & 31;
    const float* W = (type == 0) ? Wq : ((type == 1) ? Wk : Wv);
    float v = W[(size_t)l * HH * DD * DK + h * DD * DK + k * DK + kk];
    __nv_bfloat16 hh = __float2bfloat16(v);
    Wqkv_h[idx] = hh;
    Wqkv_l[idx] = __float2bfloat16(v - __bfloat162float(hh));
}

// ---------------- tensor-core split-bf16 GEMM, cp.async 2-stage pipeline ----------------
// C[M=4096, N] = A[M,KD] * B^T (B stored [n][k] hi/lo). Tile 128x64, 256 thr, 3-mma hi/lo.
// EPI 0: g_t = acc + bias; EPI 1: g_hid hi/lo = relu(acc+bias);
// EPI 2: QKV scatter (type = blockIdx.y>>2: 0=Q,1=K,2=V)
#define KSTR 20   // u32 per smem row (32 bf16 + 16B pad)
#define ASZ (128*KSTR)
#define BSZ (64*KSTR)
#define SBUF (2*ASZ + 2*BSZ)          // u32 per pipeline buffer (30 KB)
#define GEMM_SMEM (2*SBUF*4)          // 60 KB dynamic smem
template<int KD, int EPI>
__global__ void __launch_bounds__(256) gemm_kernel(
    const __nv_bfloat16* __restrict__ Ah, const __nv_bfloat16* __restrict__ Al,
    const __nv_bfloat16* __restrict__ Bh, const __nv_bfloat16* __restrict__ Bl,
    const float* __restrict__ bias)
{
    extern __shared__ uint32 smem[];
    int t = threadIdx.x, lane = t & 31, w = t >> 5;
    int m0 = blockIdx.x * 128;
    int g = lane >> 2, q4 = lane & 3;
    int mw = w * 16;

    float c[8][4];
#pragma unroll
    for (int nb = 0; nb < 8; nb++) { c[nb][0] = c[nb][1] = c[nb][2] = c[nb][3] = 0.f; }

    // staging coordinates
    int arow = t >> 1, ac4 = (t & 1) * 2;      // A: 2x16B per thread (per part)
    int brow = t >> 2, bc4 = t & 3;            // B: 1x16B per thread (per part)
    const uint4* gAh = (const uint4*)(Ah + (size_t)(m0 + arow) * KD);
    const uint4* gAl = (const uint4*)(Al + (size_t)(m0 + arow) * KD);
    const uint4* gBh = (const uint4*)(Bh + (size_t)((size_t)blockIdx.y * 64 + brow) * KD);
    const uint4* gBl = (const uint4*)(Bl + (size_t)((size_t)blockIdx.y * 64 + brow) * KD);
    uint32 base = (uint32)__cvta_generic_to_shared(smem);
    uint32 sA  = base + (arow * KSTR + ac4 * 4) * 4;
    uint32 sAl = sA + ASZ * 4;
    uint32 sB  = base + (2 * ASZ + brow * KSTR + bc4 * 4) * 4;
    uint32 sBl = sB + BSZ * 4;

    const int NCH = KD / 32;

    // prologue: chunk 0 -> buf 0
    {
        cp16(sA,       gAh + ac4);     cp16(sA + 16,  gAh + ac4 + 1);
        cp16(sAl,      gAl + ac4);     cp16(sAl + 16, gAl + ac4 + 1);
        cp16(sB,       gBh + bc4);
        cp16(sBl,      gBl + bc4);
        CP_COMMIT();
    }

    for (int i = 0; i < NCH; i++) {
        int buf = i & 1;
        __syncthreads();                       // all done computing from buf^1
        if (i + 1 < NCH) {
            uint32 off = (uint32)((buf ^ 1) * SBUF * 4);
            int k8 = (i + 1) * 4;              // k0/8 in uint4 units
            cp16(sA + off,       gAh + k8 + ac4);
            cp16(sA + off + 16,  gAh + k8 + ac4 + 1);
            cp16(sAl + off,      gAl + k8 + ac4);
            cp16(sAl + off + 16, gAl + k8 + ac4 + 1);
            cp16(sB + off,       gBh + k8 + bc4);
            cp16(sBl + off,      gBl + k8 + bc4);
            CP_COMMIT();
            CP_WAIT(1);                        // chunk i landed; i+1 in flight
        } else {
            CP_WAIT(0);
        }
        __syncthreads();                       // chunk i visible

        const uint32* As  = smem + buf * SBUF;
        const uint32* Asl = As + ASZ;
        const uint32* Bs  = smem + buf * SBUF + 2 * ASZ;
        const uint32* Bsl = Bs + BSZ;
#pragma unroll
        for (int kh = 0; kh < 2; kh++) {
            uint32 ah[4], al[4];
            int ab = (mw + g) * KSTR + kh * 8 + q4;
            ah[0] = As[ab];         ah[1] = As[ab + 8 * KSTR];
            ah[2] = As[ab + 4];     ah[3] = As[ab + 8 * KSTR + 4];
            al[0] = Asl[ab];        al[1] = Asl[ab + 8 * KSTR];
            al[2] = Asl[ab + 4];    al[3] = Asl[ab + 8 * KSTR + 4];
#pragma unroll
            for (int nb = 0; nb < 8; nb++) {
                int bb = (nb * 8 + g) * KSTR + kh * 8 + q4;
                uint32 bh2[2] = { Bs[bb], Bs[bb + 4] };
                uint32 bl2[2] = { Bsl[bb], Bsl[bb + 4] };
                mma_bf16(c[nb], ah, bh2);
                mma_bf16(c[nb], al, bh2);
                mma_bf16(c[nb], ah, bl2);
            }
        }
    }

    int r0 = m0 + mw + g;
    if (EPI == 0) {
#pragma unroll
        for (int nb = 0; nb < 8; nb++) {
            int col = blockIdx.y * 64 + nb * 8 + 2 * q4;
            float b0 = bias[col], b1 = bias[col + 1];
            *(float2*)&g_t[(size_t)r0 * DD + col] =
                make_float2(c[nb][0] + b0, c[nb][1] + b1);
            *(float2*)&g_t[(size_t)(r0 + 8) * DD + col] =
                make_float2(c[nb][2] + b0, c[nb][3] + b1);
        }
    } else if (EPI == 1) {
#pragma unroll
        for (int nb = 0; nb < 8; nb++) {
            int col = blockIdx.y * 64 + nb * 8 + 2 * q4;
            float b0 = bias[col], b1 = bias[col + 1];
            float v0 = fmaxf(c[nb][0] + b0, 0.f), v1 = fmaxf(c[nb][1] + b1, 0.f);
            float v2 = fmaxf(c[nb][2] + b0, 0.f), v3 = fmaxf(c[nb][3] + b1, 0.f);
            uint32 hw, lw;
            split2(v0, v1, hw, lw);
            ((uint32*)g_hidh)[((size_t)r0 * FF + col) >> 1] = hw;
            ((uint32*)g_hidl)[((size_t)r0 * FF + col) >> 1] = lw;
            split2(v2, v3, hw, lw);
            ((uint32*)g_hidh)[((size_t)(r0 + 8) * FF + col) >> 1] = hw;
            ((uint32*)g_hidl)[((size_t)(r0 + 8) * FF + col) >> 1] = lw;
        }
    } else {
        // QKV scatter: blockIdx.y 0..11, type 0=Q,1=K,2=V
        int type = blockIdx.y >> 2;
        int nbase = (blockIdx.y & 3) * 64;
        int b = r0 >> 11, s0 = r0 & 2047;
#pragma unroll
        for (int nb = 0; nb < 8; nb++) {
            int nl = nbase + nb * 8 + 2 * q4;
            int h = nl >> 5, kk = nl & 31;
            if (type == 2) {
                size_t vb = ((size_t)(b * HH + h) * DK + kk) * SS;
                g_vh[vb + s0]             = __float2bfloat16(c[nb][0]);
                g_vh[vb + SS + s0]        = __float2bfloat16(c[nb][1]);
                g_vh[vb + s0 + 8]         = __float2bfloat16(c[nb][2]);
                g_vh[vb + SS + s0 + 8]    = __float2bfloat16(c[nb][3]);
            } else {
                __nv_bfloat16* dst = (type == 0) ? g_qh : g_kh;
                size_t i0 = (((size_t)(b * HH + h) * SS + s0) * DK + kk) >> 1;
                ((uint32*)dst)[i0]       = pack_bf16(c[nb][0], c[nb][1]);
                ((uint32*)dst)[i0 + 128] = pack_bf16(c[nb][2], c[nb][3]);
            }
        }
    }
}

// ------------- tensor-core flash attention, split-KV x2, cp.async 2-stage -------------
#define KSTRIDE 20
#define VSTRIDE 36
__global__ void __launch_bounds__(128) attn_mma_kernel() {
    __shared__ uint32 Ks[2][64 * KSTRIDE];
    __shared__ uint32 Vt[2][32 * VSTRIDE];
    __shared__ uint32 Msk[2][128];

    int t = threadIdx.x;
    int lane = t & 31, w = t >> 5;
    int cid = blockIdx.x & (NCHUNK - 1);
    int qb = blockIdx.x >> 1;             // NCHUNK==2
    int bh = qb >> 5;
    int qt = qb & 31;
    int b = bh >> 3;
    int m0 = w * 16;
    int g = lane >> 2, q4 = lane & 3;

    int sq_lo = qt * 64 + m0 + g;
    const uint32* qrow_lo = (const uint32*)(g_qh + ((size_t)bh * SS + sq_lo) * DK);
    const uint32* qrow_hi = qrow_lo + 8 * (DK / 2);
    uint32 aq[2][4];
#pragma unroll
    for (int kk = 0; kk < 2; kk++) {
        int base = kk * 8 + q4;
        aq[kk][0] = qrow_lo[base];     aq[kk][1] = qrow_hi[base];
        aq[kk][2] = qrow_lo[base + 4]; aq[kk][3] = qrow_hi[base + 4];
    }

    float mr_lo = -INFINITY, mr_hi = -INFINITY, l_lo = 0.f, l_hi = 0.f;
    float o[4][4];
#pragma unroll
    for (int jn = 0; jn < 4; jn++)
#pragma unroll
        for (int e = 0; e < 4; e++) o[jn][e] = 0.f;

    const float4* ksrc = (const float4*)(g_kh + (size_t)bh * SS * DK);
    const unsigned int* mbase = g_mpk + (size_t)(b * SS + qt * 64) * (SS / 32);

    // staging coordinates (fixed per thread)
    int krow = t >> 2, kc4 = t & 3;       // K: thread covers rows krow, krow+32
    int vrow_s = t >> 3, vc4 = t & 7;     // V: rows vrow_s, vrow_s+16
    uint32 ks0 = (uint32)__cvta_generic_to_shared(&Ks[0][krow * KSTRIDE + kc4 * 4]);
    uint32 ks1 = (uint32)__cvta_generic_to_shared(&Ks[0][(krow + 32) * KSTRIDE + kc4 * 4]);
    uint32 vs0 = (uint32)__cvta_generic_to_shared(&Vt[0][vrow_s * VSTRIDE + vc4 * 4]);
    uint32 vs1 = (uint32)__cvta_generic_to_shared(&Vt[0][(vrow_s + 16) * VSTRIDE + vc4 * 4]);
    uint32 ms0 = (uint32)__cvta_generic_to_shared(&Msk[0][t]);
    const uint32 kbufsz = (uint32)(64 * KSTRIDE * 4);
    const uint32 vbufsz = (uint32)(32 * VSTRIDE * 4);

    int kstart = cid * CHUNK;
    const int NT = CHUNK / 64;

    // prologue: issue tile 0 into buf 0
    {
        int k0 = kstart;
        cp16(ks0, ksrc + k0 * 4 + t);
        cp16(ks1, ksrc + k0 * 4 + t + 128);
        cp16(vs0, (const float4*)(g_vh + ((size_t)bh * DK + vrow_s) * SS + k0) + vc4);
        cp16(vs1, (const float4*)(g_vh + ((size_t)bh * DK + vrow_s + 16) * SS + k0) + vc4);
        cp4(ms0, mbase + (size_t)(t >> 1) * (SS / 32) + (k0 >> 5) + (t & 1));
        CP_COMMIT();
    }

    for (int i = 0; i < NT; i++) {
        int buf = i & 1;
        __syncthreads();                        // everyone done computing from buf^1
        if (i + 1 < NT) {
            int k0 = kstart + (i + 1) * 64;
            uint32 off = (buf ^ 1) ? 1u : 0u;
            cp16(ks0 + off * kbufsz, ksrc + k0 * 4 + t);
            cp16(ks1 + off * kbufsz, ksrc + k0 * 4 + t + 128);
            cp16(vs0 + off * vbufsz, (const float4*)(g_vh + ((size_t)bh * DK + vrow_s) * SS + k0) + vc4);
            cp16(vs1 + off * vbufsz, (const float4*)(g_vh + ((size_t)bh * DK + vrow_s + 16) * SS + k0) + vc4);
            cp4(ms0 + off * 512u, mbase + (size_t)(t >> 1) * (SS / 32) + (k0 >> 5) + (t & 1));
            CP_COMMIT();
            CP_WAIT(1);                          // tile i complete; tile i+1 in flight
        } else {
            CP_WAIT(0);
        }
        __syncthreads();                        // tile i visible to all threads

        // ---- compute tile i from buf ----
        float c[8][4];
#pragma unroll
        for (int j = 0; j < 8; j++) { c[j][0] = c[j][1] = c[j][2] = c[j][3] = 0.f; }
#pragma unroll
        for (int j = 0; j < 8; j++) {
            int kr = (8 * j + g) * KSTRIDE;
            uint32 bfr[2];
            bfr[0] = Ks[buf][kr + q4];     bfr[1] = Ks[buf][kr + q4 + 4];
            mma_bf16(c[j], aq[0], bfr);
            bfr[0] = Ks[buf][kr + 8 + q4]; bfr[1] = Ks[buf][kr + 8 + q4 + 4];
            mma_bf16(c[j], aq[1], bfr);
        }
        uint32 ml0 = Msk[buf][(m0 + g) * 2],     ml1 = Msk[buf][(m0 + g) * 2 + 1];
        uint32 mh0 = Msk[buf][(m0 + g + 8) * 2], mh1 = Msk[buf][(m0 + g + 8) * 2 + 1];
#pragma unroll
        for (int j = 0; j < 8; j++) {
#pragma unroll
            for (int e = 0; e < 2; e++) {
                int bit = 8 * j + 2 * q4 + e;
                uint32 wl = (bit < 32) ? ml0 : ml1;
                uint32 wh = (bit < 32) ? mh0 : mh1;
                int bp = bit & 31;
                c[j][e]     = ((wl >> bp) & 1u) ? NEG_MAX : c[j][e] * SCALE;
                c[j][2 + e] = ((wh >> bp) & 1u) ? NEG_MAX : c[j][2 + e] * SCALE;
            }
        }
        float mx_lo = c[0][0], mx_hi = c[0][2];
#pragma unroll
        for (int j = 0; j < 8; j++) {
            mx_lo = fmaxf(mx_lo, fmaxf(c[j][0], c[j][1]));
            mx_hi = fmaxf(mx_hi, fmaxf(c[j][2], c[j][3]));
        }
        mx_lo = fmaxf(mx_lo, __shfl_xor_sync(0xffffffffu, mx_lo, 1));
        mx_lo = fmaxf(mx_lo, __shfl_xor_sync(0xffffffffu, mx_lo, 2));
        mx_hi = fmaxf(mx_hi, __shfl_xor_sync(0xffffffffu, mx_hi, 1));
        mx_hi = fmaxf(mx_hi, __shfl_xor_sync(0xffffffffu, mx_hi, 2));
        float mn_lo = fmaxf(mr_lo, mx_lo), mn_hi = fmaxf(mr_hi, mx_hi);
        float corr_lo = __expf(mr_lo - mn_lo), corr_hi = __expf(mr_hi - mn_hi);
        mr_lo = mn_lo; mr_hi = mn_hi;

        float sum_lo = 0.f, sum_hi = 0.f;
#pragma unroll
        for (int j = 0; j < 8; j++) {
            c[j][0] = __expf(c[j][0] - mn_lo); sum_lo += c[j][0];
            c[j][1] = __expf(c[j][1] - mn_lo); sum_lo += c[j][1];
            c[j][2] = __expf(c[j][2] - mn_hi); sum_hi += c[j][2];
            c[j][3] = __expf(c[j][3] - mn_hi); sum_hi += c[j][3];
        }
        sum_lo += __shfl_xor_sync(0xffffffffu, sum_lo, 1);
        sum_lo += __shfl_xor_sync(0xffffffffu, sum_lo, 2);
        sum_hi += __shfl_xor_sync(0xffffffffu, sum_hi, 1);
        sum_hi += __shfl_xor_sync(0xffffffffu, sum_hi, 2);
        l_lo = l_lo * corr_lo + sum_lo;
        l_hi = l_hi * corr_hi + sum_hi;
#pragma unroll
        for (int jn = 0; jn < 4; jn++) {
            o[jn][0] *= corr_lo; o[jn][1] *= corr_lo;
            o[jn][2] *= corr_hi; o[jn][3] *= corr_hi;
        }
        uint32 pf[4][4];
#pragma unroll
        for (int jj = 0; jj < 4; jj++) {
            pf[jj][0] = pack_bf16(c[2 * jj][0],     c[2 * jj][1]);
            pf[jj][1] = pack_bf16(c[2 * jj][2],     c[2 * jj][3]);
            pf[jj][2] = pack_bf16(c[2 * jj + 1][0], c[2 * jj + 1][1]);
            pf[jj][3] = pack_bf16(c[2 * jj + 1][2], c[2 * jj + 1][3]);
        }
#pragma unroll
        for (int jn = 0; jn < 4; jn++) {
            int vr = (8 * jn + g) * VSTRIDE;
#pragma unroll
            for (int jj = 0; jj < 4; jj++) {
                uint32 bfr[2];
                bfr[0] = Vt[buf][vr + 8 * jj + q4];
                bfr[1] = Vt[buf][vr + 8 * jj + q4 + 4];
                mma_bf16(o[jn], pf[jj], bfr);
            }
        }
    }
    // store unnormalized partials
    int qidx = bh * SS + sq_lo;       // rows qidx, qidx+8
    float* pp = g_pacc + ((size_t)cid * BHS + qidx) * DK;
#pragma unroll
    for (int jn = 0; jn < 4; jn++) {
        int col = 8 * jn + 2 * q4;
        *(float2*)&pp[col]          = make_float2(o[jn][0], o[jn][1]);
        *(float2*)&pp[8 * DK + col] = make_float2(o[jn][2], o[jn][3]);
    }
    if (q4 == 0) {
        g_pm[cid * BHS + qidx] = mr_lo;     g_pl[cid * BHS + qidx] = l_lo;
        g_pm[cid * BHS + qidx + 8] = mr_hi; g_pl[cid * BHS + qidx + 8] = l_hi;
    }
}

// merge 2 partials, normalize, write hi/lo attn output (head-concat layout)
__global__ void __launch_bounds__(256) attn_combine_kernel() {
    int q = blockIdx.x * 256 + threadIdx.x;   // 0..BHS-1
    float m0 = g_pm[q], m1 = g_pm[BHS + q];
    float gm = fmaxf(m0, m1);
    float w0 = __expf(m0 - gm), w1 = __expf(m1 - gm);
    float L = g_pl[q] * w0 + g_pl[BHS + q] * w1;
    float inv = 1.f / L;
    w0 *= inv; w1 *= inv;
    const float4* p0 = (const float4*)(g_pacc + (size_t)q * DK);
    const float4* p1 = (const float4*)(g_pacc + ((size_t)BHS + q) * DK);
    int bh = q >> 11, sq = q & 2047;
    int b = bh >> 3, h = bh & 7;
    size_t obase = ((size_t)b * SS + sq) * DD + h * DK;
    uint32* doh = (uint32*)g_oh + (obase >> 1);
    uint32* dol = (uint32*)g_ol + (obase >> 1);
#pragma unroll
    for (int i = 0; i < 8; i++) {
        float4 a = p0[i], bb = p1[i];
        float r0 = a.x * w0 + bb.x * w1, r1 = a.y * w0 + bb.y * w1;
        float r2 = a.z * w0 + bb.z * w1, r3 = a.w * w0 + bb.w * w1;
        uint32 hw, lw;
        split2(r0, r1, hw, lw);
        doh[i * 2] = hw; dol[i * 2] = lw;
        split2(r2, r3, hw, lw);
        doh[i * 2 + 1] = hw; dol[i * 2 + 1] = lw;
    }
}

// residual + layernorm: warp per row, 8 rows/block, shfl-only reductions.
// outp == nullptr: write g_x + hi/lo. outp != nullptr (last layer): write outp only.
__global__ void __launch_bounds__(256) ln_kernel(const float* __restrict__ gam,
                                                 const float* __restrict__ bet,
                                                 float* __restrict__ outp) {
    int lane = threadIdx.x & 31, wrp = threadIdx.x >> 5;
    int row = blockIdx.x * 8 + wrp;
    const float4* t4 = (const float4*)(g_t + (size_t)row * DD) + lane * 2;
    const float4* x4 = (const float4*)(g_x + (size_t)row * DD) + lane * 2;
    float4 a0 = t4[0], a1 = t4[1], b0 = x4[0], b1 = x4[1];
    float v[8] = { a0.x + b0.x, a0.y + b0.y, a0.z + b0.z, a0.w + b0.w,
                   a1.x + b1.x, a1.y + b1.y, a1.z + b1.z, a1.w + b1.w };
    float s = 0.f;
#pragma unroll
    for (int i = 0; i < 8; i++) s += v[i];
#pragma unroll
    for (int o = 16; o; o >>= 1) s += __shfl_xor_sync(0xffffffffu, s, o);
    float mu = s * (1.f / DD);
    float s2 = 0.f;
#pragma unroll
    for (int i = 0; i < 8; i++) { float d = v[i] - mu; s2 += d * d; }
#pragma unroll
    for (int o = 16; o; o >>= 1) s2 += __shfl_xor_sync(0xffffffffu, s2, o);
    float rstd = rsqrtf(s2 * (1.f / DD) + 1e-7f);

    const float4* g4 = (const float4*)gam + lane * 2;
    const float4* be4 = (const float4*)bet + lane * 2;
    float4 gg0 = g4[0], gg1 = g4[1], bb0 = be4[0], bb1 = be4[1];
    float out[8];
    out[0] = (v[0] - mu) * rstd * gg0.x + bb0.x;
    out[1] = (v[1] - mu) * rstd * gg0.y + bb0.y;
    out[2] = (v[2] - mu) * rstd * gg0.z + bb0.z;
    out[3] = (v[3] - mu) * rstd * gg0.w + bb0.w;
    out[4] = (v[4] - mu) * rstd * gg1.x + bb1.x;
    out[5] = (v[5] - mu) * rstd * gg1.y + bb1.y;
    out[6] = (v[6] - mu) * rstd * gg1.z + bb1.z;
    out[7] = (v[7] - mu) * rstd * gg1.w + bb1.w;

    if (outp) {
        float4* oo = (float4*)(outp + (size_t)row * DD) + lane * 2;
        oo[0] = make_float4(out[0], out[1], out[2], out[3]);
        oo[1] = make_float4(out[4], out[5], out[6], out[7]);
    } else {
        float4* xo = (float4*)(g_x + (size_t)row * DD) + lane * 2;
        xo[0] = make_float4(out[0], out[1], out[2], out[3]);
        xo[1] = make_float4(out[4], out[5], out[6], out[7]);
        uint32 hw[4], lw[4];
#pragma unroll
        for (int i = 0; i < 4; i++) split2(out[2 * i], out[2 * i + 1], hw[i], lw[i]);
        size_t wi = ((size_t)row * DD) / 2 + lane * 4;
        *(uint4*)((uint32*)g_xh + wi) = *(uint4*)hw;
        *(uint4*)((uint32*)g_xl + wi) = *(uint4*)lw;
    }
}

// ---------------- launch ----------------
extern "C" void kernel_launch(void* const* d_in, const int* in_sizes, int n_in,
                              void* d_out, int out_size) {
    const float* x  = (const float*)d_in[0];
    const int*   mask = (const int*)d_in[1];     // jnp bool promoted to int32
    const float* pe = (const float*)d_in[2];
    const float* Wq = (const float*)d_in[3];
    const float* Wk = (const float*)d_in[4];
    const float* Wv = (const float*)d_in[5];
    const float* Wo = (const float*)d_in[6];
    const float* bo = (const float*)d_in[7];
    const float* ln1_g = (const float*)d_in[8];
    const float* ln1_b = (const float*)d_in[9];
    const float* W1 = (const float*)d_in[10];
    const float* b1 = (const float*)d_in[11];
    const float* W2 = (const float*)d_in[12];
    const float* b2 = (const float*)d_in[13];
    const float* ln2_g = (const float*)d_in[14];
    const float* ln2_b = (const float*)d_in[15];

    void *p_xh, *p_xl, *p_oh, *p_ol, *p_hh, *p_hl;
    void *p_wqkvh, *p_wqkvl, *p_woh, *p_wol, *p_w1h, *p_w1l, *p_w2h, *p_w2l;
    cudaGetSymbolAddress(&p_xh, g_xh);   cudaGetSymbolAddress(&p_xl, g_xl);
    cudaGetSymbolAddress(&p_oh, g_oh);   cudaGetSymbolAddress(&p_ol, g_ol);
    cudaGetSymbolAddress(&p_hh, g_hidh); cudaGetSymbolAddress(&p_hl, g_hidl);
    cudaGetSymbolAddress(&p_wqkvh, Wqkv_h); cudaGetSymbolAddress(&p_wqkvl, Wqkv_l);
    cudaGetSymbolAddress(&p_woh, Wo_h);  cudaGetSymbolAddress(&p_wol, Wo_l);
    cudaGetSymbolAddress(&p_w1h, W1_h);  cudaGetSymbolAddress(&p_w1l, W1_l);
    cudaGetSymbolAddress(&p_w2h, W2_h);  cudaGetSymbolAddress(&p_w2l, W2_l);
    const __nv_bfloat16 *xh = (const __nv_bfloat16*)p_xh, *xl = (const __nv_bfloat16*)p_xl;
    const __nv_bfloat16 *oh = (const __nv_bfloat16*)p_oh, *ol = (const __nv_bfloat16*)p_ol;
    const __nv_bfloat16 *hh = (const __nv_bfloat16*)p_hh, *hl = (const __nv_bfloat16*)p_hl;

    // dynamic-smem opt-in for all gemm instantiations (host-side, capture-safe)
    cudaFuncSetAttribute(gemm_kernel<256, 0>,  cudaFuncAttributeMaxDynamicSharedMemorySize, GEMM_SMEM);
    cudaFuncSetAttribute(gemm_kernel<256, 1>,  cudaFuncAttributeMaxDynamicSharedMemorySize, GEMM_SMEM);
    cudaFuncSetAttribute(gemm_kernel<256, 2>,  cudaFuncAttributeMaxDynamicSharedMemorySize, GEMM_SMEM);
    cudaFuncSetAttribute(gemm_kernel<1024, 0>, cudaFuncAttributeMaxDynamicSharedMemorySize, GEMM_SMEM);

    // weight prep (idempotent)
    wqkvsplit_kernel<<<LL * 768 * 256 / 256, 256>>>(Wq, Wk, Wv);
    wtsplit_kernel<<<LL * DD * DD / 256, 256>>>(Wo, (__nv_bfloat16*)p_woh, (__nv_bfloat16*)p_wol, DD, DD);
    wtsplit_kernel<<<LL * DD * FF / 256, 256>>>(W1, (__nv_bfloat16*)p_w1h, (__nv_bfloat16*)p_w1l, DD, FF);
    wtsplit_kernel<<<LL * FF * DD / 256, 256>>>(W2, (__nv_bfloat16*)p_w2h, (__nv_bfloat16*)p_w2l, FF, DD);
    maskpack_kernel<<<(BB*SS*SS/32) / 256, 256>>>(mask);
    addpe_kernel<<<BS * DD / 256, 256>>>(x, pe);

    for (int l = 0; l < LL; l++) {
        const __nv_bfloat16* wqh = (const __nv_bfloat16*)p_wqkvh + (size_t)l * 768 * DD;
        const __nv_bfloat16* wql = (const __nv_bfloat16*)p_wqkvl + (size_t)l * 768 * DD;
        const __nv_bfloat16* woh2 = (const __nv_bfloat16*)p_woh + (size_t)l * DD * DD;
        const __nv_bfloat16* wol2 = (const __nv_bfloat16*)p_wol + (size_t)l * DD * DD;
        const __nv_bfloat16* w1h2 = (const __nv_bfloat16*)p_w1h + (size_t)l * FF * DD;
        const __nv_bfloat16* w1l2 = (const __nv_bfloat16*)p_w1l + (size_t)l * FF * DD;
        const __nv_bfloat16* w2h2 = (const __nv_bfloat16*)p_w2h + (size_t)l * DD * FF;
        const __nv_bfloat16* w2l2 = (const __nv_bfloat16*)p_w2l + (size_t)l * DD * FF;

        gemm_kernel<256, 2><<<dim3(32, 12), 256, GEMM_SMEM>>>(xh, xl, wqh, wql, nullptr);       // QKV
        attn_mma_kernel<<<BB * HH * (SS / 64) * NCHUNK, 128>>>();
        attn_combine_kernel<<<BHS / 256, 256>>>();
        gemm_kernel<256, 0><<<dim3(32, 4), 256, GEMM_SMEM>>>(oh, ol, woh2, wol2, bo + l * DD);  // Wo
        ln_kernel<<<BS / 8, 256>>>(ln1_g + l * DD, ln1_b + l * DD, nullptr);
        gemm_kernel<256, 1><<<dim3(32, 16), 256, GEMM_SMEM>>>(xh, xl, w1h2, w1l2, b1 + l * FF); // FFN1
        gemm_kernel<1024, 0><<<dim3(32, 4), 256, GEMM_SMEM>>>(hh, hl, w2h2, w2l2, b2 + l * DD); // FFN2
        ln_kernel<<<BS / 8, 256>>>(ln2_g + l * DD, ln2_b + l * DD,
                                   (l == LL - 1) ? (float*)d_out : nullptr);
    }
}

// round 15
// speedup vs baseline: 5.1088x; 1.0789x over previous
#include <cuda_runtime.h>
#include <cuda_bf16.h>
#include <math.h>

// Problem constants
#define BB 2
#define SS 2048
#define DD 256
#define HH 8
#define FF 1024
#define DK 32
#define LL 3
#define BS (BB*SS)            // 4096 rows
#define BHS (BB*HH*SS)        // 32768 query slots
#define NEG_MAX (-3.402823466e38f)
#define SCALE 0.17677669529663687f   // 1/sqrt(32)
#define NCHUNK 4
#define CHUNK (SS/NCHUNK)     // 512 keys per split-KV chunk

typedef unsigned int uint32;

// ---------------- device scratch (static: no allocations allowed) ----------------
__device__ float g_x  [BS*DD];           // residual stream fp32
__device__ float g_t  [BS*DD];           // pre-LN temp fp32
__device__ __nv_bfloat16 g_xh[BS*DD], g_xl[BS*DD];      // x hi/lo
__device__ __nv_bfloat16 g_oh[BS*DD], g_ol[BS*DD];      // attn out hi/lo
__device__ __nv_bfloat16 g_hidh[BS*FF], g_hidl[BS*FF];  // FFN hidden hi/lo
__device__ unsigned int g_mpk[BB*SS*SS/32];             // packed mask bits
__device__ __nv_bfloat16 g_qh[BS*DD];    // Q bf16 [bh][s][dk]
__device__ __nv_bfloat16 g_kh[BS*DD];    // K bf16 [bh][s][dk]
__device__ __nv_bfloat16 g_vh[BS*DD];    // V bf16 transposed [bh][dk][s]
// split-KV partials
__device__ float g_pm[NCHUNK*BHS], g_pl[NCHUNK*BHS];
__device__ float g_pacc[(size_t)NCHUNK*BHS*DK];
// split/transposed weights: layout [n][k], hi/lo
__device__ __nv_bfloat16 Wqkv_h[LL*768*DD], Wqkv_l[LL*768*DD];
__device__ __nv_bfloat16 Wo_h [LL*DD*DD],  Wo_l [LL*DD*DD];
__device__ __nv_bfloat16 W1_h [LL*FF*DD],  W1_l [LL*FF*DD];
__device__ __nv_bfloat16 W2_h [LL*DD*FF],  W2_l [LL*DD*FF];

// ---------------- helpers ----------------
__device__ __forceinline__ void mma_bf16(float* c, const uint32* a, const uint32* b) {
    asm volatile(
        "mma.sync.aligned.m16n8k16.row.col.f32.bf16.bf16.f32 "
        "{%0,%1,%2,%3}, {%4,%5,%6,%7}, {%8,%9}, {%0,%1,%2,%3};\n"
        : "+f"(c[0]), "+f"(c[1]), "+f"(c[2]), "+f"(c[3])
        : "r"(a[0]), "r"(a[1]), "r"(a[2]), "r"(a[3]), "r"(b[0]), "r"(b[1]));
}
__device__ __forceinline__ void ldsm4(uint32* r, uint32 addr) {
    asm volatile("ldmatrix.sync.aligned.m8n8.x4.shared.b16 {%0,%1,%2,%3}, [%4];"
        : "=r"(r[0]), "=r"(r[1]), "=r"(r[2]), "=r"(r[3]) : "r"(addr));
}
__device__ __forceinline__ void ldsm2(uint32* r, uint32 addr) {
    asm volatile("ldmatrix.sync.aligned.m8n8.x2.shared.b16 {%0,%1}, [%2];"
        : "=r"(r[0]), "=r"(r[1]) : "r"(addr));
}
__device__ __forceinline__ uint32 pack_bf16(float lo, float hi) {
    uint32 d;
    asm("cvt.rn.bf16x2.f32 %0, %1, %2;" : "=r"(d) : "f"(hi), "f"(lo));
    return d;
}
__device__ __forceinline__ void split2(float v0, float v1, uint32& hw, uint32& lw) {
    float h0 = __bfloat162float(__float2bfloat16(v0));
    float h1 = __bfloat162float(__float2bfloat16(v1));
    hw = pack_bf16(v0, v1);
    lw = pack_bf16(v0 - h0, v1 - h1);
}
__device__ __forceinline__ void cp16(uint32 saddr, const void* gptr) {
    asm volatile("cp.async.cg.shared.global [%0], [%1], 16;\n" :: "r"(saddr), "l"(gptr));
}
__device__ __forceinline__ void cp4(uint32 saddr, const void* gptr) {
    asm volatile("cp.async.ca.shared.global [%0], [%1], 4;\n" :: "r"(saddr), "l"(gptr));
}
#define CP_COMMIT()  asm volatile("cp.async.commit_group;\n" ::: "memory")
#define CP_WAIT(n)   asm volatile("cp.async.wait_group %0;\n" :: "n"(n) : "memory")

// ---------------- mask / pe / weight prep ----------------
__global__ void maskpack_kernel(const int* __restrict__ mask) {
    int w = blockIdx.x * 256 + threadIdx.x;
    const int4* p = (const int4*)(mask) + w * 8;
    unsigned int bits = 0;
#pragma unroll
    for (int j = 0; j < 8; j++) {
        int4 v = p[j];
        bits |= (v.x != 0 ? 1u : 0u) << (j * 4 + 0);
        bits |= (v.y != 0 ? 1u : 0u) << (j * 4 + 1);
        bits |= (v.z != 0 ? 1u : 0u) << (j * 4 + 2);
        bits |= (v.w != 0 ? 1u : 0u) << (j * 4 + 3);
    }
    g_mpk[w] = bits;
}

__global__ void addpe_kernel(const float* __restrict__ x, const float* __restrict__ pe) {
    int i = blockIdx.x * 256 + threadIdx.x;
    float v = x[i] + pe[i & (SS*DD - 1)];
    g_x[i] = v;
    __nv_bfloat16 h = __float2bfloat16(v);
    g_xh[i] = h;
    g_xl[i] = __float2bfloat16(v - __bfloat162float(h));
}

// coalesced weight transpose+split via 32x32 smem tile: Wt[l][n][k] from W[l][k][n]
__global__ void __launch_bounds__(256) wtsplit_kernel(const float* __restrict__ W,
                               __nv_bfloat16* __restrict__ Th,
                               __nv_bfloat16* __restrict__ Tl, int K, int N) {
    __shared__ float tile[32][33];
    int l = blockIdx.z;
    int k0 = blockIdx.x * 32, n0 = blockIdx.y * 32;
    int tx = threadIdx.x & 31, ty = threadIdx.x >> 5;   // 8 rows per pass
    const float* src = W + (size_t)l * K * N;
#pragma unroll
    for (int r = 0; r < 32; r += 8)
        tile[ty + r][tx] = src[(size_t)(k0 + ty + r) * N + n0 + tx];
    __syncthreads();
    __nv_bfloat16* dh = Th + (size_t)l * K * N;
    __nv_bfloat16* dl = Tl + (size_t)l * K * N;
#pragma unroll
    for (int r = 0; r < 32; r += 8) {
        float v = tile[tx][ty + r];
        __nv_bfloat16 h = __float2bfloat16(v);
        size_t di = (size_t)(n0 + ty + r) * K + k0 + tx;
        dh[di] = h;
        dl[di] = __float2bfloat16(v - __bfloat162float(h));
    }
}

// qkv weights, coalesced: W[l][h][d][kk] -> Wqkv[l][type*256+h*32+kk][d]
__global__ void __launch_bounds__(256) wqkvsplit_kernel(const float* __restrict__ Wq,
                                 const float* __restrict__ Wk,
                                 const float* __restrict__ Wv) {
    __shared__ float tile[32][33];
    int l = blockIdx.z;
    int type = blockIdx.y >> 3, h = blockIdx.y & 7;
    int d0 = blockIdx.x * 32;
    int tx = threadIdx.x & 31, ty = threadIdx.x >> 5;
    const float* W = (type == 0) ? Wq : ((type == 1) ? Wk : Wv);
    const float* src = W + (size_t)l * HH * DD * DK + (size_t)h * DD * DK;
#pragma unroll
    for (int r = 0; r < 32; r += 8)
        tile[ty + r][tx] = src[(size_t)(d0 + ty + r) * DK + tx];   // tx = kk (coalesced)
    __syncthreads();
    int nbase = type * 256 + h * 32;
#pragma unroll
    for (int r = 0; r < 32; r += 8) {
        int kk = ty + r, d = d0 + tx;
        float v = tile[tx][kk];
        __nv_bfloat16 hh = __float2bfloat16(v);
        size_t di = ((size_t)l * 768 + nbase + kk) * DD + d;
        Wqkv_h[di] = hh;
        Wqkv_l[di] = __float2bfloat16(v - __bfloat162float(hh));
    }
}

// ---------------- tensor-core split-bf16 GEMM, cp.async 2-stage + ldmatrix ----------------
// C[M=4096, N] = A[M,KD] * B^T (B stored [n][k] hi/lo). Tile 128x64, 256 thr, 3-mma hi/lo.
// EPI 0: g_t = acc + bias; EPI 1: g_hid hi/lo = relu(acc+bias);
// EPI 2: QKV scatter (type = blockIdx.y>>2: 0=Q,1=K,2=V)
#define KSTR 20   // u32 per smem row (32 bf16 + 16B pad)
#define ASZ (128*KSTR)
#define BSZ (64*KSTR)
#define SBUF (2*ASZ + 2*BSZ)          // u32 per pipeline buffer (30 KB)
#define GEMM_SMEM (2*SBUF*4)          // 60 KB dynamic smem
template<int KD, int EPI>
__global__ void __launch_bounds__(256) gemm_kernel(
    const __nv_bfloat16* __restrict__ Ah, const __nv_bfloat16* __restrict__ Al,
    const __nv_bfloat16* __restrict__ Bh, const __nv_bfloat16* __restrict__ Bl,
    const float* __restrict__ bias)
{
    extern __shared__ uint32 smem[];
    int t = threadIdx.x, lane = t & 31, w = t >> 5;
    int m0 = blockIdx.x * 128;
    int g = lane >> 2, q4 = lane & 3;
    int mw = w * 16;

    float c[8][4];
#pragma unroll
    for (int nb = 0; nb < 8; nb++) { c[nb][0] = c[nb][1] = c[nb][2] = c[nb][3] = 0.f; }

    // staging coordinates
    int arow = t >> 1, ac4 = (t & 1) * 2;      // A: 2x16B per thread (per part)
    int brow = t >> 2, bc4 = t & 3;            // B: 1x16B per thread (per part)
    const uint4* gAh = (const uint4*)(Ah + (size_t)(m0 + arow) * KD);
    const uint4* gAl = (const uint4*)(Al + (size_t)(m0 + arow) * KD);
    const uint4* gBh = (const uint4*)(Bh + (size_t)((size_t)blockIdx.y * 64 + brow) * KD);
    const uint4* gBl = (const uint4*)(Bl + (size_t)((size_t)blockIdx.y * 64 + brow) * KD);
    uint32 base = (uint32)__cvta_generic_to_shared(smem);
    uint32 sA  = base + (arow * KSTR + ac4 * 4) * 4;
    uint32 sAl = sA + ASZ * 4;
    uint32 sB  = base + (2 * ASZ + brow * KSTR + bc4 * 4) * 4;
    uint32 sBl = sB + BSZ * 4;

    // ldmatrix lane addresses (bytes, buf 0)
    uint32 aAh0 = base + ((mw + (lane & 15)) * KSTR + ((lane & 16) ? 4 : 0)) * 4;
    uint32 aAl0 = aAh0 + ASZ * 4;
    uint32 aBh0 = base + (2 * ASZ + (lane & 7) * KSTR + ((lane & 8) ? 4 : 0)) * 4;
    uint32 aBl0 = aBh0 + BSZ * 4;

    const int NCH = KD / 32;

    // prologue: chunk 0 -> buf 0
    {
        cp16(sA,       gAh + ac4);     cp16(sA + 16,  gAh + ac4 + 1);
        cp16(sAl,      gAl + ac4);     cp16(sAl + 16, gAl + ac4 + 1);
        cp16(sB,       gBh + bc4);
        cp16(sBl,      gBl + bc4);
        CP_COMMIT();
    }

    for (int i = 0; i < NCH; i++) {
        int buf = i & 1;
        __syncthreads();                       // all done computing from buf^1
        if (i + 1 < NCH) {
            uint32 off = (uint32)((buf ^ 1) * SBUF * 4);
            int k8 = (i + 1) * 4;              // k0/8 in uint4 units
            cp16(sA + off,       gAh + k8 + ac4);
            cp16(sA + off + 16,  gAh + k8 + ac4 + 1);
            cp16(sAl + off,      gAl + k8 + ac4);
            cp16(sAl + off + 16, gAl + k8 + ac4 + 1);
            cp16(sB + off,       gBh + k8 + bc4);
            cp16(sBl + off,      gBl + k8 + bc4);
            CP_COMMIT();
            CP_WAIT(1);                        // chunk i landed; i+1 in flight
        } else {
            CP_WAIT(0);
        }
        __syncthreads();                       // chunk i visible

        uint32 bufoff = (uint32)(buf * SBUF * 4);
#pragma unroll
        for (int kh = 0; kh < 2; kh++) {
            uint32 ah[4], al[4];
            ldsm4(ah, aAh0 + bufoff + kh * 32);
            ldsm4(al, aAl0 + bufoff + kh * 32);
#pragma unroll
            for (int nb = 0; nb < 8; nb++) {
                uint32 nboff = bufoff + (uint32)(nb * 8 * KSTR * 4) + kh * 32;
                uint32 bh2[2], bl2[2];
                ldsm2(bh2, aBh0 + nboff);
                ldsm2(bl2, aBl0 + nboff);
                mma_bf16(c[nb], ah, bh2);
                mma_bf16(c[nb], al, bh2);
                mma_bf16(c[nb], ah, bl2);
            }
        }
    }

    int r0 = m0 + mw + g;
    if (EPI == 0) {
#pragma unroll
        for (int nb = 0; nb < 8; nb++) {
            int col = blockIdx.y * 64 + nb * 8 + 2 * q4;
            float b0 = bias[col], b1 = bias[col + 1];
            *(float2*)&g_t[(size_t)r0 * DD + col] =
                make_float2(c[nb][0] + b0, c[nb][1] + b1);
            *(float2*)&g_t[(size_t)(r0 + 8) * DD + col] =
                make_float2(c[nb][2] + b0, c[nb][3] + b1);
        }
    } else if (EPI == 1) {
#pragma unroll
        for (int nb = 0; nb < 8; nb++) {
            int col = blockIdx.y * 64 + nb * 8 + 2 * q4;
            float b0 = bias[col], b1 = bias[col + 1];
            float v0 = fmaxf(c[nb][0] + b0, 0.f), v1 = fmaxf(c[nb][1] + b1, 0.f);
            float v2 = fmaxf(c[nb][2] + b0, 0.f), v3 = fmaxf(c[nb][3] + b1, 0.f);
            uint32 hw, lw;
            split2(v0, v1, hw, lw);
            ((uint32*)g_hidh)[((size_t)r0 * FF + col) >> 1] = hw;
            ((uint32*)g_hidl)[((size_t)r0 * FF + col) >> 1] = lw;
            split2(v2, v3, hw, lw);
            ((uint32*)g_hidh)[((size_t)(r0 + 8) * FF + col) >> 1] = hw;
            ((uint32*)g_hidl)[((size_t)(r0 + 8) * FF + col) >> 1] = lw;
        }
    } else {
        // QKV scatter: blockIdx.y 0..11, type 0=Q,1=K,2=V
        int type = blockIdx.y >> 2;
        int nbase = (blockIdx.y & 3) * 64;
        int b = r0 >> 11, s0 = r0 & 2047;
#pragma unroll
        for (int nb = 0; nb < 8; nb++) {
            int nl = nbase + nb * 8 + 2 * q4;
            int h = nl >> 5, kk = nl & 31;
            if (type == 2) {
                size_t vb = ((size_t)(b * HH + h) * DK + kk) * SS;
                g_vh[vb + s0]             = __float2bfloat16(c[nb][0]);
                g_vh[vb + SS + s0]        = __float2bfloat16(c[nb][1]);
                g_vh[vb + s0 + 8]         = __float2bfloat16(c[nb][2]);
                g_vh[vb + SS + s0 + 8]    = __float2bfloat16(c[nb][3]);
            } else {
                __nv_bfloat16* dst = (type == 0) ? g_qh : g_kh;
                size_t i0 = (((size_t)(b * HH + h) * SS + s0) * DK + kk) >> 1;
                ((uint32*)dst)[i0]       = pack_bf16(c[nb][0], c[nb][1]);
                ((uint32*)dst)[i0 + 128] = pack_bf16(c[nb][2], c[nb][3]);
            }
        }
    }
}

// ------------- tensor-core flash attention, split-KV x4, cp.async 2-stage -------------
#define KSTRIDE 20
#define VSTRIDE 36
__global__ void __launch_bounds__(128) attn_mma_kernel() {
    __shared__ uint32 Ks[2][64 * KSTRIDE];
    __shared__ uint32 Vt[2][32 * VSTRIDE];
    __shared__ uint32 Msk[2][128];

    int t = threadIdx.x;
    int lane = t & 31, w = t >> 5;
    int cid = blockIdx.x & (NCHUNK - 1);
    int qb = blockIdx.x >> 2;             // NCHUNK==4
    int bh = qb >> 5;
    int qt = qb & 31;
    int b = bh >> 3;
    int m0 = w * 16;
    int g = lane >> 2, q4 = lane & 3;

    int sq_lo = qt * 64 + m0 + g;
    const uint32* qrow_lo = (const uint32*)(g_qh + ((size_t)bh * SS + sq_lo) * DK);
    const uint32* qrow_hi = qrow_lo + 8 * (DK / 2);
    uint32 aq[2][4];
#pragma unroll
    for (int kk = 0; kk < 2; kk++) {
        int base = kk * 8 + q4;
        aq[kk][0] = qrow_lo[base];     aq[kk][1] = qrow_hi[base];
        aq[kk][2] = qrow_lo[base + 4]; aq[kk][3] = qrow_hi[base + 4];
    }

    float mr_lo = -INFINITY, mr_hi = -INFINITY, l_lo = 0.f, l_hi = 0.f;
    float o[4][4];
#pragma unroll
    for (int jn = 0; jn < 4; jn++)
#pragma unroll
        for (int e = 0; e < 4; e++) o[jn][e] = 0.f;

    const float4* ksrc = (const float4*)(g_kh + (size_t)bh * SS * DK);
    const unsigned int* mbase = g_mpk + (size_t)(b * SS + qt * 64) * (SS / 32);

    // staging coordinates (fixed per thread)
    int krow = t >> 2, kc4 = t & 3;       // K: thread covers rows krow, krow+32
    int vrow_s = t >> 3, vc4 = t & 7;     // V: rows vrow_s, vrow_s+16
    uint32 ks0 = (uint32)__cvta_generic_to_shared(&Ks[0][krow * KSTRIDE + kc4 * 4]);
    uint32 ks1 = (uint32)__cvta_generic_to_shared(&Ks[0][(krow + 32) * KSTRIDE + kc4 * 4]);
    uint32 vs0 = (uint32)__cvta_generic_to_shared(&Vt[0][vrow_s * VSTRIDE + vc4 * 4]);
    uint32 vs1 = (uint32)__cvta_generic_to_shared(&Vt[0][(vrow_s + 16) * VSTRIDE + vc4 * 4]);
    uint32 ms0 = (uint32)__cvta_generic_to_shared(&Msk[0][t]);
    const uint32 kbufsz = (uint32)(64 * KSTRIDE * 4);
    const uint32 vbufsz = (uint32)(32 * VSTRIDE * 4);

    int kstart = cid * CHUNK;
    const int NT = CHUNK / 64;

    // prologue: issue tile 0 into buf 0
    {
        int k0 = kstart;
        cp16(ks0, ksrc + k0 * 4 + t);
        cp16(ks1, ksrc + k0 * 4 + t + 128);
        cp16(vs0, (const float4*)(g_vh + ((size_t)bh * DK + vrow_s) * SS + k0) + vc4);
        cp16(vs1, (const float4*)(g_vh + ((size_t)bh * DK + vrow_s + 16) * SS + k0) + vc4);
        cp4(ms0, mbase + (size_t)(t >> 1) * (SS / 32) + (k0 >> 5) + (t & 1));
        CP_COMMIT();
    }

    for (int i = 0; i < NT; i++) {
        int buf = i & 1;
        __syncthreads();                        // everyone done computing from buf^1
        if (i + 1 < NT) {
            int k0 = kstart + (i + 1) * 64;
            uint32 off = (buf ^ 1) ? 1u : 0u;
            cp16(ks0 + off * kbufsz, ksrc + k0 * 4 + t);
            cp16(ks1 + off * kbufsz, ksrc + k0 * 4 + t + 128);
            cp16(vs0 + off * vbufsz, (const float4*)(g_vh + ((size_t)bh * DK + vrow_s) * SS + k0) + vc4);
            cp16(vs1 + off * vbufsz, (const float4*)(g_vh + ((size_t)bh * DK + vrow_s + 16) * SS + k0) + vc4);
            cp4(ms0 + off * 512u, mbase + (size_t)(t >> 1) * (SS / 32) + (k0 >> 5) + (t & 1));
            CP_COMMIT();
            CP_WAIT(1);                          // tile i complete; tile i+1 in flight
        } else {
            CP_WAIT(0);
        }
        __syncthreads();                        // tile i visible to all threads

        // ---- compute tile i from buf ----
        float c[8][4];
#pragma unroll
        for (int j = 0; j < 8; j++) { c[j][0] = c[j][1] = c[j][2] = c[j][3] = 0.f; }
#pragma unroll
        for (int j = 0; j < 8; j++) {
            int kr = (8 * j + g) * KSTRIDE;
            uint32 bfr[2];
            bfr[0] = Ks[buf][kr + q4];     bfr[1] = Ks[buf][kr + q4 + 4];
            mma_bf16(c[j], aq[0], bfr);
            bfr[0] = Ks[buf][kr + 8 + q4]; bfr[1] = Ks[buf][kr + 8 + q4 + 4];
            mma_bf16(c[j], aq[1], bfr);
        }
        uint32 ml0 = Msk[buf][(m0 + g) * 2],     ml1 = Msk[buf][(m0 + g) * 2 + 1];
        uint32 mh0 = Msk[buf][(m0 + g + 8) * 2], mh1 = Msk[buf][(m0 + g + 8) * 2 + 1];
#pragma unroll
        for (int j = 0; j < 8; j++) {
#pragma unroll
            for (int e = 0; e < 2; e++) {
                int bit = 8 * j + 2 * q4 + e;
                uint32 wl = (bit < 32) ? ml0 : ml1;
                uint32 wh = (bit < 32) ? mh0 : mh1;
                int bp = bit & 31;
                c[j][e]     = ((wl >> bp) & 1u) ? NEG_MAX : c[j][e] * SCALE;
                c[j][2 + e] = ((wh >> bp) & 1u) ? NEG_MAX : c[j][2 + e] * SCALE;
            }
        }
        float mx_lo = c[0][0], mx_hi = c[0][2];
#pragma unroll
        for (int j = 0; j < 8; j++) {
            mx_lo = fmaxf(mx_lo, fmaxf(c[j][0], c[j][1]));
            mx_hi = fmaxf(mx_hi, fmaxf(c[j][2], c[j][3]));
        }
        mx_lo = fmaxf(mx_lo, __shfl_xor_sync(0xffffffffu, mx_lo, 1));
        mx_lo = fmaxf(mx_lo, __shfl_xor_sync(0xffffffffu, mx_lo, 2));
        mx_hi = fmaxf(mx_hi, __shfl_xor_sync(0xffffffffu, mx_hi, 1));
        mx_hi = fmaxf(mx_hi, __shfl_xor_sync(0xffffffffu, mx_hi, 2));
        float mn_lo = fmaxf(mr_lo, mx_lo), mn_hi = fmaxf(mr_hi, mx_hi);
        float corr_lo = __expf(mr_lo - mn_lo), corr_hi = __expf(mr_hi - mn_hi);
        mr_lo = mn_lo; mr_hi = mn_hi;

        float sum_lo = 0.f, sum_hi = 0.f;
#pragma unroll
        for (int j = 0; j < 8; j++) {
            c[j][0] = __expf(c[j][0] - mn_lo); sum_lo += c[j][0];
            c[j][1] = __expf(c[j][1] - mn_lo); sum_lo += c[j][1];
            c[j][2] = __expf(c[j][2] - mn_hi); sum_hi += c[j][2];
            c[j][3] = __expf(c[j][3] - mn_hi); sum_hi += c[j][3];
        }
        sum_lo += __shfl_xor_sync(0xffffffffu, sum_lo, 1);
        sum_lo += __shfl_xor_sync(0xffffffffu, sum_lo, 2);
        sum_hi += __shfl_xor_sync(0xffffffffu, sum_hi, 1);
        sum_hi += __shfl_xor_sync(0xffffffffu, sum_hi, 2);
        l_lo = l_lo * corr_lo + sum_lo;
        l_hi = l_hi * corr_hi + sum_hi;
#pragma unroll
        for (int jn = 0; jn < 4; jn++) {
            o[jn][0] *= corr_lo; o[jn][1] *= corr_lo;
            o[jn][2] *= corr_hi; o[jn][3] *= corr_hi;
        }
        uint32 pf[4][4];
#pragma unroll
        for (int jj = 0; jj < 4; jj++) {
            pf[jj][0] = pack_bf16(c[2 * jj][0],     c[2 * jj][1]);
            pf[jj][1] = pack_bf16(c[2 * jj][2],     c[2 * jj][3]);
            pf[jj][2] = pack_bf16(c[2 * jj + 1][0], c[2 * jj + 1][1]);
            pf[jj][3] = pack_bf16(c[2 * jj + 1][2], c[2 * jj + 1][3]);
        }
#pragma unroll
        for (int jn = 0; jn < 4; jn++) {
            int vr = (8 * jn + g) * VSTRIDE;
#pragma unroll
            for (int jj = 0; jj < 4; jj++) {
                uint32 bfr[2];
                bfr[0] = Vt[buf][vr + 8 * jj + q4];
                bfr[1] = Vt[buf][vr + 8 * jj + q4 + 4];
                mma_bf16(o[jn], pf[jj], bfr);
            }
        }
    }
    // store unnormalized partials
    int qidx = bh * SS + sq_lo;       // rows qidx, qidx+8
    float* pp = g_pacc + ((size_t)cid * BHS + qidx) * DK;
#pragma unroll
    for (int jn = 0; jn < 4; jn++) {
        int col = 8 * jn + 2 * q4;
        *(float2*)&pp[col]          = make_float2(o[jn][0], o[jn][1]);
        *(float2*)&pp[8 * DK + col] = make_float2(o[jn][2], o[jn][3]);
    }
    if (q4 == 0) {
        g_pm[cid * BHS + qidx] = mr_lo;     g_pl[cid * BHS + qidx] = l_lo;
        g_pm[cid * BHS + qidx + 8] = mr_hi; g_pl[cid * BHS + qidx + 8] = l_hi;
    }
}

// merge NCHUNK partials, normalize, write hi/lo attn output (head-concat layout)
__global__ void __launch_bounds__(256) attn_combine_kernel() {
    int q = blockIdx.x * 256 + threadIdx.x;   // 0..BHS-1
    float gm = -INFINITY;
#pragma unroll
    for (int c = 0; c < NCHUNK; c++) gm = fmaxf(gm, g_pm[c * BHS + q]);
    float wgt[NCHUNK];
    float L = 0.f;
#pragma unroll
    for (int c = 0; c < NCHUNK; c++) {
        wgt[c] = __expf(g_pm[c * BHS + q] - gm);
        L += g_pl[c * BHS + q] * wgt[c];
    }
    float inv = 1.f / L;
#pragma unroll
    for (int c = 0; c < NCHUNK; c++) wgt[c] *= inv;

    int bh = q >> 11, sq = q & 2047;
    int b = bh >> 3, h = bh & 7;
    size_t obase = ((size_t)b * SS + sq) * DD + h * DK;
    uint32* doh = (uint32*)g_oh + (obase >> 1);
    uint32* dol = (uint32*)g_ol + (obase >> 1);
#pragma unroll
    for (int i = 0; i < 8; i++) {
        float r0 = 0.f, r1 = 0.f, r2 = 0.f, r3 = 0.f;
#pragma unroll
        for (int c = 0; c < NCHUNK; c++) {
            float4 a = ((const float4*)(g_pacc + ((size_t)c * BHS + q) * DK))[i];
            r0 = fmaf(a.x, wgt[c], r0); r1 = fmaf(a.y, wgt[c], r1);
            r2 = fmaf(a.z, wgt[c], r2); r3 = fmaf(a.w, wgt[c], r3);
        }
        uint32 hw, lw;
        split2(r0, r1, hw, lw);
        doh[i * 2] = hw; dol[i * 2] = lw;
        split2(r2, r3, hw, lw);
        doh[i * 2 + 1] = hw; dol[i * 2 + 1] = lw;
    }
}

// residual + layernorm: warp per row, 8 rows/block, shfl-only reductions.
// outp == nullptr: write g_x + hi/lo. outp != nullptr (last layer): write outp only.
__global__ void __launch_bounds__(256) ln_kernel(const float* __restrict__ gam,
                                                 const float* __restrict__ bet,
                                                 float* __restrict__ outp) {
    int lane = threadIdx.x & 31, wrp = threadIdx.x >> 5;
    int row = blockIdx.x * 8 + wrp;
    const float4* t4 = (const float4*)(g_t + (size_t)row * DD) + lane * 2;
    const float4* x4 = (const float4*)(g_x + (size_t)row * DD) + lane * 2;
    float4 a0 = t4[0], a1 = t4[1], b0 = x4[0], b1 = x4[1];
    float v[8] = { a0.x + b0.x, a0.y + b0.y, a0.z + b0.z, a0.w + b0.w,
                   a1.x + b1.x, a1.y + b1.y, a1.z + b1.z, a1.w + b1.w };
    float s = 0.f;
#pragma unroll
    for (int i = 0; i < 8; i++) s += v[i];
#pragma unroll
    for (int o = 16; o; o >>= 1) s += __shfl_xor_sync(0xffffffffu, s, o);
    float mu = s * (1.f / DD);
    float s2 = 0.f;
#pragma unroll
    for (int i = 0; i < 8; i++) { float d = v[i] - mu; s2 += d * d; }
#pragma unroll
    for (int o = 16; o; o >>= 1) s2 += __shfl_xor_sync(0xffffffffu, s2, o);
    float rstd = rsqrtf(s2 * (1.f / DD) + 1e-7f);

    const float4* g4 = (const float4*)gam + lane * 2;
    const float4* be4 = (const float4*)bet + lane * 2;
    float4 gg0 = g4[0], gg1 = g4[1], bb0 = be4[0], bb1 = be4[1];
    float out[8];
    out[0] = (v[0] - mu) * rstd * gg0.x + bb0.x;
    out[1] = (v[1] - mu) * rstd * gg0.y + bb0.y;
    out[2] = (v[2] - mu) * rstd * gg0.z + bb0.z;
    out[3] = (v[3] - mu) * rstd * gg0.w + bb0.w;
    out[4] = (v[4] - mu) * rstd * gg1.x + bb1.x;
    out[5] = (v[5] - mu) * rstd * gg1.y + bb1.y;
    out[6] = (v[6] - mu) * rstd * gg1.z + bb1.z;
    out[7] = (v[7] - mu) * rstd * gg1.w + bb1.w;

    if (outp) {
        float4* oo = (float4*)(outp + (size_t)row * DD) + lane * 2;
        oo[0] = make_float4(out[0], out[1], out[2], out[3]);
        oo[1] = make_float4(out[4], out[5], out[6], out[7]);
    } else {
        float4* xo = (float4*)(g_x + (size_t)row * DD) + lane * 2;
        xo[0] = make_float4(out[0], out[1], out[2], out[3]);
        xo[1] = make_float4(out[4], out[5], out[6], out[7]);
        uint32 hw[4], lw[4];
#pragma unroll
        for (int i = 0; i < 4; i++) split2(out[2 * i], out[2 * i + 1], hw[i], lw[i]);
        size_t wi = ((size_t)row * DD) / 2 + lane * 4;
        *(uint4*)((uint32*)g_xh + wi) = *(uint4*)hw;
        *(uint4*)((uint32*)g_xl + wi) = *(uint4*)lw;
    }
}

// ---------------- launch ----------------
extern "C" void kernel_launch(void* const* d_in, const int* in_sizes, int n_in,
                              void* d_out, int out_size) {
    const float* x  = (const float*)d_in[0];
    const int*   mask = (const int*)d_in[1];     // jnp bool promoted to int32
    const float* pe = (const float*)d_in[2];
    const float* Wq = (const float*)d_in[3];
    const float* Wk = (const float*)d_in[4];
    const float* Wv = (const float*)d_in[5];
    const float* Wo = (const float*)d_in[6];
    const float* bo = (const float*)d_in[7];
    const float* ln1_g = (const float*)d_in[8];
    const float* ln1_b = (const float*)d_in[9];
    const float* W1 = (const float*)d_in[10];
    const float* b1 = (const float*)d_in[11];
    const float* W2 = (const float*)d_in[12];
    const float* b2 = (const float*)d_in[13];
    const float* ln2_g = (const float*)d_in[14];
    const float* ln2_b = (const float*)d_in[15];

    void *p_xh, *p_xl, *p_oh, *p_ol, *p_hh, *p_hl;
    void *p_wqkvh, *p_wqkvl, *p_woh, *p_wol, *p_w1h, *p_w1l, *p_w2h, *p_w2l;
    cudaGetSymbolAddress(&p_xh, g_xh);   cudaGetSymbolAddress(&p_xl, g_xl);
    cudaGetSymbolAddress(&p_oh, g_oh);   cudaGetSymbolAddress(&p_ol, g_ol);
    cudaGetSymbolAddress(&p_hh, g_hidh); cudaGetSymbolAddress(&p_hl, g_hidl);
    cudaGetSymbolAddress(&p_wqkvh, Wqkv_h); cudaGetSymbolAddress(&p_wqkvl, Wqkv_l);
    cudaGetSymbolAddress(&p_woh, Wo_h);  cudaGetSymbolAddress(&p_wol, Wo_l);
    cudaGetSymbolAddress(&p_w1h, W1_h);  cudaGetSymbolAddress(&p_w1l, W1_l);
    cudaGetSymbolAddress(&p_w2h, W2_h);  cudaGetSymbolAddress(&p_w2l, W2_l);
    const __nv_bfloat16 *xh = (const __nv_bfloat16*)p_xh, *xl = (const __nv_bfloat16*)p_xl;
    const __nv_bfloat16 *oh = (const __nv_bfloat16*)p_oh, *ol = (const __nv_bfloat16*)p_ol;
    const __nv_bfloat16 *hh = (const __nv_bfloat16*)p_hh, *hl = (const __nv_bfloat16*)p_hl;

    // dynamic-smem opt-in for all gemm instantiations (host-side, capture-safe)
    cudaFuncSetAttribute(gemm_kernel<256, 0>,  cudaFuncAttributeMaxDynamicSharedMemorySize, GEMM_SMEM);
    cudaFuncSetAttribute(gemm_kernel<256, 1>,  cudaFuncAttributeMaxDynamicSharedMemorySize, GEMM_SMEM);
    cudaFuncSetAttribute(gemm_kernel<256, 2>,  cudaFuncAttributeMaxDynamicSharedMemorySize, GEMM_SMEM);
    cudaFuncSetAttribute(gemm_kernel<1024, 0>, cudaFuncAttributeMaxDynamicSharedMemorySize, GEMM_SMEM);

    // weight prep (idempotent, coalesced tile transposes)
    wqkvsplit_kernel<<<dim3(DD / 32, 24, LL), 256>>>(Wq, Wk, Wv);
    wtsplit_kernel<<<dim3(DD / 32, DD / 32, LL), 256>>>(Wo, (__nv_bfloat16*)p_woh, (__nv_bfloat16*)p_wol, DD, DD);
    wtsplit_kernel<<<dim3(DD / 32, FF / 32, LL), 256>>>(W1, (__nv_bfloat16*)p_w1h, (__nv_bfloat16*)p_w1l, DD, FF);
    wtsplit_kernel<<<dim3(FF / 32, DD / 32, LL), 256>>>(W2, (__nv_bfloat16*)p_w2h, (__nv_bfloat16*)p_w2l, FF, DD);
    maskpack_kernel<<<(BB*SS*SS/32) / 256, 256>>>(mask);
    addpe_kernel<<<BS * DD / 256, 256>>>(x, pe);

    for (int l = 0; l < LL; l++) {
        const __nv_bfloat16* wqh = (const __nv_bfloat16*)p_wqkvh + (size_t)l * 768 * DD;
        const __nv_bfloat16* wql = (const __nv_bfloat16*)p_wqkvl + (size_t)l * 768 * DD;
        const __nv_bfloat16* woh2 = (const __nv_bfloat16*)p_woh + (size_t)l * DD * DD;
        const __nv_bfloat16* wol2 = (const __nv_bfloat16*)p_wol + (size_t)l * DD * DD;
        const __nv_bfloat16* w1h2 = (const __nv_bfloat16*)p_w1h + (size_t)l * FF * DD;
        const __nv_bfloat16* w1l2 = (const __nv_bfloat16*)p_w1l + (size_t)l * FF * DD;
        const __nv_bfloat16* w2h2 = (const __nv_bfloat16*)p_w2h + (size_t)l * DD * FF;
        const __nv_bfloat16* w2l2 = (const __nv_bfloat16*)p_w2l + (size_t)l * DD * FF;

        gemm_kernel<256, 2><<<dim3(32, 12), 256, GEMM_SMEM>>>(xh, xl, wqh, wql, nullptr);       // QKV
        attn_mma_kernel<<<BB * HH * (SS / 64) * NCHUNK, 128>>>();
        attn_combine_kernel<<<BHS / 256, 256>>>();
        gemm_kernel<256, 0><<<dim3(32, 4), 256, GEMM_SMEM>>>(oh, ol, woh2, wol2, bo + l * DD);  // Wo
        ln_kernel<<<BS / 8, 256>>>(ln1_g + l * DD, ln1_b + l * DD, nullptr);
        gemm_kernel<256, 1><<<dim3(32, 16), 256, GEMM_SMEM>>>(xh, xl, w1h2, w1l2, b1 + l * FF); // FFN1
        gemm_kernel<1024, 0><<<dim3(32, 4), 256, GEMM_SMEM>>>(hh, hl, w2h2, w2l2, b2 + l * DD); // FFN2
        ln_kernel<<<BS / 8, 256>>>(ln2_g + l * DD, ln2_b + l * DD,
                                   (l == LL - 1) ? (float*)d_out : nullptr);
    }
}